// round 3
// baseline (speedup 1.0000x reference)
#include <cuda_runtime.h>
#include <cuda_bf16.h>
#include <math.h>

// Problem constants
#define BATCH   2
#define SQ      2048
#define DMODEL  1024
#define NHEADS  16
#define DHID    4096
#define DKH     64      // dk per head
#define DVH     256     // dv per head
#define MROWS   (BATCH*SQ)   // 4096

// ---------------- scratch (device globals; no allocation allowed) ----------
__device__ float g_K[MROWS * DMODEL];   // 16 MB
__device__ float g_V[MROWS * DHID];     // 64 MB
__device__ float g_O[MROWS * DHID];     // 64 MB  (stores gelu(attn_out))

// ---------------- generic tiled fp32 GEMM:  C = A@B + bias (+ res) ----------
#define TBM 128
#define TBN 128
#define TBK 16

template<bool RES>
__global__ __launch_bounds__(256)
void gemm_kernel(const float* __restrict__ A, const float* __restrict__ Bm,
                 const float* __restrict__ bias, const float* __restrict__ res,
                 float* __restrict__ C, int M, int N, int K)
{
    __shared__ float As[TBK][TBM];
    __shared__ float Bs[TBK][TBN];

    const int t  = threadIdx.x;
    const int rowBase = blockIdx.y * TBM;
    const int colBase = blockIdx.x * TBN;
    const int ty = t >> 4;       // 0..15
    const int tx = t & 15;       // 0..15

    float acc[8][8];
    #pragma unroll
    for (int i = 0; i < 8; ++i)
        #pragma unroll
        for (int j = 0; j < 8; ++j) acc[i][j] = 0.f;

    for (int kt = 0; kt < K; kt += TBK) {
        // load A tile 128x16 (transposed into As[k][m])
        #pragma unroll
        for (int it = 0; it < 2; ++it) {
            int lin = t + it * 256;          // 0..511 float4s
            int r   = lin >> 2;              // 0..127
            int kc  = (lin & 3) * 4;
            float4 v = *(const float4*)&A[(size_t)(rowBase + r) * K + kt + kc];
            As[kc + 0][r] = v.x;
            As[kc + 1][r] = v.y;
            As[kc + 2][r] = v.z;
            As[kc + 3][r] = v.w;
        }
        // load B tile 16x128
        #pragma unroll
        for (int it = 0; it < 2; ++it) {
            int lin = t + it * 256;
            int kr  = lin >> 5;              // 0..15
            int c   = (lin & 31) * 4;
            *(float4*)&Bs[kr][c] =
                *(const float4*)&Bm[(size_t)(kt + kr) * N + colBase + c];
        }
        __syncthreads();

        #pragma unroll
        for (int k = 0; k < TBK; ++k) {
            float ra[8], rb[8];
            *(float4*)&ra[0] = *(const float4*)&As[k][ty * 8];
            *(float4*)&ra[4] = *(const float4*)&As[k][ty * 8 + 4];
            *(float4*)&rb[0] = *(const float4*)&Bs[k][tx * 8];
            *(float4*)&rb[4] = *(const float4*)&Bs[k][tx * 8 + 4];
            #pragma unroll
            for (int i = 0; i < 8; ++i)
                #pragma unroll
                for (int j = 0; j < 8; ++j)
                    acc[i][j] += ra[i] * rb[j];
        }
        __syncthreads();
    }

    // epilogue
    #pragma unroll
    for (int i = 0; i < 8; ++i) {
        int row = rowBase + ty * 8 + i;
        #pragma unroll
        for (int j4 = 0; j4 < 2; ++j4) {
            int col = colBase + tx * 8 + j4 * 4;
            float4 bv4 = *(const float4*)&bias[col];
            float4 o;
            o.x = acc[i][j4 * 4 + 0] + bv4.x;
            o.y = acc[i][j4 * 4 + 1] + bv4.y;
            o.z = acc[i][j4 * 4 + 2] + bv4.z;
            o.w = acc[i][j4 * 4 + 3] + bv4.w;
            if (RES) {
                float4 r4 = *(const float4*)&res[(size_t)row * N + col];
                o.x += r4.x; o.y += r4.y; o.z += r4.z; o.w += r4.w;
            }
            *(float4*)&C[(size_t)row * N + col] = o;
        }
    }
}

// ---------------- causal flash attention + fused GELU epilogue --------------
// Grid: (32 q-tiles, 32 b*h).  Block: 256 threads.
// thread t: q = t/4 (query row in tile), m = t%4.
// Score slice of thread:  k  in { g*16 + m*4 + i : g<4,  i<4 }  (16 keys)
// Output slice of thread: c  in { g*16 + m*4 + i : g<16, i<4 }  (64 cols)
// (the m*4 interleave makes every LDS.128 across a warp hit 4 consecutive
//  16B addresses -> conflict-free, 8-way broadcast)
#define QT   64
#define KT   64
#define QPAD 65
#define PPAD 65
#define ATTN_SMEM ((QT*QPAD + DKH*KT + KT*DVH + QT*PPAD) * (int)sizeof(float))

__device__ __forceinline__ float gelu_exact(float v) {
    return 0.5f * v * (1.0f + erff(v * 0.70710678118654752f));
}

__global__ __launch_bounds__(256)
void attn_kernel(const float* __restrict__ x, const float* __restrict__ Kg,
                 const float* __restrict__ Vg, float* __restrict__ Og)
{
    extern __shared__ float sm[];
    float* Qs = sm;                          // [QT][QPAD]
    float* Ks = Qs + QT * QPAD;              // [DKH][KT]   (d-major, transposed)
    float* Vs = Ks + DKH * KT;               // [KT][DVH]
    float* Ps = Vs + KT * DVH;               // [QT][PPAD]

    const int qtile = blockIdx.x;
    const int bh    = blockIdx.y;
    const int b = bh >> 4, h = bh & 15;
    const int t = threadIdx.x;
    const int q = t >> 2;
    const int m = t & 3;
    const int q0 = qtile * QT;

    const float* xb = x  + (size_t)b * SQ * DMODEL + (size_t)h * DKH;
    const float* Kb = Kg + (size_t)b * SQ * DMODEL + (size_t)h * DKH;
    const float* Vb = Vg + (size_t)b * SQ * DHID   + (size_t)h * DVH;

    // load Q tile (64x64) into padded smem
    #pragma unroll
    for (int it = 0; it < 4; ++it) {
        int lin = t + it * 256;               // 0..1023 float4s
        int r   = lin >> 4;                   // 0..63
        int dc  = (lin & 15) * 4;
        float4 v = *(const float4*)&xb[(size_t)(q0 + r) * DMODEL + dc];
        Qs[r * QPAD + dc + 0] = v.x;
        Qs[r * QPAD + dc + 1] = v.y;
        Qs[r * QPAD + dc + 2] = v.z;
        Qs[r * QPAD + dc + 3] = v.w;
    }

    float acc[64];
    #pragma unroll
    for (int i = 0; i < 64; ++i) acc[i] = 0.f;
    float mrow = -INFINITY;
    float lrow = 0.f;

    for (int j = 0; j <= qtile; ++j) {
        const int kb = j * KT;
        __syncthreads();   // previous tile's Vs/Ps reads done before overwrite
        // load K tile transposed -> Ks[d][k]
        #pragma unroll
        for (int it = 0; it < 4; ++it) {
            int lin = t + it * 256;
            int r   = lin >> 4;
            int dc  = (lin & 15) * 4;
            float4 v = *(const float4*)&Kb[(size_t)(kb + r) * DMODEL + dc];
            Ks[(dc + 0) * KT + r] = v.x;
            Ks[(dc + 1) * KT + r] = v.y;
            Ks[(dc + 2) * KT + r] = v.z;
            Ks[(dc + 3) * KT + r] = v.w;
        }
        // load V tile (64x256)
        #pragma unroll
        for (int it = 0; it < 16; ++it) {
            int lin = t + it * 256;           // 0..4095 float4s
            int r   = lin >> 6;               // 0..63
            int c   = (lin & 63) * 4;
            *(float4*)&Vs[r * DVH + c] =
                *(const float4*)&Vb[(size_t)(kb + r) * DHID + c];
        }
        __syncthreads();

        // ---- scores: 16 keys per thread ----
        float s[16];
        #pragma unroll
        for (int i = 0; i < 16; ++i) s[i] = 0.f;
        #pragma unroll 4
        for (int d = 0; d < DKH; ++d) {
            float qv = Qs[q * QPAD + d];
            const float4* Krow = (const float4*)&Ks[d * KT];
            #pragma unroll
            for (int g = 0; g < 4; ++g) {
                float4 kv = Krow[g * 4 + m];
                s[g * 4 + 0] += qv * kv.x;
                s[g * 4 + 1] += qv * kv.y;
                s[g * 4 + 2] += qv * kv.z;
                s[g * 4 + 3] += qv * kv.w;
            }
        }
        // causal mask on diagonal tile
        if (j == qtile) {
            #pragma unroll
            for (int g = 0; g < 4; ++g)
                #pragma unroll
                for (int i = 0; i < 4; ++i)
                    if (g * 16 + m * 4 + i > q) s[g * 4 + i] = -INFINITY;
        }
        // row max across this thread's 16 + the other 3 threads of the row
        float tmax = s[0];
        #pragma unroll
        for (int i = 1; i < 16; ++i) tmax = fmaxf(tmax, s[i]);
        tmax = fmaxf(tmax, __shfl_xor_sync(0xffffffffu, tmax, 1));
        tmax = fmaxf(tmax, __shfl_xor_sync(0xffffffffu, tmax, 2));

        float mnew  = fmaxf(mrow, tmax);
        float alpha = __expf(mrow - mnew);     // 0 on first tile (mrow=-inf)
        float psum = 0.f;
        #pragma unroll
        for (int g = 0; g < 4; ++g)
            #pragma unroll
            for (int i = 0; i < 4; ++i) {
                float p = __expf(s[g * 4 + i] - mnew);
                psum += p;
                Ps[q * PPAD + g * 16 + m * 4 + i] = p;
            }
        psum += __shfl_xor_sync(0xffffffffu, psum, 1);
        psum += __shfl_xor_sync(0xffffffffu, psum, 2);
        lrow = lrow * alpha + psum;
        mrow = mnew;
        #pragma unroll
        for (int c = 0; c < 64; ++c) acc[c] *= alpha;
        __syncwarp();    // Ps row written by the 4 lanes of this row-group

        // ---- P @ V : 64 output cols per thread ----
        for (int k = 0; k < KT; ++k) {
            float p = Ps[q * PPAD + k];
            const float4* Vrow = (const float4*)&Vs[k * DVH];
            #pragma unroll
            for (int g = 0; g < 16; ++g) {
                float4 v = Vrow[g * 4 + m];
                acc[g * 4 + 0] += p * v.x;
                acc[g * 4 + 1] += p * v.y;
                acc[g * 4 + 2] += p * v.z;
                acc[g * 4 + 3] += p * v.w;
            }
        }
    }

    // ---- epilogue: normalize + GELU, store ----
    const float inv = 1.0f / lrow;
    float* orow = Og + (size_t)(b * SQ + q0 + q) * DHID + (size_t)h * DVH;
    #pragma unroll
    for (int g = 0; g < 16; ++g) {
        float4 o;
        o.x = gelu_exact(acc[g * 4 + 0] * inv);
        o.y = gelu_exact(acc[g * 4 + 1] * inv);
        o.z = gelu_exact(acc[g * 4 + 2] * inv);
        o.w = gelu_exact(acc[g * 4 + 3] * inv);
        *(float4*)&orow[g * 16 + m * 4] = o;
    }
}

// ---------------------------------------------------------------------------
extern "C" void kernel_launch(void* const* d_in, const int* in_sizes, int n_in,
                              void* d_out, int out_size)
{
    const float* x  = (const float*)d_in[0];
    const float* Wk = (const float*)d_in[1];
    const float* bk = (const float*)d_in[2];
    const float* Wv = (const float*)d_in[3];
    const float* bv = (const float*)d_in[4];
    const float* Wf = (const float*)d_in[5];
    const float* bf = (const float*)d_in[6];
    float* out = (float*)d_out;

    float *gK, *gV, *gO;
    cudaGetSymbolAddress((void**)&gK, g_K);
    cudaGetSymbolAddress((void**)&gV, g_V);
    cudaGetSymbolAddress((void**)&gO, g_O);

    cudaFuncSetAttribute(attn_kernel,
                         cudaFuncAttributeMaxDynamicSharedMemorySize, ATTN_SMEM);

    dim3 blk(256);

    // 1) K = x @ Wk + bk           [4096,1024]
    gemm_kernel<false><<<dim3(DMODEL / TBN, MROWS / TBM), blk>>>(
        x, Wk, bk, nullptr, gK, MROWS, DMODEL, DMODEL);

    // 2) V = x @ Wv + bv           [4096,4096]
    gemm_kernel<false><<<dim3(DHID / TBN, MROWS / TBM), blk>>>(
        x, Wv, bv, nullptr, gV, MROWS, DHID, DMODEL);

    // 3) gelu(attn(x, K, V)) -> gO [4096,4096]
    attn_kernel<<<dim3(SQ / QT, BATCH * NHEADS), blk, ATTN_SMEM>>>(x, gK, gV, gO);

    // 4) out = x + gO @ Wf + bf    [4096,1024]
    gemm_kernel<true><<<dim3(DMODEL / TBN, MROWS / TBM), blk>>>(
        gO, Wf, bf, x, out, MROWS, DMODEL, DHID);
}

// round 5
// speedup vs baseline: 1.2501x; 1.2501x over previous
#include <cuda_runtime.h>
#include <cuda_bf16.h>
#include <cstdint>
#include <cstddef>
#include <math.h>

// Problem constants
#define BATCH   2
#define SQ      2048
#define DMODEL  1024
#define NHEADS  16
#define DHID    4096
#define DKH     64
#define DVH     256
#define MROWS   (BATCH*SQ)   // 4096

typedef __nv_bfloat16 bf16;

// ---------------- scratch (device globals; no allocation allowed) ----------
__device__ float g_K[MROWS * DMODEL];     // 16 MB  (fp32 K for attention)
__device__ float g_V[MROWS * DHID];       // 64 MB  (fp32 V for attention)
__device__ bf16  g_xh[MROWS * DMODEL];    // x split hi
__device__ bf16  g_xl[MROWS * DMODEL];    // x split lo
__device__ bf16  g_Oh[MROWS * DHID];      // gelu(attn) split hi
__device__ bf16  g_Ol[MROWS * DHID];      // gelu(attn) split lo
__device__ bf16  g_Wkh[DMODEL * DMODEL];  // Wk^T split   [N=1024][K=1024]
__device__ bf16  g_Wkl[DMODEL * DMODEL];
__device__ bf16  g_Wvh[DHID * DMODEL];    // Wv^T split   [N=4096][K=1024]
__device__ bf16  g_Wvl[DHID * DMODEL];
__device__ bf16  g_Wfh[DMODEL * DHID];    // Wf^T split   [N=1024][K=4096]
__device__ bf16  g_Wfl[DMODEL * DHID];

// ---------------- conversion kernels ---------------------------------------
// elementwise fp32 -> (hi, lo) bf16 split
__global__ __launch_bounds__(256)
void convert_hl_kernel(const float* __restrict__ src, bf16* __restrict__ hi,
                       bf16* __restrict__ lo, int n4)
{
    int i = blockIdx.x * blockDim.x + threadIdx.x;
    if (i >= n4) return;
    float4 v = ((const float4*)src)[i];
    bf16 h0 = __float2bfloat16(v.x);
    bf16 h1 = __float2bfloat16(v.y);
    bf16 h2 = __float2bfloat16(v.z);
    bf16 h3 = __float2bfloat16(v.w);
    bf16 l0 = __float2bfloat16(v.x - __bfloat162float(h0));
    bf16 l1 = __float2bfloat16(v.y - __bfloat162float(h1));
    bf16 l2 = __float2bfloat16(v.z - __bfloat162float(h2));
    bf16 l3 = __float2bfloat16(v.w - __bfloat162float(h3));
    ((__nv_bfloat162*)hi)[i*2 + 0] = __halves2bfloat162(h0, h1);
    ((__nv_bfloat162*)hi)[i*2 + 1] = __halves2bfloat162(h2, h3);
    ((__nv_bfloat162*)lo)[i*2 + 0] = __halves2bfloat162(l0, l1);
    ((__nv_bfloat162*)lo)[i*2 + 1] = __halves2bfloat162(l2, l3);
}

// fp32 [R][C] -> transposed bf16 split [C][R]
__global__ __launch_bounds__(256)
void transpose_hl_kernel(const float* __restrict__ W, bf16* __restrict__ Th,
                         bf16* __restrict__ Tl, int R, int C)
{
    __shared__ float tile[32][33];
    const int c0 = blockIdx.x * 32, r0 = blockIdx.y * 32;
    const int tx = threadIdx.x, ty = threadIdx.y;   // 32 x 8
    #pragma unroll
    for (int j = 0; j < 4; ++j)
        tile[ty + j*8][tx] = W[(size_t)(r0 + ty + j*8) * C + c0 + tx];
    __syncthreads();
    #pragma unroll
    for (int j = 0; j < 4; ++j) {
        float v = tile[tx][ty + j*8];
        bf16 h = __float2bfloat16(v);
        size_t o = (size_t)(c0 + ty + j*8) * R + r0 + tx;
        Th[o] = h;
        Tl[o] = __float2bfloat16(v - __bfloat162float(h));
    }
}

// ---------------- bf16-split tensor-core GEMM ------------------------------
//  C[M][N] = (Ah+Al) @ (Bh+Bl)^T + bias (+ res),  fp32 accumulate
//  A: [M][K] row-major bf16 pair.  B: [N][K] bf16 pair (pre-transposed).
#define GBM 128
#define GBN 128
#define GBK 32
#define LDT 40                 // smem row stride (bf16) — conflict-free
#define TBUF (GBM * LDT)       // 5120 bf16 per tile buffer
#define GEMM_SMEM (8 * TBUF * (int)sizeof(bf16))   // 81920 B

__device__ __forceinline__ void cp16(void* s, const void* g) {
    uint32_t sa = (uint32_t)__cvta_generic_to_shared(s);
    asm volatile("cp.async.cg.shared.global [%0], [%1], 16;\n" :: "r"(sa), "l"(g));
}
__device__ __forceinline__ uint32_t lds32(const bf16* p) {
    return *reinterpret_cast<const uint32_t*>(p);
}
__device__ __forceinline__ void mma_bf16(float* c, uint32_t a0, uint32_t a1,
                                         uint32_t a2, uint32_t a3,
                                         uint32_t b0, uint32_t b1) {
    asm volatile(
        "mma.sync.aligned.m16n8k16.row.col.f32.bf16.bf16.f32 "
        "{%0,%1,%2,%3}, {%4,%5,%6,%7}, {%8,%9}, {%0,%1,%2,%3};\n"
        : "+f"(c[0]), "+f"(c[1]), "+f"(c[2]), "+f"(c[3])
        : "r"(a0), "r"(a1), "r"(a2), "r"(a3), "r"(b0), "r"(b1));
}

template<bool RES>
__global__ __launch_bounds__(256)
void gemm_mma_kernel(const bf16* __restrict__ Ah, const bf16* __restrict__ Al,
                     const bf16* __restrict__ Bh, const bf16* __restrict__ Bl,
                     const float* __restrict__ bias, const float* __restrict__ res,
                     float* __restrict__ C, int M, int N, int K)
{
    extern __shared__ bf16 sm[];
    bf16* sAh = sm;
    bf16* sAl = sm + 2 * TBUF;
    bf16* sBh = sm + 4 * TBUF;
    bf16* sBl = sm + 6 * TBUF;

    const int t = threadIdx.x;
    const int warp = t >> 5, lane = t & 31;
    const int g = lane >> 2, tq = lane & 3;
    const int wm = warp >> 2, wn = warp & 3;
    const int m0 = wm * 64, n0 = wn * 32;
    const int rowBase = blockIdx.y * GBM, colBase = blockIdx.x * GBN;

    float acc[4][4][4];
    #pragma unroll
    for (int i = 0; i < 4; ++i)
        #pragma unroll
        for (int j = 0; j < 4; ++j)
            #pragma unroll
            for (int k = 0; k < 4; ++k) acc[i][j][k] = 0.f;

    auto load_tile = [&](int stage, int kt) {
        bf16* dAh = sAh + stage * TBUF;
        bf16* dAl = sAl + stage * TBUF;
        bf16* dBh = sBh + stage * TBUF;
        bf16* dBl = sBl + stage * TBUF;
        #pragma unroll
        for (int it = 0; it < 2; ++it) {
            int c  = t + it * 256;
            int r  = c >> 2, cc = (c & 3) * 8;
            size_t ga = (size_t)(rowBase + r) * K + kt + cc;
            size_t gb = (size_t)(colBase + r) * K + kt + cc;
            cp16(dAh + r * LDT + cc, Ah + ga);
            cp16(dAl + r * LDT + cc, Al + ga);
            cp16(dBh + r * LDT + cc, Bh + gb);
            cp16(dBl + r * LDT + cc, Bl + gb);
        }
    };

    const int nk = K / GBK;
    load_tile(0, 0);
    asm volatile("cp.async.commit_group;\n");

    for (int kt = 0; kt < nk; ++kt) {
        const int cur = kt & 1;
        if (kt + 1 < nk) load_tile(cur ^ 1, (kt + 1) * GBK);
        asm volatile("cp.async.commit_group;\n");
        asm volatile("cp.async.wait_group 1;\n");
        __syncthreads();

        const bf16* Ahc = sAh + cur * TBUF;
        const bf16* Alc = sAl + cur * TBUF;
        const bf16* Bhc = sBh + cur * TBUF;
        const bf16* Blc = sBl + cur * TBUF;

        #pragma unroll
        for (int ks = 0; ks < 2; ++ks) {
            uint32_t bhf[4][2], blf[4][2];
            #pragma unroll
            for (int ni = 0; ni < 4; ++ni) {
                const bf16* p = Bhc + (n0 + ni*8 + g) * LDT + ks*16 + tq*2;
                bhf[ni][0] = lds32(p);  bhf[ni][1] = lds32(p + 8);
                const bf16* q2 = Blc + (n0 + ni*8 + g) * LDT + ks*16 + tq*2;
                blf[ni][0] = lds32(q2); blf[ni][1] = lds32(q2 + 8);
            }
            #pragma unroll
            for (int mi = 0; mi < 4; ++mi) {
                const bf16* pa = Ahc + (m0 + mi*16 + g) * LDT + ks*16 + tq*2;
                uint32_t ah0 = lds32(pa),     ah1 = lds32(pa + 8*LDT);
                uint32_t ah2 = lds32(pa + 8), ah3 = lds32(pa + 8*LDT + 8);
                const bf16* pl = Alc + (m0 + mi*16 + g) * LDT + ks*16 + tq*2;
                uint32_t al0 = lds32(pl),     al1 = lds32(pl + 8*LDT);
                uint32_t al2 = lds32(pl + 8), al3 = lds32(pl + 8*LDT + 8);
                #pragma unroll
                for (int ni = 0; ni < 4; ++ni) {
                    mma_bf16(acc[mi][ni], ah0, ah1, ah2, ah3, bhf[ni][0], bhf[ni][1]);
                    mma_bf16(acc[mi][ni], ah0, ah1, ah2, ah3, blf[ni][0], blf[ni][1]);
                    mma_bf16(acc[mi][ni], al0, al1, al2, al3, bhf[ni][0], bhf[ni][1]);
                }
            }
        }
        __syncthreads();
    }

    // epilogue: bias (+ residual), fp32 stores
    #pragma unroll
    for (int mi = 0; mi < 4; ++mi) {
        #pragma unroll
        for (int ni = 0; ni < 4; ++ni) {
            int r0 = rowBase + m0 + mi*16 + g;
            int cb = colBase + n0 + ni*8 + tq*2;
            float b0 = bias[cb], b1 = bias[cb + 1];
            float2 o0 = { acc[mi][ni][0] + b0, acc[mi][ni][1] + b1 };
            float2 o1 = { acc[mi][ni][2] + b0, acc[mi][ni][3] + b1 };
            if (RES) {
                float2 r0v = *(const float2*)&res[(size_t)r0 * N + cb];
                float2 r1v = *(const float2*)&res[(size_t)(r0+8) * N + cb];
                o0.x += r0v.x; o0.y += r0v.y;
                o1.x += r1v.x; o1.y += r1v.y;
            }
            *(float2*)&C[(size_t)r0 * N + cb]     = o0;
            *(float2*)&C[(size_t)(r0+8) * N + cb] = o1;
        }
    }
}

// ---------------- causal flash attention + fused GELU epilogue --------------
#define QT   64
#define KT   64
#define QPAD 65
#define PPAD 65
#define ATTN_SMEM ((QT*QPAD + DKH*KT + KT*DVH + QT*PPAD) * (int)sizeof(float))

__device__ __forceinline__ float gelu_exact(float v) {
    return 0.5f * v * (1.0f + erff(v * 0.70710678118654752f));
}

__global__ __launch_bounds__(256)
void attn_kernel(const float* __restrict__ x, const float* __restrict__ Kg,
                 const float* __restrict__ Vg,
                 bf16* __restrict__ Ohg, bf16* __restrict__ Olg)
{
    extern __shared__ float smf[];
    float* Qs = smf;                         // [QT][QPAD]
    float* Ks = Qs + QT * QPAD;              // [DKH][KT]
    float* Vs = Ks + DKH * KT;               // [KT][DVH]
    float* Ps = Vs + KT * DVH;               // [QT][PPAD]

    const int qtile = blockIdx.x;
    const int bh    = blockIdx.y;
    const int b = bh >> 4, h = bh & 15;
    const int t = threadIdx.x;
    const int q = t >> 2;
    const int m = t & 3;
    const int q0 = qtile * QT;

    const float* xb = x  + (size_t)b * SQ * DMODEL + (size_t)h * DKH;
    const float* Kb = Kg + (size_t)b * SQ * DMODEL + (size_t)h * DKH;
    const float* Vb = Vg + (size_t)b * SQ * DHID   + (size_t)h * DVH;

    #pragma unroll
    for (int it = 0; it < 4; ++it) {
        int lin = t + it * 256;
        int r   = lin >> 4;
        int dc  = (lin & 15) * 4;
        float4 v = *(const float4*)&xb[(size_t)(q0 + r) * DMODEL + dc];
        Qs[r * QPAD + dc + 0] = v.x;
        Qs[r * QPAD + dc + 1] = v.y;
        Qs[r * QPAD + dc + 2] = v.z;
        Qs[r * QPAD + dc + 3] = v.w;
    }

    float acc[64];
    #pragma unroll
    for (int i = 0; i < 64; ++i) acc[i] = 0.f;
    float mrow = -INFINITY;
    float lrow = 0.f;

    for (int j = 0; j <= qtile; ++j) {
        const int kb = j * KT;
        __syncthreads();
        #pragma unroll
        for (int it = 0; it < 4; ++it) {
            int lin = t + it * 256;
            int r   = lin >> 4;
            int dc  = (lin & 15) * 4;
            float4 v = *(const float4*)&Kb[(size_t)(kb + r) * DMODEL + dc];
            Ks[(dc + 0) * KT + r] = v.x;
            Ks[(dc + 1) * KT + r] = v.y;
            Ks[(dc + 2) * KT + r] = v.z;
            Ks[(dc + 3) * KT + r] = v.w;
        }
        #pragma unroll
        for (int it = 0; it < 16; ++it) {
            int lin = t + it * 256;
            int r   = lin >> 6;
            int c   = (lin & 63) * 4;
            *(float4*)&Vs[r * DVH + c] =
                *(const float4*)&Vb[(size_t)(kb + r) * DHID + c];
        }
        __syncthreads();

        float s[16];
        #pragma unroll
        for (int i = 0; i < 16; ++i) s[i] = 0.f;
        #pragma unroll 4
        for (int d = 0; d < DKH; ++d) {
            float qv = Qs[q * QPAD + d];
            const float4* Krow = (const float4*)&Ks[d * KT];
            #pragma unroll
            for (int gg = 0; gg < 4; ++gg) {
                float4 kv = Krow[gg * 4 + m];
                s[gg * 4 + 0] += qv * kv.x;
                s[gg * 4 + 1] += qv * kv.y;
                s[gg * 4 + 2] += qv * kv.z;
                s[gg * 4 + 3] += qv * kv.w;
            }
        }
        if (j == qtile) {
            #pragma unroll
            for (int gg = 0; gg < 4; ++gg)
                #pragma unroll
                for (int i = 0; i < 4; ++i)
                    if (gg * 16 + m * 4 + i > q) s[gg * 4 + i] = -INFINITY;
        }
        float tmax = s[0];
        #pragma unroll
        for (int i = 1; i < 16; ++i) tmax = fmaxf(tmax, s[i]);
        tmax = fmaxf(tmax, __shfl_xor_sync(0xffffffffu, tmax, 1));
        tmax = fmaxf(tmax, __shfl_xor_sync(0xffffffffu, tmax, 2));

        float mnew  = fmaxf(mrow, tmax);
        float alpha = __expf(mrow - mnew);
        float psum = 0.f;
        #pragma unroll
        for (int gg = 0; gg < 4; ++gg)
            #pragma unroll
            for (int i = 0; i < 4; ++i) {
                float p = __expf(s[gg * 4 + i] - mnew);
                psum += p;
                Ps[q * PPAD + gg * 16 + m * 4 + i] = p;
            }
        psum += __shfl_xor_sync(0xffffffffu, psum, 1);
        psum += __shfl_xor_sync(0xffffffffu, psum, 2);
        lrow = lrow * alpha + psum;
        mrow = mnew;
        #pragma unroll
        for (int c = 0; c < 64; ++c) acc[c] *= alpha;
        __syncwarp();

        #pragma unroll 2
        for (int k = 0; k < KT; ++k) {
            float p = Ps[q * PPAD + k];
            const float4* Vrow = (const float4*)&Vs[k * DVH];
            #pragma unroll
            for (int gg = 0; gg < 16; ++gg) {
                float4 v = Vrow[gg * 4 + m];
                acc[gg * 4 + 0] += p * v.x;
                acc[gg * 4 + 1] += p * v.y;
                acc[gg * 4 + 2] += p * v.z;
                acc[gg * 4 + 3] += p * v.w;
            }
        }
    }

    // epilogue: normalize + GELU, emit bf16 hi/lo split for the final GEMM
    const float inv = 1.0f / lrow;
    size_t off = (size_t)(b * SQ + q0 + q) * DHID + (size_t)h * DVH;
    bf16* ohrow = Ohg + off;
    bf16* olrow = Olg + off;
    #pragma unroll
    for (int gg = 0; gg < 16; ++gg) {
        float v0 = gelu_exact(acc[gg*4 + 0] * inv);
        float v1 = gelu_exact(acc[gg*4 + 1] * inv);
        float v2 = gelu_exact(acc[gg*4 + 2] * inv);
        float v3 = gelu_exact(acc[gg*4 + 3] * inv);
        bf16 h0 = __float2bfloat16(v0), h1 = __float2bfloat16(v1);
        bf16 h2 = __float2bfloat16(v2), h3 = __float2bfloat16(v3);
        bf16 l0 = __float2bfloat16(v0 - __bfloat162float(h0));
        bf16 l1 = __float2bfloat16(v1 - __bfloat162float(h1));
        bf16 l2 = __float2bfloat16(v2 - __bfloat162float(h2));
        bf16 l3 = __float2bfloat16(v3 - __bfloat162float(h3));
        ((__nv_bfloat162*)(ohrow + gg*16 + m*4))[0] = __halves2bfloat162(h0, h1);
        ((__nv_bfloat162*)(ohrow + gg*16 + m*4))[1] = __halves2bfloat162(h2, h3);
        ((__nv_bfloat162*)(olrow + gg*16 + m*4))[0] = __halves2bfloat162(l0, l1);
        ((__nv_bfloat162*)(olrow + gg*16 + m*4))[1] = __halves2bfloat162(l2, l3);
    }
}

// ---------------------------------------------------------------------------
extern "C" void kernel_launch(void* const* d_in, const int* in_sizes, int n_in,
                              void* d_out, int out_size)
{
    const float* x  = (const float*)d_in[0];
    const float* Wk = (const float*)d_in[1];
    const float* bk = (const float*)d_in[2];
    const float* Wv = (const float*)d_in[3];
    const float* bv = (const float*)d_in[4];
    const float* Wf = (const float*)d_in[5];
    const float* bf_ = (const float*)d_in[6];
    float* out = (float*)d_out;

    float *gK, *gV;
    bf16 *gxh, *gxl, *gOh, *gOl, *gWkh, *gWkl, *gWvh, *gWvl, *gWfh, *gWfl;
    cudaGetSymbolAddress((void**)&gK,  g_K);
    cudaGetSymbolAddress((void**)&gV,  g_V);
    cudaGetSymbolAddress((void**)&gxh, g_xh);
    cudaGetSymbolAddress((void**)&gxl, g_xl);
    cudaGetSymbolAddress((void**)&gOh, g_Oh);
    cudaGetSymbolAddress((void**)&gOl, g_Ol);
    cudaGetSymbolAddress((void**)&gWkh, g_Wkh);
    cudaGetSymbolAddress((void**)&gWkl, g_Wkl);
    cudaGetSymbolAddress((void**)&gWvh, g_Wvh);
    cudaGetSymbolAddress((void**)&gWvl, g_Wvl);
    cudaGetSymbolAddress((void**)&gWfh, g_Wfh);
    cudaGetSymbolAddress((void**)&gWfl, g_Wfl);

    cudaFuncSetAttribute(attn_kernel,
        cudaFuncAttributeMaxDynamicSharedMemorySize, ATTN_SMEM);
    cudaFuncSetAttribute(gemm_mma_kernel<false>,
        cudaFuncAttributeMaxDynamicSharedMemorySize, GEMM_SMEM);
    cudaFuncSetAttribute(gemm_mma_kernel<true>,
        cudaFuncAttributeMaxDynamicSharedMemorySize, GEMM_SMEM);

    // 0) precision-split conversions
    convert_hl_kernel<<<(MROWS*DMODEL/4 + 255)/256, 256>>>(x, gxh, gxl, MROWS*DMODEL/4);
    transpose_hl_kernel<<<dim3(DMODEL/32, DMODEL/32), dim3(32,8)>>>(Wk, gWkh, gWkl, DMODEL, DMODEL);
    transpose_hl_kernel<<<dim3(DHID/32,   DMODEL/32), dim3(32,8)>>>(Wv, gWvh, gWvl, DMODEL, DHID);
    transpose_hl_kernel<<<dim3(DMODEL/32, DHID/32),   dim3(32,8)>>>(Wf, gWfh, gWfl, DHID, DMODEL);

    // 1) K = x @ Wk + bk   [4096,1024]
    gemm_mma_kernel<false><<<dim3(DMODEL/GBN, MROWS/GBM), 256, GEMM_SMEM>>>(
        gxh, gxl, gWkh, gWkl, bk, nullptr, gK, MROWS, DMODEL, DMODEL);

    // 2) V = x @ Wv + bv   [4096,4096]
    gemm_mma_kernel<false><<<dim3(DHID/GBN, MROWS/GBM), 256, GEMM_SMEM>>>(
        gxh, gxl, gWvh, gWvl, bv, nullptr, gV, MROWS, DHID, DMODEL);

    // 3) gelu(attn(x,K,V)) -> (Oh, Ol)
    attn_kernel<<<dim3(SQ/QT, BATCH*NHEADS), 256, ATTN_SMEM>>>(x, gK, gV, gOh, gOl);

    // 4) out = x + O @ Wf + bf   [4096,1024]
    gemm_mma_kernel<true><<<dim3(DMODEL/GBN, MROWS/GBM), 256, GEMM_SMEM>>>(
        gOh, gOl, gWfh, gWfl, bf_, x, out, MROWS, DMODEL, DHID);
}

// round 6
// speedup vs baseline: 3.8747x; 3.0996x over previous
#include <cuda_runtime.h>
#include <cuda_bf16.h>
#include <cstdint>
#include <cstddef>
#include <math.h>

// Problem constants
#define BATCH   2
#define SQ      2048
#define DMODEL  1024
#define NHEADS  16
#define DHID    4096
#define DKH     64
#define DVH     256
#define MROWS   (BATCH*SQ)   // 4096

typedef __nv_bfloat16 bf16;

// ---------------- scratch (device globals; no allocation allowed) ----------
__device__ bf16  g_xh[MROWS * DMODEL];
__device__ bf16  g_xl[MROWS * DMODEL];
__device__ bf16  g_Kh[MROWS * DMODEL];
__device__ bf16  g_Kl[MROWS * DMODEL];
__device__ bf16  g_Vh[MROWS * DHID];
__device__ bf16  g_Vl[MROWS * DHID];
__device__ bf16  g_Oh[MROWS * DHID];
__device__ bf16  g_Ol[MROWS * DHID];
__device__ bf16  g_Wkh[DMODEL * DMODEL];
__device__ bf16  g_Wkl[DMODEL * DMODEL];
__device__ bf16  g_Wvh[DHID * DMODEL];
__device__ bf16  g_Wvl[DHID * DMODEL];
__device__ bf16  g_Wfh[DMODEL * DHID];
__device__ bf16  g_Wfl[DMODEL * DHID];

// ---------------- helpers ---------------------------------------------------
__device__ __forceinline__ void cp16(void* s, const void* g) {
    uint32_t sa = (uint32_t)__cvta_generic_to_shared(s);
    asm volatile("cp.async.cg.shared.global [%0], [%1], 16;\n" :: "r"(sa), "l"(g));
}
__device__ __forceinline__ uint32_t lds32(const bf16* p) {
    return *reinterpret_cast<const uint32_t*>(p);
}
__device__ __forceinline__ uint32_t packbf2(bf16 a, bf16 b) {
    __nv_bfloat162 v = __halves2bfloat162(a, b);
    return *reinterpret_cast<uint32_t*>(&v);
}
__device__ __forceinline__ void mma_bf16(float* c, uint32_t a0, uint32_t a1,
                                         uint32_t a2, uint32_t a3,
                                         uint32_t b0, uint32_t b1) {
    asm volatile(
        "mma.sync.aligned.m16n8k16.row.col.f32.bf16.bf16.f32 "
        "{%0,%1,%2,%3}, {%4,%5,%6,%7}, {%8,%9}, {%0,%1,%2,%3};\n"
        : "+f"(c[0]), "+f"(c[1]), "+f"(c[2]), "+f"(c[3])
        : "r"(a0), "r"(a1), "r"(a2), "r"(a3), "r"(b0), "r"(b1));
}
__device__ __forceinline__ void ldmx4t(uint32_t& r0, uint32_t& r1,
                                       uint32_t& r2, uint32_t& r3, const bf16* p) {
    uint32_t a = (uint32_t)__cvta_generic_to_shared(p);
    asm volatile("ldmatrix.sync.aligned.m8n8.x4.trans.shared.b16 {%0,%1,%2,%3}, [%4];"
                 : "=r"(r0), "=r"(r1), "=r"(r2), "=r"(r3) : "r"(a));
}
__device__ __forceinline__ float gelu_exact(float v) {
    return 0.5f * v * (1.0f + erff(v * 0.70710678118654752f));
}

// ---------------- conversion kernels ---------------------------------------
__global__ __launch_bounds__(256)
void convert_hl_kernel(const float* __restrict__ src, bf16* __restrict__ hi,
                       bf16* __restrict__ lo, int n4)
{
    int i = blockIdx.x * blockDim.x + threadIdx.x;
    if (i >= n4) return;
    float4 v = ((const float4*)src)[i];
    bf16 h0 = __float2bfloat16(v.x), h1 = __float2bfloat16(v.y);
    bf16 h2 = __float2bfloat16(v.z), h3 = __float2bfloat16(v.w);
    bf16 l0 = __float2bfloat16(v.x - __bfloat162float(h0));
    bf16 l1 = __float2bfloat16(v.y - __bfloat162float(h1));
    bf16 l2 = __float2bfloat16(v.z - __bfloat162float(h2));
    bf16 l3 = __float2bfloat16(v.w - __bfloat162float(h3));
    ((uint32_t*)hi)[i*2 + 0] = packbf2(h0, h1);
    ((uint32_t*)hi)[i*2 + 1] = packbf2(h2, h3);
    ((uint32_t*)lo)[i*2 + 0] = packbf2(l0, l1);
    ((uint32_t*)lo)[i*2 + 1] = packbf2(l2, l3);
}

__global__ __launch_bounds__(256)
void transpose_hl_kernel(const float* __restrict__ W, bf16* __restrict__ Th,
                         bf16* __restrict__ Tl, int R, int C)
{
    __shared__ float tile[32][33];
    const int c0 = blockIdx.x * 32, r0 = blockIdx.y * 32;
    const int tx = threadIdx.x, ty = threadIdx.y;   // 32 x 8
    #pragma unroll
    for (int j = 0; j < 4; ++j)
        tile[ty + j*8][tx] = W[(size_t)(r0 + ty + j*8) * C + c0 + tx];
    __syncthreads();
    #pragma unroll
    for (int j = 0; j < 4; ++j) {
        float v = tile[tx][ty + j*8];
        bf16 h = __float2bfloat16(v);
        size_t o = (size_t)(c0 + ty + j*8) * R + r0 + tx;
        Th[o] = h;
        Tl[o] = __float2bfloat16(v - __bfloat162float(h));
    }
}

// ---------------- bf16-split tensor-core GEMM ------------------------------
#define GBM 128
#define GBN 128
#define GBK 32
#define LDT 40
#define TBUF (GBM * LDT)
#define GEMM_SMEM (8 * TBUF * (int)sizeof(bf16))

template<bool RES, bool SPLIT>
__global__ __launch_bounds__(256)
void gemm_mma_kernel(const bf16* __restrict__ Ah, const bf16* __restrict__ Al,
                     const bf16* __restrict__ Bh, const bf16* __restrict__ Bl,
                     const float* __restrict__ bias, const float* __restrict__ res,
                     float* __restrict__ C, bf16* __restrict__ Ch, bf16* __restrict__ Cl,
                     int M, int N, int K)
{
    extern __shared__ bf16 sm[];
    bf16* sAh = sm;
    bf16* sAl = sm + 2 * TBUF;
    bf16* sBh = sm + 4 * TBUF;
    bf16* sBl = sm + 6 * TBUF;

    const int t = threadIdx.x;
    const int warp = t >> 5, lane = t & 31;
    const int g = lane >> 2, tq = lane & 3;
    const int wm = warp >> 2, wn = warp & 3;
    const int m0 = wm * 64, n0 = wn * 32;
    const int rowBase = blockIdx.y * GBM, colBase = blockIdx.x * GBN;

    float acc[4][4][4];
    #pragma unroll
    for (int i = 0; i < 4; ++i)
        #pragma unroll
        for (int j = 0; j < 4; ++j)
            #pragma unroll
            for (int k = 0; k < 4; ++k) acc[i][j][k] = 0.f;

    auto load_tile = [&](int stage, int kt) {
        bf16* dAh = sAh + stage * TBUF;
        bf16* dAl = sAl + stage * TBUF;
        bf16* dBh = sBh + stage * TBUF;
        bf16* dBl = sBl + stage * TBUF;
        #pragma unroll
        for (int it = 0; it < 2; ++it) {
            int c  = t + it * 256;
            int r  = c >> 2, cc = (c & 3) * 8;
            size_t ga = (size_t)(rowBase + r) * K + kt + cc;
            size_t gb = (size_t)(colBase + r) * K + kt + cc;
            cp16(dAh + r * LDT + cc, Ah + ga);
            cp16(dAl + r * LDT + cc, Al + ga);
            cp16(dBh + r * LDT + cc, Bh + gb);
            cp16(dBl + r * LDT + cc, Bl + gb);
        }
    };

    const int nk = K / GBK;
    load_tile(0, 0);
    asm volatile("cp.async.commit_group;\n");

    for (int kt = 0; kt < nk; ++kt) {
        const int cur = kt & 1;
        if (kt + 1 < nk) load_tile(cur ^ 1, (kt + 1) * GBK);
        asm volatile("cp.async.commit_group;\n");
        asm volatile("cp.async.wait_group 1;\n");
        __syncthreads();

        const bf16* Ahc = sAh + cur * TBUF;
        const bf16* Alc = sAl + cur * TBUF;
        const bf16* Bhc = sBh + cur * TBUF;
        const bf16* Blc = sBl + cur * TBUF;

        #pragma unroll
        for (int ks = 0; ks < 2; ++ks) {
            uint32_t bhf[4][2], blf[4][2];
            #pragma unroll
            for (int ni = 0; ni < 4; ++ni) {
                const bf16* p = Bhc + (n0 + ni*8 + g) * LDT + ks*16 + tq*2;
                bhf[ni][0] = lds32(p);  bhf[ni][1] = lds32(p + 8);
                const bf16* q2 = Blc + (n0 + ni*8 + g) * LDT + ks*16 + tq*2;
                blf[ni][0] = lds32(q2); blf[ni][1] = lds32(q2 + 8);
            }
            #pragma unroll
            for (int mi = 0; mi < 4; ++mi) {
                const bf16* pa = Ahc + (m0 + mi*16 + g) * LDT + ks*16 + tq*2;
                uint32_t ah0 = lds32(pa),     ah1 = lds32(pa + 8*LDT);
                uint32_t ah2 = lds32(pa + 8), ah3 = lds32(pa + 8*LDT + 8);
                const bf16* pl = Alc + (m0 + mi*16 + g) * LDT + ks*16 + tq*2;
                uint32_t al0 = lds32(pl),     al1 = lds32(pl + 8*LDT);
                uint32_t al2 = lds32(pl + 8), al3 = lds32(pl + 8*LDT + 8);
                #pragma unroll
                for (int ni = 0; ni < 4; ++ni) {
                    mma_bf16(acc[mi][ni], ah0, ah1, ah2, ah3, bhf[ni][0], bhf[ni][1]);
                    mma_bf16(acc[mi][ni], ah0, ah1, ah2, ah3, blf[ni][0], blf[ni][1]);
                    mma_bf16(acc[mi][ni], al0, al1, al2, al3, bhf[ni][0], bhf[ni][1]);
                }
            }
        }
        __syncthreads();
    }

    #pragma unroll
    for (int mi = 0; mi < 4; ++mi) {
        #pragma unroll
        for (int ni = 0; ni < 4; ++ni) {
            int r0 = rowBase + m0 + mi*16 + g;
            int cb = colBase + n0 + ni*8 + tq*2;
            float b0 = bias[cb], b1 = bias[cb + 1];
            float v0 = acc[mi][ni][0] + b0, v1 = acc[mi][ni][1] + b1;
            float v2 = acc[mi][ni][2] + b0, v3 = acc[mi][ni][3] + b1;
            if (SPLIT) {
                bf16 h0 = __float2bfloat16(v0), h1 = __float2bfloat16(v1);
                bf16 h2 = __float2bfloat16(v2), h3 = __float2bfloat16(v3);
                bf16 e0 = __float2bfloat16(v0 - __bfloat162float(h0));
                bf16 e1 = __float2bfloat16(v1 - __bfloat162float(h1));
                bf16 e2 = __float2bfloat16(v2 - __bfloat162float(h2));
                bf16 e3 = __float2bfloat16(v3 - __bfloat162float(h3));
                *(uint32_t*)&Ch[(size_t)r0 * N + cb]     = packbf2(h0, h1);
                *(uint32_t*)&Cl[(size_t)r0 * N + cb]     = packbf2(e0, e1);
                *(uint32_t*)&Ch[(size_t)(r0+8) * N + cb] = packbf2(h2, h3);
                *(uint32_t*)&Cl[(size_t)(r0+8) * N + cb] = packbf2(e2, e3);
            } else {
                if (RES) {
                    float2 r0v = *(const float2*)&res[(size_t)r0 * N + cb];
                    float2 r1v = *(const float2*)&res[(size_t)(r0+8) * N + cb];
                    v0 += r0v.x; v1 += r0v.y; v2 += r1v.x; v3 += r1v.y;
                }
                float2 o0 = { v0, v1 }, o1 = { v2, v3 };
                *(float2*)&C[(size_t)r0 * N + cb]     = o0;
                *(float2*)&C[(size_t)(r0+8) * N + cb] = o1;
            }
        }
    }
}

// ---------------- tensor-core causal flash attention + GELU ----------------
#define AQT 128
#define AKT 64
#define LDQ 72
#define LDK 72
#define LDV 264
#define QBUF (AQT*LDQ)                 // 9216
#define KBUF (AKT*LDK)                 // 4608
#define VBUF (AKT*LDV)                 // 16896
#define ATTN_SMEM ((2*QBUF + 4*KBUF + 4*VBUF) * (int)sizeof(bf16))  // 208896

__global__ __launch_bounds__(256, 1)
void attn_mma_kernel(const bf16* __restrict__ xh, const bf16* __restrict__ xl,
                     const bf16* __restrict__ Kh, const bf16* __restrict__ Kl,
                     const bf16* __restrict__ Vh, const bf16* __restrict__ Vl,
                     bf16* __restrict__ Ohg, bf16* __restrict__ Olg)
{
    extern __shared__ bf16 smx[];
    bf16* sQh = smx;
    bf16* sQl = sQh + QBUF;
    bf16* sKh = sQl + QBUF;       // [2][KBUF]
    bf16* sKl = sKh + 2*KBUF;
    bf16* sVh = sKl + 2*KBUF;     // [2][VBUF]
    bf16* sVl = sVh + 2*VBUF;

    const int qtile = gridDim.x - 1 - blockIdx.x;   // long CTAs first
    const int bh = blockIdx.y;
    const int b = bh >> 4, h = bh & 15;
    const int q0 = qtile * AQT;
    const int t = threadIdx.x, warp = t >> 5, lane = t & 31;
    const int g = lane >> 2, tq = lane & 3;
    const int wrow = warp * 16;

    // ---- Q tile load (once) ----
    const size_t qbase = (size_t)(b*SQ + q0) * DMODEL + (size_t)h * DKH;
    #pragma unroll
    for (int i = 0; i < 8; ++i) {
        int chunk = t + i*256;              // 0..2047
        int r = chunk >> 4;
        int rem = chunk & 15;
        const bf16* src = (rem & 8) ? xl : xh;
        bf16* dst = (rem & 8) ? sQl : sQh;
        int c = (rem & 7) * 8;
        cp16(dst + r*LDQ + c, src + qbase + (size_t)r*DMODEL + c);
    }

    const size_t kbase = (size_t)(b*SQ) * DMODEL + (size_t)h * DKH;
    const size_t vbase = (size_t)(b*SQ) * DHID  + (size_t)h * DVH;

    auto load_kv = [&](int st, int kb) {
        bf16* dKh = sKh + st*KBUF;  bf16* dKl = sKl + st*KBUF;
        bf16* dVh = sVh + st*VBUF;  bf16* dVl = sVl + st*VBUF;
        #pragma unroll
        for (int i = 0; i < 4; ++i) {
            int chunk = t + i*256;          // 0..1023
            int r = chunk >> 4;
            int rem = chunk & 15;
            int c = (rem & 7) * 8;
            const bf16* src = (rem & 8) ? Kl : Kh;
            bf16* dst = (rem & 8) ? dKl : dKh;
            cp16(dst + r*LDK + c, src + kbase + (size_t)(kb + r)*DMODEL + c);
        }
        #pragma unroll
        for (int i = 0; i < 16; ++i) {
            int chunk = t + i*256;          // 0..4095
            int r = chunk >> 6;
            int rem = chunk & 63;
            int c = (rem & 31) * 8;
            const bf16* src = (rem & 32) ? Vl : Vh;
            bf16* dst = (rem & 32) ? dVl : dVh;
            cp16(dst + r*LDV + c, src + vbase + (size_t)(kb + r)*DHID + c);
        }
    };

    float acc[32][4];
    #pragma unroll
    for (int i = 0; i < 32; ++i) { acc[i][0]=0.f; acc[i][1]=0.f; acc[i][2]=0.f; acc[i][3]=0.f; }
    float m0 = -INFINITY, m1 = -INFINITY, l0 = 0.f, l1 = 0.f;

    const int ntiles = 2*qtile + 2;
    load_kv(0, 0);
    asm volatile("cp.async.commit_group;\n");

    // per-lane ldmatrix offset: matrices {k0-7,n0-7},{k8-15,n0-7},{k0-7,n8-15},{k8-15,n8-15}
    const int mat = lane >> 3;
    const int lmoff = ((mat & 1)*8 + (lane & 7)) * LDV + (mat >> 1)*8;

    const int qrow0 = q0 + wrow + g;
    const int qrow1 = qrow0 + 8;

    for (int j = 0; j < ntiles; ++j) {
        const int cur = j & 1;
        const int kb = j * AKT;
        if (j + 1 < ntiles) load_kv(cur ^ 1, kb + AKT);
        asm volatile("cp.async.commit_group;\n");
        asm volatile("cp.async.wait_group 1;\n");
        __syncthreads();

        const bool active = (kb <= q0 + wrow + 15);   // warp-uniform causal skip
        if (active) {
            const bf16* cKh = sKh + cur*KBUF;
            const bf16* cKl = sKl + cur*KBUF;
            const bf16* cVh = sVh + cur*VBUF;
            const bf16* cVl = sVl + cur*VBUF;

            // ---- S = Q @ K^T (hi/lo 3-mma split) ----
            float sc[8][4];
            #pragma unroll
            for (int nt = 0; nt < 8; ++nt) { sc[nt][0]=0.f; sc[nt][1]=0.f; sc[nt][2]=0.f; sc[nt][3]=0.f; }
            #pragma unroll
            for (int ks = 0; ks < 4; ++ks) {
                const bf16* pah = sQh + (wrow+g)*LDQ + ks*16 + tq*2;
                const bf16* pal = sQl + (wrow+g)*LDQ + ks*16 + tq*2;
                uint32_t qh0 = lds32(pah),     qh1 = lds32(pah + 8*LDQ);
                uint32_t qh2 = lds32(pah + 8), qh3 = lds32(pah + 8*LDQ + 8);
                uint32_t ql0 = lds32(pal),     ql1 = lds32(pal + 8*LDQ);
                uint32_t ql2 = lds32(pal + 8), ql3 = lds32(pal + 8*LDQ + 8);
                #pragma unroll
                for (int nt = 0; nt < 8; ++nt) {
                    const bf16* pbh = cKh + (nt*8+g)*LDK + ks*16 + tq*2;
                    const bf16* pbl = cKl + (nt*8+g)*LDK + ks*16 + tq*2;
                    uint32_t kh0 = lds32(pbh), kh1 = lds32(pbh + 8);
                    uint32_t kl0 = lds32(pbl), kl1 = lds32(pbl + 8);
                    mma_bf16(sc[nt], qh0,qh1,qh2,qh3, kh0, kh1);
                    mma_bf16(sc[nt], ql0,ql1,ql2,ql3, kh0, kh1);
                    mma_bf16(sc[nt], qh0,qh1,qh2,qh3, kl0, kl1);
                }
            }

            // ---- causal mask ----
            if (kb + AKT - 1 > q0 + wrow) {
                #pragma unroll
                for (int nt = 0; nt < 8; ++nt) {
                    int k0 = kb + nt*8 + tq*2;
                    if (k0     > qrow0) sc[nt][0] = -INFINITY;
                    if (k0 + 1 > qrow0) sc[nt][1] = -INFINITY;
                    if (k0     > qrow1) sc[nt][2] = -INFINITY;
                    if (k0 + 1 > qrow1) sc[nt][3] = -INFINITY;
                }
            }

            // ---- online softmax (warp-local rows) ----
            float mx0 = -INFINITY, mx1 = -INFINITY;
            #pragma unroll
            for (int nt = 0; nt < 8; ++nt) {
                mx0 = fmaxf(mx0, fmaxf(sc[nt][0], sc[nt][1]));
                mx1 = fmaxf(mx1, fmaxf(sc[nt][2], sc[nt][3]));
            }
            mx0 = fmaxf(mx0, __shfl_xor_sync(0xffffffffu, mx0, 1));
            mx0 = fmaxf(mx0, __shfl_xor_sync(0xffffffffu, mx0, 2));
            mx1 = fmaxf(mx1, __shfl_xor_sync(0xffffffffu, mx1, 1));
            mx1 = fmaxf(mx1, __shfl_xor_sync(0xffffffffu, mx1, 2));
            float mn0 = fmaxf(m0, mx0), mn1 = fmaxf(m1, mx1);
            float al0 = __expf(m0 - mn0), al1 = __expf(m1 - mn1);
            m0 = mn0; m1 = mn1;

            float ps0 = 0.f, ps1 = 0.f;
            uint32_t ph[8][2], pel[8][2];
            #pragma unroll
            for (int nt = 0; nt < 8; ++nt) {
                float p0 = __expf(sc[nt][0] - mn0);
                float p1 = __expf(sc[nt][1] - mn0);
                float p2 = __expf(sc[nt][2] - mn1);
                float p3 = __expf(sc[nt][3] - mn1);
                ps0 += p0 + p1; ps1 += p2 + p3;
                bf16 h0 = __float2bfloat16(p0), h1 = __float2bfloat16(p1);
                bf16 h2 = __float2bfloat16(p2), h3 = __float2bfloat16(p3);
                bf16 e0 = __float2bfloat16(p0 - __bfloat162float(h0));
                bf16 e1 = __float2bfloat16(p1 - __bfloat162float(h1));
                bf16 e2 = __float2bfloat16(p2 - __bfloat162float(h2));
                bf16 e3 = __float2bfloat16(p3 - __bfloat162float(h3));
                ph[nt][0]  = packbf2(h0, h1);  ph[nt][1]  = packbf2(h2, h3);
                pel[nt][0] = packbf2(e0, e1);  pel[nt][1] = packbf2(e2, e3);
            }
            ps0 += __shfl_xor_sync(0xffffffffu, ps0, 1);
            ps0 += __shfl_xor_sync(0xffffffffu, ps0, 2);
            ps1 += __shfl_xor_sync(0xffffffffu, ps1, 1);
            ps1 += __shfl_xor_sync(0xffffffffu, ps1, 2);
            l0 = l0*al0 + ps0;
            l1 = l1*al1 + ps1;
            #pragma unroll
            for (int i = 0; i < 32; ++i) {
                acc[i][0] *= al0; acc[i][1] *= al0;
                acc[i][2] *= al1; acc[i][3] *= al1;
            }

            // ---- O += P @ V (P in regs; V via ldmatrix.trans) ----
            #pragma unroll
            for (int kk = 0; kk < 4; ++kk) {
                uint32_t a0 = ph[2*kk][0],  a1 = ph[2*kk][1];
                uint32_t a2 = ph[2*kk+1][0], a3 = ph[2*kk+1][1];
                uint32_t e0 = pel[2*kk][0],  e1 = pel[2*kk][1];
                uint32_t e2 = pel[2*kk+1][0], e3 = pel[2*kk+1][1];
                #pragma unroll
                for (int ng = 0; ng < 16; ++ng) {
                    uint32_t vh0,vh1,vh2,vh3, vl0,vl1,vl2,vl3;
                    ldmx4t(vh0,vh1,vh2,vh3, cVh + kk*16*LDV + ng*16 + lmoff);
                    ldmx4t(vl0,vl1,vl2,vl3, cVl + kk*16*LDV + ng*16 + lmoff);
                    mma_bf16(acc[2*ng],   a0,a1,a2,a3, vh0, vh1);
                    mma_bf16(acc[2*ng],   e0,e1,e2,e3, vh0, vh1);
                    mma_bf16(acc[2*ng],   a0,a1,a2,a3, vl0, vl1);
                    mma_bf16(acc[2*ng+1], a0,a1,a2,a3, vh2, vh3);
                    mma_bf16(acc[2*ng+1], e0,e1,e2,e3, vh2, vh3);
                    mma_bf16(acc[2*ng+1], a0,a1,a2,a3, vl2, vl3);
                }
            }
        }
        __syncthreads();
    }

    // ---- epilogue: normalize + GELU -> bf16 hi/lo split ----
    const float inv0 = 1.0f / l0, inv1 = 1.0f / l1;
    bf16* oh0 = Ohg + ((size_t)b*SQ + qrow0)*DHID + (size_t)h*DVH;
    bf16* ol0 = Olg + ((size_t)b*SQ + qrow0)*DHID + (size_t)h*DVH;
    bf16* oh1 = Ohg + ((size_t)b*SQ + qrow1)*DHID + (size_t)h*DVH;
    bf16* ol1 = Olg + ((size_t)b*SQ + qrow1)*DHID + (size_t)h*DVH;
    #pragma unroll
    for (int nt = 0; nt < 32; ++nt) {
        int c = nt*8 + tq*2;
        float v0 = gelu_exact(acc[nt][0] * inv0);
        float v1 = gelu_exact(acc[nt][1] * inv0);
        float v2 = gelu_exact(acc[nt][2] * inv1);
        float v3 = gelu_exact(acc[nt][3] * inv1);
        bf16 h0 = __float2bfloat16(v0), h1 = __float2bfloat16(v1);
        bf16 h2 = __float2bfloat16(v2), h3 = __float2bfloat16(v3);
        bf16 e0 = __float2bfloat16(v0 - __bfloat162float(h0));
        bf16 e1 = __float2bfloat16(v1 - __bfloat162float(h1));
        bf16 e2 = __float2bfloat16(v2 - __bfloat162float(h2));
        bf16 e3 = __float2bfloat16(v3 - __bfloat162float(h3));
        *(uint32_t*)(oh0 + c) = packbf2(h0, h1);
        *(uint32_t*)(ol0 + c) = packbf2(e0, e1);
        *(uint32_t*)(oh1 + c) = packbf2(h2, h3);
        *(uint32_t*)(ol1 + c) = packbf2(e2, e3);
    }
}

// ---------------------------------------------------------------------------
extern "C" void kernel_launch(void* const* d_in, const int* in_sizes, int n_in,
                              void* d_out, int out_size)
{
    const float* x  = (const float*)d_in[0];
    const float* Wk = (const float*)d_in[1];
    const float* bk = (const float*)d_in[2];
    const float* Wv = (const float*)d_in[3];
    const float* bv = (const float*)d_in[4];
    const float* Wf = (const float*)d_in[5];
    const float* bf_ = (const float*)d_in[6];
    float* out = (float*)d_out;

    bf16 *gxh, *gxl, *gKh, *gKl, *gVh, *gVl, *gOh, *gOl;
    bf16 *gWkh, *gWkl, *gWvh, *gWvl, *gWfh, *gWfl;
    cudaGetSymbolAddress((void**)&gxh, g_xh);
    cudaGetSymbolAddress((void**)&gxl, g_xl);
    cudaGetSymbolAddress((void**)&gKh, g_Kh);
    cudaGetSymbolAddress((void**)&gKl, g_Kl);
    cudaGetSymbolAddress((void**)&gVh, g_Vh);
    cudaGetSymbolAddress((void**)&gVl, g_Vl);
    cudaGetSymbolAddress((void**)&gOh, g_Oh);
    cudaGetSymbolAddress((void**)&gOl, g_Ol);
    cudaGetSymbolAddress((void**)&gWkh, g_Wkh);
    cudaGetSymbolAddress((void**)&gWkl, g_Wkl);
    cudaGetSymbolAddress((void**)&gWvh, g_Wvh);
    cudaGetSymbolAddress((void**)&gWvl, g_Wvl);
    cudaGetSymbolAddress((void**)&gWfh, g_Wfh);
    cudaGetSymbolAddress((void**)&gWfl, g_Wfl);

    cudaFuncSetAttribute(attn_mma_kernel,
        cudaFuncAttributeMaxDynamicSharedMemorySize, ATTN_SMEM);
    cudaFuncSetAttribute(gemm_mma_kernel<false, true>,
        cudaFuncAttributeMaxDynamicSharedMemorySize, GEMM_SMEM);
    cudaFuncSetAttribute(gemm_mma_kernel<true, false>,
        cudaFuncAttributeMaxDynamicSharedMemorySize, GEMM_SMEM);

    // 0) precision-split conversions
    convert_hl_kernel<<<(MROWS*DMODEL/4 + 255)/256, 256>>>(x, gxh, gxl, MROWS*DMODEL/4);
    transpose_hl_kernel<<<dim3(DMODEL/32, DMODEL/32), dim3(32,8)>>>(Wk, gWkh, gWkl, DMODEL, DMODEL);
    transpose_hl_kernel<<<dim3(DHID/32,   DMODEL/32), dim3(32,8)>>>(Wv, gWvh, gWvl, DMODEL, DHID);
    transpose_hl_kernel<<<dim3(DMODEL/32, DHID/32),   dim3(32,8)>>>(Wf, gWfh, gWfl, DHID, DMODEL);

    // 1) K = x @ Wk + bk  -> bf16 hi/lo
    gemm_mma_kernel<false, true><<<dim3(DMODEL/GBN, MROWS/GBM), 256, GEMM_SMEM>>>(
        gxh, gxl, gWkh, gWkl, bk, nullptr, nullptr, gKh, gKl, MROWS, DMODEL, DMODEL);

    // 2) V = x @ Wv + bv  -> bf16 hi/lo
    gemm_mma_kernel<false, true><<<dim3(DHID/GBN, MROWS/GBM), 256, GEMM_SMEM>>>(
        gxh, gxl, gWvh, gWvl, bv, nullptr, nullptr, gVh, gVl, MROWS, DHID, DMODEL);

    // 3) gelu(attn(x,K,V)) -> (Oh, Ol)  [tensor-core flash attention]
    attn_mma_kernel<<<dim3(SQ/AQT, BATCH*NHEADS), 256, ATTN_SMEM>>>(
        gxh, gxl, gKh, gKl, gVh, gVl, gOh, gOl);

    // 4) out = x + O @ Wf + bf
    gemm_mma_kernel<true, false><<<dim3(DMODEL/GBN, MROWS/GBM), 256, GEMM_SMEM>>>(
        gOh, gOl, gWfh, gWfl, bf_, x, out, nullptr, nullptr, MROWS, DMODEL, DHID);
}

// round 7
// speedup vs baseline: 5.6761x; 1.4649x over previous
#include <cuda_runtime.h>
#include <cuda_bf16.h>
#include <cuda_fp16.h>
#include <cstdint>
#include <cstddef>
#include <math.h>

// Problem constants
#define BATCH   2
#define SQ      2048
#define DMODEL  1024
#define NHEADS  16
#define DHID    4096
#define DKH     64
#define DVH     256
#define MROWS   (BATCH*SQ)   // 4096

typedef __nv_bfloat16 bf16;
typedef __half        f16;

// ---------------- scratch (device globals; no allocation allowed) ----------
__device__ bf16  g_xh [MROWS * DMODEL];   // x bf16 hi (K GEMM + attention Q)
__device__ bf16  g_xl [MROWS * DMODEL];   // x bf16 lo
__device__ f16   g_xfh[MROWS * DMODEL];   // x fp16 hi (V GEMM)
__device__ f16   g_xfl[MROWS * DMODEL];   // x fp16 lo
__device__ bf16  g_Kh [MROWS * DMODEL];   // K bf16 hi
__device__ bf16  g_Kl [MROWS * DMODEL];   // K bf16 lo
__device__ f16   g_Vf [MROWS * DHID];     // V fp16 single
__device__ f16   g_Oh [MROWS * DHID];     // gelu(attn) fp16 hi
__device__ f16   g_Ol [MROWS * DHID];     // gelu(attn) fp16 lo
__device__ bf16  g_Wkh[DMODEL * DMODEL];  // Wk^T bf16 hi
__device__ bf16  g_Wkl[DMODEL * DMODEL];  // Wk^T bf16 lo
__device__ f16   g_Wvf[DHID * DMODEL];    // Wv^T fp16 single
__device__ f16   g_Wff[DMODEL * DHID];    // Wf^T fp16 single

// ---------------- helpers ---------------------------------------------------
__device__ __forceinline__ void cp16(void* s, const void* g) {
    uint32_t sa = (uint32_t)__cvta_generic_to_shared(s);
    asm volatile("cp.async.cg.shared.global [%0], [%1], 16;\n" :: "r"(sa), "l"(g));
}
template<class T>
__device__ __forceinline__ uint32_t lds32(const T* p) {
    return *reinterpret_cast<const uint32_t*>(p);
}
__device__ __forceinline__ uint32_t packbf2(bf16 a, bf16 b) {
    __nv_bfloat162 v = __halves2bfloat162(a, b);
    return *reinterpret_cast<uint32_t*>(&v);
}
__device__ __forceinline__ uint32_t packh2(float a, float b) {
    __half2 v = __floats2half2_rn(a, b);
    return *reinterpret_cast<uint32_t*>(&v);
}
__device__ __forceinline__ void mma_bf16(float* c, uint32_t a0, uint32_t a1,
                                         uint32_t a2, uint32_t a3,
                                         uint32_t b0, uint32_t b1) {
    asm volatile(
        "mma.sync.aligned.m16n8k16.row.col.f32.bf16.bf16.f32 "
        "{%0,%1,%2,%3}, {%4,%5,%6,%7}, {%8,%9}, {%0,%1,%2,%3};\n"
        : "+f"(c[0]), "+f"(c[1]), "+f"(c[2]), "+f"(c[3])
        : "r"(a0), "r"(a1), "r"(a2), "r"(a3), "r"(b0), "r"(b1));
}
__device__ __forceinline__ void mma_f16(float* c, uint32_t a0, uint32_t a1,
                                        uint32_t a2, uint32_t a3,
                                        uint32_t b0, uint32_t b1) {
    asm volatile(
        "mma.sync.aligned.m16n8k16.row.col.f32.f16.f16.f32 "
        "{%0,%1,%2,%3}, {%4,%5,%6,%7}, {%8,%9}, {%0,%1,%2,%3};\n"
        : "+f"(c[0]), "+f"(c[1]), "+f"(c[2]), "+f"(c[3])
        : "r"(a0), "r"(a1), "r"(a2), "r"(a3), "r"(b0), "r"(b1));
}
__device__ __forceinline__ void ldmx4t(uint32_t& r0, uint32_t& r1,
                                       uint32_t& r2, uint32_t& r3, const void* p) {
    uint32_t a = (uint32_t)__cvta_generic_to_shared(p);
    asm volatile("ldmatrix.sync.aligned.m8n8.x4.trans.shared.b16 {%0,%1,%2,%3}, [%4];"
                 : "=r"(r0), "=r"(r1), "=r"(r2), "=r"(r3) : "r"(a));
}
__device__ __forceinline__ float gelu_exact(float v) {
    return 0.5f * v * (1.0f + erff(v * 0.70710678118654752f));
}

// ---------------- conversion kernels ---------------------------------------
// x -> bf16 hi/lo + fp16 hi/lo in one pass
__global__ __launch_bounds__(256)
void convert_x_kernel(const float* __restrict__ src,
                      bf16* __restrict__ bh, bf16* __restrict__ bl,
                      f16*  __restrict__ fh, f16*  __restrict__ fl, int n4)
{
    int i = blockIdx.x * blockDim.x + threadIdx.x;
    if (i >= n4) return;
    float4 v = ((const float4*)src)[i];
    // bf16 split
    bf16 h0 = __float2bfloat16(v.x), h1 = __float2bfloat16(v.y);
    bf16 h2 = __float2bfloat16(v.z), h3 = __float2bfloat16(v.w);
    ((uint32_t*)bh)[i*2+0] = packbf2(h0, h1);
    ((uint32_t*)bh)[i*2+1] = packbf2(h2, h3);
    ((uint32_t*)bl)[i*2+0] = packbf2(__float2bfloat16(v.x - __bfloat162float(h0)),
                                     __float2bfloat16(v.y - __bfloat162float(h1)));
    ((uint32_t*)bl)[i*2+1] = packbf2(__float2bfloat16(v.z - __bfloat162float(h2)),
                                     __float2bfloat16(v.w - __bfloat162float(h3)));
    // fp16 split
    f16 p0 = __float2half_rn(v.x), p1 = __float2half_rn(v.y);
    f16 p2 = __float2half_rn(v.z), p3 = __float2half_rn(v.w);
    __half2 ph0 = __halves2half2(p0, p1), ph1 = __halves2half2(p2, p3);
    ((uint32_t*)fh)[i*2+0] = *(uint32_t*)&ph0;
    ((uint32_t*)fh)[i*2+1] = *(uint32_t*)&ph1;
    ((uint32_t*)fl)[i*2+0] = packh2(v.x - __half2float(p0), v.y - __half2float(p1));
    ((uint32_t*)fl)[i*2+1] = packh2(v.z - __half2float(p2), v.w - __half2float(p3));
}

// fp32 [R][C] -> transposed bf16 hi/lo [C][R]
__global__ __launch_bounds__(256)
void transpose_hl_kernel(const float* __restrict__ W, bf16* __restrict__ Th,
                         bf16* __restrict__ Tl, int R, int C)
{
    __shared__ float tile[32][33];
    const int c0 = blockIdx.x * 32, r0 = blockIdx.y * 32;
    const int tx = threadIdx.x, ty = threadIdx.y;
    #pragma unroll
    for (int j = 0; j < 4; ++j)
        tile[ty + j*8][tx] = W[(size_t)(r0 + ty + j*8) * C + c0 + tx];
    __syncthreads();
    #pragma unroll
    for (int j = 0; j < 4; ++j) {
        float v = tile[tx][ty + j*8];
        bf16 h = __float2bfloat16(v);
        size_t o = (size_t)(c0 + ty + j*8) * R + r0 + tx;
        Th[o] = h;
        Tl[o] = __float2bfloat16(v - __bfloat162float(h));
    }
}

// fp32 [R][C] -> transposed fp16 single [C][R]
__global__ __launch_bounds__(256)
void transpose_f16_kernel(const float* __restrict__ W, f16* __restrict__ T,
                          int R, int C)
{
    __shared__ float tile[32][33];
    const int c0 = blockIdx.x * 32, r0 = blockIdx.y * 32;
    const int tx = threadIdx.x, ty = threadIdx.y;
    #pragma unroll
    for (int j = 0; j < 4; ++j)
        tile[ty + j*8][tx] = W[(size_t)(r0 + ty + j*8) * C + c0 + tx];
    __syncthreads();
    #pragma unroll
    for (int j = 0; j < 4; ++j)
        T[(size_t)(c0 + ty + j*8) * R + r0 + tx] = __float2half_rn(tile[tx][ty + j*8]);
}

// ---------------- GEMM tiling constants ------------------------------------
#define GBM 128
#define GBN 128
#define GBK 32
#define LDT 40
#define TBUF (GBM * LDT)
#define GEMM_SMEM_BF (8 * TBUF * (int)sizeof(bf16))   // 81920
#define GEMM_SMEM_F  (6 * TBUF * (int)sizeof(f16))    // 61440

// ---- bf16 3-mma split GEMM (K projection): out = bf16 hi/lo pair ----------
__global__ __launch_bounds__(256)
void gemm_bf16_kernel(const bf16* __restrict__ Ah, const bf16* __restrict__ Al,
                      const bf16* __restrict__ Bh, const bf16* __restrict__ Bl,
                      const float* __restrict__ bias,
                      bf16* __restrict__ Ch, bf16* __restrict__ Cl,
                      int M, int N, int K)
{
    extern __shared__ bf16 sm[];
    bf16* sAh = sm;
    bf16* sAl = sm + 2 * TBUF;
    bf16* sBh = sm + 4 * TBUF;
    bf16* sBl = sm + 6 * TBUF;

    const int t = threadIdx.x;
    const int warp = t >> 5, lane = t & 31;
    const int g = lane >> 2, tq = lane & 3;
    const int wm = warp >> 2, wn = warp & 3;
    const int m0 = wm * 64, n0 = wn * 32;
    const int rowBase = blockIdx.y * GBM, colBase = blockIdx.x * GBN;

    float acc[4][4][4];
    #pragma unroll
    for (int i = 0; i < 4; ++i)
        #pragma unroll
        for (int j = 0; j < 4; ++j)
            #pragma unroll
            for (int k = 0; k < 4; ++k) acc[i][j][k] = 0.f;

    auto load_tile = [&](int stage, int kt) {
        bf16* dAh = sAh + stage * TBUF;
        bf16* dAl = sAl + stage * TBUF;
        bf16* dBh = sBh + stage * TBUF;
        bf16* dBl = sBl + stage * TBUF;
        #pragma unroll
        for (int it = 0; it < 2; ++it) {
            int c  = t + it * 256;
            int r  = c >> 2, cc = (c & 3) * 8;
            size_t ga = (size_t)(rowBase + r) * K + kt + cc;
            size_t gb = (size_t)(colBase + r) * K + kt + cc;
            cp16(dAh + r * LDT + cc, Ah + ga);
            cp16(dAl + r * LDT + cc, Al + ga);
            cp16(dBh + r * LDT + cc, Bh + gb);
            cp16(dBl + r * LDT + cc, Bl + gb);
        }
    };

    const int nk = K / GBK;
    load_tile(0, 0);
    asm volatile("cp.async.commit_group;\n");

    for (int kt = 0; kt < nk; ++kt) {
        const int cur = kt & 1;
        if (kt + 1 < nk) load_tile(cur ^ 1, (kt + 1) * GBK);
        asm volatile("cp.async.commit_group;\n");
        asm volatile("cp.async.wait_group 1;\n");
        __syncthreads();

        const bf16* Ahc = sAh + cur * TBUF;
        const bf16* Alc = sAl + cur * TBUF;
        const bf16* Bhc = sBh + cur * TBUF;
        const bf16* Blc = sBl + cur * TBUF;

        #pragma unroll
        for (int ks = 0; ks < 2; ++ks) {
            uint32_t bhf[4][2], blf[4][2];
            #pragma unroll
            for (int ni = 0; ni < 4; ++ni) {
                const bf16* p = Bhc + (n0 + ni*8 + g) * LDT + ks*16 + tq*2;
                bhf[ni][0] = lds32(p);  bhf[ni][1] = lds32(p + 8);
                const bf16* q2 = Blc + (n0 + ni*8 + g) * LDT + ks*16 + tq*2;
                blf[ni][0] = lds32(q2); blf[ni][1] = lds32(q2 + 8);
            }
            #pragma unroll
            for (int mi = 0; mi < 4; ++mi) {
                const bf16* pa = Ahc + (m0 + mi*16 + g) * LDT + ks*16 + tq*2;
                uint32_t ah0 = lds32(pa),     ah1 = lds32(pa + 8*LDT);
                uint32_t ah2 = lds32(pa + 8), ah3 = lds32(pa + 8*LDT + 8);
                const bf16* pl = Alc + (m0 + mi*16 + g) * LDT + ks*16 + tq*2;
                uint32_t al0 = lds32(pl),     al1 = lds32(pl + 8*LDT);
                uint32_t al2 = lds32(pl + 8), al3 = lds32(pl + 8*LDT + 8);
                #pragma unroll
                for (int ni = 0; ni < 4; ++ni) {
                    mma_bf16(acc[mi][ni], ah0, ah1, ah2, ah3, bhf[ni][0], bhf[ni][1]);
                    mma_bf16(acc[mi][ni], ah0, ah1, ah2, ah3, blf[ni][0], blf[ni][1]);
                    mma_bf16(acc[mi][ni], al0, al1, al2, al3, bhf[ni][0], bhf[ni][1]);
                }
            }
        }
        __syncthreads();
    }

    #pragma unroll
    for (int mi = 0; mi < 4; ++mi) {
        #pragma unroll
        for (int ni = 0; ni < 4; ++ni) {
            int r0 = rowBase + m0 + mi*16 + g;
            int cb = colBase + n0 + ni*8 + tq*2;
            float b0 = bias[cb], b1 = bias[cb + 1];
            float v0 = acc[mi][ni][0] + b0, v1 = acc[mi][ni][1] + b1;
            float v2 = acc[mi][ni][2] + b0, v3 = acc[mi][ni][3] + b1;
            bf16 h0 = __float2bfloat16(v0), h1 = __float2bfloat16(v1);
            bf16 h2 = __float2bfloat16(v2), h3 = __float2bfloat16(v3);
            *(uint32_t*)&Ch[(size_t)r0 * N + cb]     = packbf2(h0, h1);
            *(uint32_t*)&Cl[(size_t)r0 * N + cb]     =
                packbf2(__float2bfloat16(v0 - __bfloat162float(h0)),
                        __float2bfloat16(v1 - __bfloat162float(h1)));
            *(uint32_t*)&Ch[(size_t)(r0+8) * N + cb] = packbf2(h2, h3);
            *(uint32_t*)&Cl[(size_t)(r0+8) * N + cb] =
                packbf2(__float2bfloat16(v2 - __bfloat162float(h2)),
                        __float2bfloat16(v3 - __bfloat162float(h3)));
        }
    }
}

// ---- fp16 2-mma GEMM: C = (Ah+Al) @ B^T + bias, A fp16 pair, B fp16 single
//  OUT==0: emit fp16 single.  OUT==1: emit fp32 with residual.
template<int OUT>
__global__ __launch_bounds__(256)
void gemm_f16_kernel(const f16* __restrict__ Ah, const f16* __restrict__ Al,
                     const f16* __restrict__ B,
                     const float* __restrict__ bias, const float* __restrict__ res,
                     f16* __restrict__ Cf, float* __restrict__ C32,
                     int M, int N, int K)
{
    extern __shared__ f16 smh[];
    f16* sAh = smh;
    f16* sAl = smh + 2 * TBUF;
    f16* sB  = smh + 4 * TBUF;

    const int t = threadIdx.x;
    const int warp = t >> 5, lane = t & 31;
    const int g = lane >> 2, tq = lane & 3;
    const int wm = warp >> 2, wn = warp & 3;
    const int m0 = wm * 64, n0 = wn * 32;
    const int rowBase = blockIdx.y * GBM, colBase = blockIdx.x * GBN;

    float acc[4][4][4];
    #pragma unroll
    for (int i = 0; i < 4; ++i)
        #pragma unroll
        for (int j = 0; j < 4; ++j)
            #pragma unroll
            for (int k = 0; k < 4; ++k) acc[i][j][k] = 0.f;

    auto load_tile = [&](int stage, int kt) {
        f16* dAh = sAh + stage * TBUF;
        f16* dAl = sAl + stage * TBUF;
        f16* dB  = sB  + stage * TBUF;
        #pragma unroll
        for (int it = 0; it < 2; ++it) {
            int c  = t + it * 256;
            int r  = c >> 2, cc = (c & 3) * 8;
            size_t ga = (size_t)(rowBase + r) * K + kt + cc;
            size_t gb = (size_t)(colBase + r) * K + kt + cc;
            cp16(dAh + r * LDT + cc, Ah + ga);
            cp16(dAl + r * LDT + cc, Al + ga);
            cp16(dB  + r * LDT + cc, B  + gb);
        }
    };

    const int nk = K / GBK;
    load_tile(0, 0);
    asm volatile("cp.async.commit_group;\n");

    for (int kt = 0; kt < nk; ++kt) {
        const int cur = kt & 1;
        if (kt + 1 < nk) load_tile(cur ^ 1, (kt + 1) * GBK);
        asm volatile("cp.async.commit_group;\n");
        asm volatile("cp.async.wait_group 1;\n");
        __syncthreads();

        const f16* Ahc = sAh + cur * TBUF;
        const f16* Alc = sAl + cur * TBUF;
        const f16* Bc  = sB  + cur * TBUF;

        #pragma unroll
        for (int ks = 0; ks < 2; ++ks) {
            uint32_t bf[4][2];
            #pragma unroll
            for (int ni = 0; ni < 4; ++ni) {
                const f16* p = Bc + (n0 + ni*8 + g) * LDT + ks*16 + tq*2;
                bf[ni][0] = lds32(p);  bf[ni][1] = lds32(p + 8);
            }
            #pragma unroll
            for (int mi = 0; mi < 4; ++mi) {
                const f16* pa = Ahc + (m0 + mi*16 + g) * LDT + ks*16 + tq*2;
                uint32_t ah0 = lds32(pa),     ah1 = lds32(pa + 8*LDT);
                uint32_t ah2 = lds32(pa + 8), ah3 = lds32(pa + 8*LDT + 8);
                const f16* pl = Alc + (m0 + mi*16 + g) * LDT + ks*16 + tq*2;
                uint32_t al0 = lds32(pl),     al1 = lds32(pl + 8*LDT);
                uint32_t al2 = lds32(pl + 8), al3 = lds32(pl + 8*LDT + 8);
                #pragma unroll
                for (int ni = 0; ni < 4; ++ni) {
                    mma_f16(acc[mi][ni], ah0, ah1, ah2, ah3, bf[ni][0], bf[ni][1]);
                    mma_f16(acc[mi][ni], al0, al1, al2, al3, bf[ni][0], bf[ni][1]);
                }
            }
        }
        __syncthreads();
    }

    #pragma unroll
    for (int mi = 0; mi < 4; ++mi) {
        #pragma unroll
        for (int ni = 0; ni < 4; ++ni) {
            int r0 = rowBase + m0 + mi*16 + g;
            int cb = colBase + n0 + ni*8 + tq*2;
            float b0 = bias[cb], b1 = bias[cb + 1];
            float v0 = acc[mi][ni][0] + b0, v1 = acc[mi][ni][1] + b1;
            float v2 = acc[mi][ni][2] + b0, v3 = acc[mi][ni][3] + b1;
            if (OUT == 0) {
                *(uint32_t*)&Cf[(size_t)r0 * N + cb]     = packh2(v0, v1);
                *(uint32_t*)&Cf[(size_t)(r0+8) * N + cb] = packh2(v2, v3);
            } else {
                float2 r0v = *(const float2*)&res[(size_t)r0 * N + cb];
                float2 r1v = *(const float2*)&res[(size_t)(r0+8) * N + cb];
                float2 o0 = { v0 + r0v.x, v1 + r0v.y };
                float2 o1 = { v2 + r1v.x, v3 + r1v.y };
                *(float2*)&C32[(size_t)r0 * N + cb]     = o0;
                *(float2*)&C32[(size_t)(r0+8) * N + cb] = o1;
            }
        }
    }
}

// ---------------- tensor-core causal flash attention + GELU ----------------
#define AQT 128
#define AKT 64
#define LDQ 72
#define LDK 72
#define LDV 264
#define QBUF (AQT*LDQ)                 // 9216
#define KBUF (AKT*LDK)                 // 4608
#define VBUF (AKT*LDV)                 // 16896
// Q bf16 pair + K bf16 pair x2 stages + V fp16 single x2 stages
#define ATTN_SMEM ((2*QBUF + 4*KBUF + 2*VBUF) * 2)    // 141312 B

__global__ __launch_bounds__(256, 1)
void attn_mma_kernel(const bf16* __restrict__ xh, const bf16* __restrict__ xl,
                     const bf16* __restrict__ Kh, const bf16* __restrict__ Kl,
                     const f16* __restrict__ Vf,
                     f16* __restrict__ Ohg, f16* __restrict__ Olg)
{
    extern __shared__ char smraw[];
    bf16* sQh = (bf16*)smraw;
    bf16* sQl = sQh + QBUF;
    bf16* sKh = sQl + QBUF;       // [2][KBUF]
    bf16* sKl = sKh + 2*KBUF;
    f16*  sV  = (f16*)(sKl + 2*KBUF);   // [2][VBUF]

    const int qtile = gridDim.x - 1 - blockIdx.x;   // long CTAs first
    const int bh = blockIdx.y;
    const int b = bh >> 4, h = bh & 15;
    const int q0 = qtile * AQT;
    const int t = threadIdx.x, warp = t >> 5, lane = t & 31;
    const int g = lane >> 2, tq = lane & 3;
    const int wrow = warp * 16;

    // ---- Q tile load (once) ----
    const size_t qbase = (size_t)(b*SQ + q0) * DMODEL + (size_t)h * DKH;
    #pragma unroll
    for (int i = 0; i < 8; ++i) {
        int chunk = t + i*256;              // 0..2047
        int r = chunk >> 4;
        int rem = chunk & 15;
        const bf16* src = (rem & 8) ? xl : xh;
        bf16* dst = (rem & 8) ? sQl : sQh;
        int c = (rem & 7) * 8;
        cp16(dst + r*LDQ + c, src + qbase + (size_t)r*DMODEL + c);
    }

    const size_t kbase = (size_t)(b*SQ) * DMODEL + (size_t)h * DKH;
    const size_t vbase = (size_t)(b*SQ) * DHID  + (size_t)h * DVH;

    auto load_kv = [&](int st, int kb) {
        bf16* dKh = sKh + st*KBUF;  bf16* dKl = sKl + st*KBUF;
        f16*  dV  = sV  + st*VBUF;
        #pragma unroll
        for (int i = 0; i < 4; ++i) {
            int chunk = t + i*256;          // 0..1023
            int r = chunk >> 4;
            int rem = chunk & 15;
            int c = (rem & 7) * 8;
            const bf16* src = (rem & 8) ? Kl : Kh;
            bf16* dst = (rem & 8) ? dKl : dKh;
            cp16(dst + r*LDK + c, src + kbase + (size_t)(kb + r)*DMODEL + c);
        }
        #pragma unroll
        for (int i = 0; i < 8; ++i) {
            int chunk = t + i*256;          // 0..2047
            int r = chunk >> 5;             // 0..63
            int c = (chunk & 31) * 8;
            cp16(dV + r*LDV + c, Vf + vbase + (size_t)(kb + r)*DHID + c);
        }
    };

    float acc[32][4];
    #pragma unroll
    for (int i = 0; i < 32; ++i) { acc[i][0]=0.f; acc[i][1]=0.f; acc[i][2]=0.f; acc[i][3]=0.f; }
    float m0 = -INFINITY, m1 = -INFINITY, l0 = 0.f, l1 = 0.f;

    const int ntiles = 2*qtile + 2;
    load_kv(0, 0);
    asm volatile("cp.async.commit_group;\n");

    const int mat = lane >> 3;
    const int lmoff = ((mat & 1)*8 + (lane & 7)) * LDV + (mat >> 1)*8;

    const int qrow0 = q0 + wrow + g;
    const int qrow1 = qrow0 + 8;

    for (int j = 0; j < ntiles; ++j) {
        const int cur = j & 1;
        const int kb = j * AKT;
        if (j + 1 < ntiles) load_kv(cur ^ 1, kb + AKT);
        asm volatile("cp.async.commit_group;\n");
        asm volatile("cp.async.wait_group 1;\n");
        __syncthreads();

        const bool active = (kb <= q0 + wrow + 15);   // warp-uniform causal skip
        if (active) {
            const bf16* cKh = sKh + cur*KBUF;
            const bf16* cKl = sKl + cur*KBUF;
            const f16*  cV  = sV  + cur*VBUF;

            // ---- S = Q @ K^T (bf16 hi/lo 3-mma) ----
            float sc[8][4];
            #pragma unroll
            for (int nt = 0; nt < 8; ++nt) { sc[nt][0]=0.f; sc[nt][1]=0.f; sc[nt][2]=0.f; sc[nt][3]=0.f; }
            #pragma unroll
            for (int ks = 0; ks < 4; ++ks) {
                const bf16* pah = sQh + (wrow+g)*LDQ + ks*16 + tq*2;
                const bf16* pal = sQl + (wrow+g)*LDQ + ks*16 + tq*2;
                uint32_t qh0 = lds32(pah),     qh1 = lds32(pah + 8*LDQ);
                uint32_t qh2 = lds32(pah + 8), qh3 = lds32(pah + 8*LDQ + 8);
                uint32_t ql0 = lds32(pal),     ql1 = lds32(pal + 8*LDQ);
                uint32_t ql2 = lds32(pal + 8), ql3 = lds32(pal + 8*LDQ + 8);
                #pragma unroll
                for (int nt = 0; nt < 8; ++nt) {
                    const bf16* pbh = cKh + (nt*8+g)*LDK + ks*16 + tq*2;
                    const bf16* pbl = cKl + (nt*8+g)*LDK + ks*16 + tq*2;
                    uint32_t kh0 = lds32(pbh), kh1 = lds32(pbh + 8);
                    uint32_t kl0 = lds32(pbl), kl1 = lds32(pbl + 8);
                    mma_bf16(sc[nt], qh0,qh1,qh2,qh3, kh0, kh1);
                    mma_bf16(sc[nt], ql0,ql1,ql2,ql3, kh0, kh1);
                    mma_bf16(sc[nt], qh0,qh1,qh2,qh3, kl0, kl1);
                }
            }

            // ---- causal mask ----
            if (kb + AKT - 1 > q0 + wrow) {
                #pragma unroll
                for (int nt = 0; nt < 8; ++nt) {
                    int k0 = kb + nt*8 + tq*2;
                    if (k0     > qrow0) sc[nt][0] = -INFINITY;
                    if (k0 + 1 > qrow0) sc[nt][1] = -INFINITY;
                    if (k0     > qrow1) sc[nt][2] = -INFINITY;
                    if (k0 + 1 > qrow1) sc[nt][3] = -INFINITY;
                }
            }

            // ---- online softmax ----
            float mx0 = -INFINITY, mx1 = -INFINITY;
            #pragma unroll
            for (int nt = 0; nt < 8; ++nt) {
                mx0 = fmaxf(mx0, fmaxf(sc[nt][0], sc[nt][1]));
                mx1 = fmaxf(mx1, fmaxf(sc[nt][2], sc[nt][3]));
            }
            mx0 = fmaxf(mx0, __shfl_xor_sync(0xffffffffu, mx0, 1));
            mx0 = fmaxf(mx0, __shfl_xor_sync(0xffffffffu, mx0, 2));
            mx1 = fmaxf(mx1, __shfl_xor_sync(0xffffffffu, mx1, 1));
            mx1 = fmaxf(mx1, __shfl_xor_sync(0xffffffffu, mx1, 2));
            float mn0 = fmaxf(m0, mx0), mn1 = fmaxf(m1, mx1);
            float al0 = __expf(m0 - mn0), al1 = __expf(m1 - mn1);
            m0 = mn0; m1 = mn1;

            float ps0 = 0.f, ps1 = 0.f;
            uint32_t ph[8][2];
            #pragma unroll
            for (int nt = 0; nt < 8; ++nt) {
                float p0 = __expf(sc[nt][0] - mn0);
                float p1 = __expf(sc[nt][1] - mn0);
                float p2 = __expf(sc[nt][2] - mn1);
                float p3 = __expf(sc[nt][3] - mn1);
                ps0 += p0 + p1; ps1 += p2 + p3;
                ph[nt][0] = packh2(p0, p1);
                ph[nt][1] = packh2(p2, p3);
            }
            ps0 += __shfl_xor_sync(0xffffffffu, ps0, 1);
            ps0 += __shfl_xor_sync(0xffffffffu, ps0, 2);
            ps1 += __shfl_xor_sync(0xffffffffu, ps1, 1);
            ps1 += __shfl_xor_sync(0xffffffffu, ps1, 2);
            l0 = l0*al0 + ps0;
            l1 = l1*al1 + ps1;
            #pragma unroll
            for (int i = 0; i < 32; ++i) {
                acc[i][0] *= al0; acc[i][1] *= al0;
                acc[i][2] *= al1; acc[i][3] *= al1;
            }

            // ---- O += P @ V  (fp16 P single, fp16 V single) ----
            #pragma unroll
            for (int kk = 0; kk < 4; ++kk) {
                uint32_t a0 = ph[2*kk][0],   a1 = ph[2*kk][1];
                uint32_t a2 = ph[2*kk+1][0], a3 = ph[2*kk+1][1];
                #pragma unroll
                for (int ng = 0; ng < 16; ++ng) {
                    uint32_t v0,v1,v2,v3;
                    ldmx4t(v0,v1,v2,v3, cV + kk*16*LDV + ng*16 + lmoff);
                    mma_f16(acc[2*ng],   a0,a1,a2,a3, v0, v1);
                    mma_f16(acc[2*ng+1], a0,a1,a2,a3, v2, v3);
                }
            }
        }
        __syncthreads();
    }

    // ---- epilogue: normalize + GELU -> fp16 hi/lo split ----
    const float inv0 = 1.0f / l0, inv1 = 1.0f / l1;
    f16* oh0 = Ohg + ((size_t)b*SQ + qrow0)*DHID + (size_t)h*DVH;
    f16* ol0 = Olg + ((size_t)b*SQ + qrow0)*DHID + (size_t)h*DVH;
    f16* oh1 = Ohg + ((size_t)b*SQ + qrow1)*DHID + (size_t)h*DVH;
    f16* ol1 = Olg + ((size_t)b*SQ + qrow1)*DHID + (size_t)h*DVH;
    #pragma unroll
    for (int nt = 0; nt < 32; ++nt) {
        int c = nt*8 + tq*2;
        float v0 = gelu_exact(acc[nt][0] * inv0);
        float v1 = gelu_exact(acc[nt][1] * inv0);
        float v2 = gelu_exact(acc[nt][2] * inv1);
        float v3 = gelu_exact(acc[nt][3] * inv1);
        f16 h0 = __float2half_rn(v0), h1 = __float2half_rn(v1);
        f16 h2 = __float2half_rn(v2), h3 = __float2half_rn(v3);
        __half2 hh0 = __halves2half2(h0, h1), hh1 = __halves2half2(h2, h3);
        *(uint32_t*)(oh0 + c) = *(uint32_t*)&hh0;
        *(uint32_t*)(ol0 + c) = packh2(v0 - __half2float(h0), v1 - __half2float(h1));
        *(uint32_t*)(oh1 + c) = *(uint32_t*)&hh1;
        *(uint32_t*)(ol1 + c) = packh2(v2 - __half2float(h2), v3 - __half2float(h3));
    }
}

// ---------------------------------------------------------------------------
extern "C" void kernel_launch(void* const* d_in, const int* in_sizes, int n_in,
                              void* d_out, int out_size)
{
    const float* x  = (const float*)d_in[0];
    const float* Wk = (const float*)d_in[1];
    const float* bk = (const float*)d_in[2];
    const float* Wv = (const float*)d_in[3];
    const float* bv = (const float*)d_in[4];
    const float* Wf = (const float*)d_in[5];
    const float* bf_ = (const float*)d_in[6];
    float* out = (float*)d_out;

    bf16 *gxh, *gxl, *gKh, *gKl, *gWkh, *gWkl;
    f16  *gxfh, *gxfl, *gVf, *gOh, *gOl, *gWvf, *gWff;
    cudaGetSymbolAddress((void**)&gxh,  g_xh);
    cudaGetSymbolAddress((void**)&gxl,  g_xl);
    cudaGetSymbolAddress((void**)&gxfh, g_xfh);
    cudaGetSymbolAddress((void**)&gxfl, g_xfl);
    cudaGetSymbolAddress((void**)&gKh,  g_Kh);
    cudaGetSymbolAddress((void**)&gKl,  g_Kl);
    cudaGetSymbolAddress((void**)&gVf,  g_Vf);
    cudaGetSymbolAddress((void**)&gOh,  g_Oh);
    cudaGetSymbolAddress((void**)&gOl,  g_Ol);
    cudaGetSymbolAddress((void**)&gWkh, g_Wkh);
    cudaGetSymbolAddress((void**)&gWkl, g_Wkl);
    cudaGetSymbolAddress((void**)&gWvf, g_Wvf);
    cudaGetSymbolAddress((void**)&gWff, g_Wff);

    cudaFuncSetAttribute(attn_mma_kernel,
        cudaFuncAttributeMaxDynamicSharedMemorySize, ATTN_SMEM);
    cudaFuncSetAttribute(gemm_bf16_kernel,
        cudaFuncAttributeMaxDynamicSharedMemorySize, GEMM_SMEM_BF);
    cudaFuncSetAttribute(gemm_f16_kernel<0>,
        cudaFuncAttributeMaxDynamicSharedMemorySize, GEMM_SMEM_F);
    cudaFuncSetAttribute(gemm_f16_kernel<1>,
        cudaFuncAttributeMaxDynamicSharedMemorySize, GEMM_SMEM_F);

    // 0) conversions
    convert_x_kernel<<<(MROWS*DMODEL/4 + 255)/256, 256>>>(
        x, gxh, gxl, gxfh, gxfl, MROWS*DMODEL/4);
    transpose_hl_kernel<<<dim3(DMODEL/32, DMODEL/32), dim3(32,8)>>>(
        Wk, gWkh, gWkl, DMODEL, DMODEL);
    transpose_f16_kernel<<<dim3(DHID/32,   DMODEL/32), dim3(32,8)>>>(
        Wv, gWvf, DMODEL, DHID);
    transpose_f16_kernel<<<dim3(DMODEL/32, DHID/32),   dim3(32,8)>>>(
        Wf, gWff, DHID, DMODEL);

    // 1) K = x @ Wk + bk  -> bf16 hi/lo  (accuracy-critical path)
    gemm_bf16_kernel<<<dim3(DMODEL/GBN, MROWS/GBM), 256, GEMM_SMEM_BF>>>(
        gxh, gxl, gWkh, gWkl, bk, gKh, gKl, MROWS, DMODEL, DMODEL);

    // 2) V = x @ Wv + bv  -> fp16 single  (fp16 2-mma)
    gemm_f16_kernel<0><<<dim3(DHID/GBN, MROWS/GBM), 256, GEMM_SMEM_F>>>(
        gxfh, gxfl, gWvf, bv, nullptr, gVf, nullptr, MROWS, DHID, DMODEL);

    // 3) gelu(attn(x,K,V)) -> fp16 hi/lo
    attn_mma_kernel<<<dim3(SQ/AQT, BATCH*NHEADS), 256, ATTN_SMEM>>>(
        gxh, gxl, gKh, gKl, gVf, gOh, gOl);

    // 4) out = x + O @ Wf + bf  (fp16 2-mma)
    gemm_f16_kernel<1><<<dim3(DMODEL/GBN, MROWS/GBM), 256, GEMM_SMEM_F>>>(
        gOh, gOl, gWff, bf_, x, nullptr, out, MROWS, DMODEL, DHID);
}

// round 9
// speedup vs baseline: 7.5196x; 1.3248x over previous
#include <cuda_runtime.h>
#include <cuda_bf16.h>
#include <cuda_fp16.h>
#include <cstdint>
#include <cstddef>
#include <math.h>

// Problem constants
#define BATCH   2
#define SQ      2048
#define DMODEL  1024
#define NHEADS  16
#define DHID    4096
#define DKH     64
#define DVH     256
#define MROWS   (BATCH*SQ)   // 4096

typedef __nv_bfloat16 bf16;
typedef __half        f16;

// ---------------- scratch (device globals; no allocation allowed) ----------
__device__ bf16  g_xh [MROWS * DMODEL];   // x bf16 hi (K GEMM + attention Q)
__device__ bf16  g_xl [MROWS * DMODEL];   // x bf16 lo
__device__ f16   g_xf [MROWS * DMODEL];   // x fp16 single (V GEMM)
__device__ bf16  g_Kh [MROWS * DMODEL];   // K bf16 hi
__device__ bf16  g_Kl [MROWS * DMODEL];   // K bf16 lo
__device__ f16   g_Vf [MROWS * DHID];     // V fp16 single
__device__ f16   g_Of [MROWS * DHID];     // gelu(attn) fp16 single
__device__ bf16  g_Wkh[DMODEL * DMODEL];  // Wk^T bf16 hi
__device__ bf16  g_Wkl[DMODEL * DMODEL];  // Wk^T bf16 lo
__device__ f16   g_Wvf[DHID * DMODEL];    // Wv^T fp16 single
__device__ f16   g_Wff[DMODEL * DHID];    // Wf^T fp16 single

// ---------------- helpers ---------------------------------------------------
__device__ __forceinline__ void cp16(void* s, const void* g) {
    uint32_t sa = (uint32_t)__cvta_generic_to_shared(s);
    asm volatile("cp.async.cg.shared.global [%0], [%1], 16;\n" :: "r"(sa), "l"(g));
}
template<class T>
__device__ __forceinline__ uint32_t lds32(const T* p) {
    return *reinterpret_cast<const uint32_t*>(p);
}
__device__ __forceinline__ uint32_t packbf2(bf16 a, bf16 b) {
    __nv_bfloat162 v = __halves2bfloat162(a, b);
    return *reinterpret_cast<uint32_t*>(&v);
}
__device__ __forceinline__ uint32_t packh2(float a, float b) {
    __half2 v = __floats2half2_rn(a, b);
    return *reinterpret_cast<uint32_t*>(&v);
}
__device__ __forceinline__ void mma_bf16(float* c, uint32_t a0, uint32_t a1,
                                         uint32_t a2, uint32_t a3,
                                         uint32_t b0, uint32_t b1) {
    asm volatile(
        "mma.sync.aligned.m16n8k16.row.col.f32.bf16.bf16.f32 "
        "{%0,%1,%2,%3}, {%4,%5,%6,%7}, {%8,%9}, {%0,%1,%2,%3};\n"
        : "+f"(c[0]), "+f"(c[1]), "+f"(c[2]), "+f"(c[3])
        : "r"(a0), "r"(a1), "r"(a2), "r"(a3), "r"(b0), "r"(b1));
}
__device__ __forceinline__ void mma_f16(float* c, uint32_t a0, uint32_t a1,
                                        uint32_t a2, uint32_t a3,
                                        uint32_t b0, uint32_t b1) {
    asm volatile(
        "mma.sync.aligned.m16n8k16.row.col.f32.f16.f16.f32 "
        "{%0,%1,%2,%3}, {%4,%5,%6,%7}, {%8,%9}, {%0,%1,%2,%3};\n"
        : "+f"(c[0]), "+f"(c[1]), "+f"(c[2]), "+f"(c[3])
        : "r"(a0), "r"(a1), "r"(a2), "r"(a3), "r"(b0), "r"(b1));
}
__device__ __forceinline__ void ldmx4t(uint32_t& r0, uint32_t& r1,
                                       uint32_t& r2, uint32_t& r3, const void* p) {
    uint32_t a = (uint32_t)__cvta_generic_to_shared(p);
    asm volatile("ldmatrix.sync.aligned.m8n8.x4.trans.shared.b16 {%0,%1,%2,%3}, [%4];"
                 : "=r"(r0), "=r"(r1), "=r"(r2), "=r"(r3) : "r"(a));
}
__device__ __forceinline__ float gelu_exact(float v) {
    return 0.5f * v * (1.0f + erff(v * 0.70710678118654752f));
}

// ---------------- conversion kernels ---------------------------------------
// x -> bf16 hi/lo + fp16 single in one pass
__global__ __launch_bounds__(256)
void convert_x_kernel(const float* __restrict__ src,
                      bf16* __restrict__ bh, bf16* __restrict__ bl,
                      f16*  __restrict__ fh, int n4)
{
    int i = blockIdx.x * blockDim.x + threadIdx.x;
    if (i >= n4) return;
    float4 v = ((const float4*)src)[i];
    bf16 h0 = __float2bfloat16(v.x), h1 = __float2bfloat16(v.y);
    bf16 h2 = __float2bfloat16(v.z), h3 = __float2bfloat16(v.w);
    ((uint32_t*)bh)[i*2+0] = packbf2(h0, h1);
    ((uint32_t*)bh)[i*2+1] = packbf2(h2, h3);
    ((uint32_t*)bl)[i*2+0] = packbf2(__float2bfloat16(v.x - __bfloat162float(h0)),
                                     __float2bfloat16(v.y - __bfloat162float(h1)));
    ((uint32_t*)bl)[i*2+1] = packbf2(__float2bfloat16(v.z - __bfloat162float(h2)),
                                     __float2bfloat16(v.w - __bfloat162float(h3)));
    ((uint32_t*)fh)[i*2+0] = packh2(v.x, v.y);
    ((uint32_t*)fh)[i*2+1] = packh2(v.z, v.w);
}

// fp32 [R][C] -> transposed bf16 hi/lo [C][R]
__global__ __launch_bounds__(256)
void transpose_hl_kernel(const float* __restrict__ W, bf16* __restrict__ Th,
                         bf16* __restrict__ Tl, int R, int C)
{
    __shared__ float tile[32][33];
    const int c0 = blockIdx.x * 32, r0 = blockIdx.y * 32;
    const int tx = threadIdx.x, ty = threadIdx.y;
    #pragma unroll
    for (int j = 0; j < 4; ++j)
        tile[ty + j*8][tx] = W[(size_t)(r0 + ty + j*8) * C + c0 + tx];
    __syncthreads();
    #pragma unroll
    for (int j = 0; j < 4; ++j) {
        float v = tile[tx][ty + j*8];
        bf16 h = __float2bfloat16(v);
        size_t o = (size_t)(c0 + ty + j*8) * R + r0 + tx;
        Th[o] = h;
        Tl[o] = __float2bfloat16(v - __bfloat162float(h));
    }
}

// fp32 [R][C] -> transposed fp16 single [C][R]
__global__ __launch_bounds__(256)
void transpose_f16_kernel(const float* __restrict__ W, f16* __restrict__ T,
                          int R, int C)
{
    __shared__ float tile[32][33];
    const int c0 = blockIdx.x * 32, r0 = blockIdx.y * 32;
    const int tx = threadIdx.x, ty = threadIdx.y;
    #pragma unroll
    for (int j = 0; j < 4; ++j)
        tile[ty + j*8][tx] = W[(size_t)(r0 + ty + j*8) * C + c0 + tx];
    __syncthreads();
    #pragma unroll
    for (int j = 0; j < 4; ++j)
        T[(size_t)(c0 + ty + j*8) * R + r0 + tx] = __float2half_rn(tile[tx][ty + j*8]);
}

// ---------------- GEMM tiling constants ------------------------------------
#define GBM 128
#define GBN 128
#define GBK 32
#define LDT 40
#define TBUF (GBM * LDT)
#define GEMM_SMEM_BF (8 * TBUF * (int)sizeof(bf16))   // 81920
#define GEMM_SMEM_F1 (4 * TBUF * (int)sizeof(f16))    // 40960

// ---- bf16 3-mma split GEMM (K projection): out = bf16 hi/lo pair ----------
__global__ __launch_bounds__(256)
void gemm_bf16_kernel(const bf16* __restrict__ Ah, const bf16* __restrict__ Al,
                      const bf16* __restrict__ Bh, const bf16* __restrict__ Bl,
                      const float* __restrict__ bias,
                      bf16* __restrict__ Ch, bf16* __restrict__ Cl,
                      int M, int N, int K)
{
    extern __shared__ bf16 sm[];
    bf16* sAh = sm;
    bf16* sAl = sm + 2 * TBUF;
    bf16* sBh = sm + 4 * TBUF;
    bf16* sBl = sm + 6 * TBUF;

    const int t = threadIdx.x;
    const int warp = t >> 5, lane = t & 31;
    const int g = lane >> 2, tq = lane & 3;
    const int wm = warp >> 2, wn = warp & 3;
    const int m0 = wm * 64, n0 = wn * 32;
    const int rowBase = blockIdx.y * GBM, colBase = blockIdx.x * GBN;

    float acc[4][4][4];
    #pragma unroll
    for (int i = 0; i < 4; ++i)
        #pragma unroll
        for (int j = 0; j < 4; ++j)
            #pragma unroll
            for (int k = 0; k < 4; ++k) acc[i][j][k] = 0.f;

    auto load_tile = [&](int stage, int kt) {
        bf16* dAh = sAh + stage * TBUF;
        bf16* dAl = sAl + stage * TBUF;
        bf16* dBh = sBh + stage * TBUF;
        bf16* dBl = sBl + stage * TBUF;
        #pragma unroll
        for (int it = 0; it < 2; ++it) {
            int c  = t + it * 256;
            int r  = c >> 2, cc = (c & 3) * 8;
            size_t ga = (size_t)(rowBase + r) * K + kt + cc;
            size_t gb = (size_t)(colBase + r) * K + kt + cc;
            cp16(dAh + r * LDT + cc, Ah + ga);
            cp16(dAl + r * LDT + cc, Al + ga);
            cp16(dBh + r * LDT + cc, Bh + gb);
            cp16(dBl + r * LDT + cc, Bl + gb);
        }
    };

    const int nk = K / GBK;
    load_tile(0, 0);
    asm volatile("cp.async.commit_group;\n");

    for (int kt = 0; kt < nk; ++kt) {
        const int cur = kt & 1;
        if (kt + 1 < nk) load_tile(cur ^ 1, (kt + 1) * GBK);
        asm volatile("cp.async.commit_group;\n");
        asm volatile("cp.async.wait_group 1;\n");
        __syncthreads();

        const bf16* Ahc = sAh + cur * TBUF;
        const bf16* Alc = sAl + cur * TBUF;
        const bf16* Bhc = sBh + cur * TBUF;
        const bf16* Blc = sBl + cur * TBUF;

        #pragma unroll
        for (int ks = 0; ks < 2; ++ks) {
            uint32_t bhf[4][2], blf[4][2];
            #pragma unroll
            for (int ni = 0; ni < 4; ++ni) {
                const bf16* p = Bhc + (n0 + ni*8 + g) * LDT + ks*16 + tq*2;
                bhf[ni][0] = lds32(p);  bhf[ni][1] = lds32(p + 8);
                const bf16* q2 = Blc + (n0 + ni*8 + g) * LDT + ks*16 + tq*2;
                blf[ni][0] = lds32(q2); blf[ni][1] = lds32(q2 + 8);
            }
            #pragma unroll
            for (int mi = 0; mi < 4; ++mi) {
                const bf16* pa = Ahc + (m0 + mi*16 + g) * LDT + ks*16 + tq*2;
                uint32_t ah0 = lds32(pa),     ah1 = lds32(pa + 8*LDT);
                uint32_t ah2 = lds32(pa + 8), ah3 = lds32(pa + 8*LDT + 8);
                const bf16* pl = Alc + (m0 + mi*16 + g) * LDT + ks*16 + tq*2;
                uint32_t al0 = lds32(pl),     al1 = lds32(pl + 8*LDT);
                uint32_t al2 = lds32(pl + 8), al3 = lds32(pl + 8*LDT + 8);
                #pragma unroll
                for (int ni = 0; ni < 4; ++ni) {
                    mma_bf16(acc[mi][ni], ah0, ah1, ah2, ah3, bhf[ni][0], bhf[ni][1]);
                    mma_bf16(acc[mi][ni], ah0, ah1, ah2, ah3, blf[ni][0], blf[ni][1]);
                    mma_bf16(acc[mi][ni], al0, al1, al2, al3, bhf[ni][0], bhf[ni][1]);
                }
            }
        }
        __syncthreads();
    }

    #pragma unroll
    for (int mi = 0; mi < 4; ++mi) {
        #pragma unroll
        for (int ni = 0; ni < 4; ++ni) {
            int r0 = rowBase + m0 + mi*16 + g;
            int cb = colBase + n0 + ni*8 + tq*2;
            float b0 = bias[cb], b1 = bias[cb + 1];
            float v0 = acc[mi][ni][0] + b0, v1 = acc[mi][ni][1] + b1;
            float v2 = acc[mi][ni][2] + b0, v3 = acc[mi][ni][3] + b1;
            bf16 h0 = __float2bfloat16(v0), h1 = __float2bfloat16(v1);
            bf16 h2 = __float2bfloat16(v2), h3 = __float2bfloat16(v3);
            *(uint32_t*)&Ch[(size_t)r0 * N + cb]     = packbf2(h0, h1);
            *(uint32_t*)&Cl[(size_t)r0 * N + cb]     =
                packbf2(__float2bfloat16(v0 - __bfloat162float(h0)),
                        __float2bfloat16(v1 - __bfloat162float(h1)));
            *(uint32_t*)&Ch[(size_t)(r0+8) * N + cb] = packbf2(h2, h3);
            *(uint32_t*)&Cl[(size_t)(r0+8) * N + cb] =
                packbf2(__float2bfloat16(v2 - __bfloat162float(h2)),
                        __float2bfloat16(v3 - __bfloat162float(h3)));
        }
    }
}

// ---- fp16 single-mma GEMM: C = A @ B^T + bias, both operands single fp16 --
//  OUT==0: emit fp16 single.  OUT==1: emit fp32 with residual.
template<int OUT>
__global__ __launch_bounds__(256)
void gemm_f16_kernel(const f16* __restrict__ A, const f16* __restrict__ B,
                     const float* __restrict__ bias, const float* __restrict__ res,
                     f16* __restrict__ Cf, float* __restrict__ C32,
                     int M, int N, int K)
{
    extern __shared__ f16 smh[];
    f16* sA = smh;                 // [2][TBUF]
    f16* sB = smh + 2 * TBUF;      // [2][TBUF]

    const int t = threadIdx.x;
    const int warp = t >> 5, lane = t & 31;
    const int g = lane >> 2, tq = lane & 3;
    const int wm = warp >> 2, wn = warp & 3;
    const int m0 = wm * 64, n0 = wn * 32;
    const int rowBase = blockIdx.y * GBM, colBase = blockIdx.x * GBN;

    float acc[4][4][4];
    #pragma unroll
    for (int i = 0; i < 4; ++i)
        #pragma unroll
        for (int j = 0; j < 4; ++j)
            #pragma unroll
            for (int k = 0; k < 4; ++k) acc[i][j][k] = 0.f;

    auto load_tile = [&](int stage, int kt) {
        f16* dA = sA + stage * TBUF;
        f16* dB = sB + stage * TBUF;
        #pragma unroll
        for (int it = 0; it < 2; ++it) {
            int c  = t + it * 256;
            int r  = c >> 2, cc = (c & 3) * 8;
            cp16(dA + r * LDT + cc, A + (size_t)(rowBase + r) * K + kt + cc);
            cp16(dB + r * LDT + cc, B + (size_t)(colBase + r) * K + kt + cc);
        }
    };

    const int nk = K / GBK;
    load_tile(0, 0);
    asm volatile("cp.async.commit_group;\n");

    for (int kt = 0; kt < nk; ++kt) {
        const int cur = kt & 1;
        if (kt + 1 < nk) load_tile(cur ^ 1, (kt + 1) * GBK);
        asm volatile("cp.async.commit_group;\n");
        asm volatile("cp.async.wait_group 1;\n");
        __syncthreads();

        const f16* Ac = sA + cur * TBUF;
        const f16* Bc = sB + cur * TBUF;

        #pragma unroll
        for (int ks = 0; ks < 2; ++ks) {
            uint32_t bf[4][2];
            #pragma unroll
            for (int ni = 0; ni < 4; ++ni) {
                const f16* p = Bc + (n0 + ni*8 + g) * LDT + ks*16 + tq*2;
                bf[ni][0] = lds32(p);  bf[ni][1] = lds32(p + 8);
            }
            #pragma unroll
            for (int mi = 0; mi < 4; ++mi) {
                const f16* pa = Ac + (m0 + mi*16 + g) * LDT + ks*16 + tq*2;
                uint32_t a0 = lds32(pa),     a1 = lds32(pa + 8*LDT);
                uint32_t a2 = lds32(pa + 8), a3 = lds32(pa + 8*LDT + 8);
                #pragma unroll
                for (int ni = 0; ni < 4; ++ni)
                    mma_f16(acc[mi][ni], a0, a1, a2, a3, bf[ni][0], bf[ni][1]);
            }
        }
        __syncthreads();
    }

    #pragma unroll
    for (int mi = 0; mi < 4; ++mi) {
        #pragma unroll
        for (int ni = 0; ni < 4; ++ni) {
            int r0 = rowBase + m0 + mi*16 + g;
            int cb = colBase + n0 + ni*8 + tq*2;
            float b0 = bias[cb], b1 = bias[cb + 1];
            float v0 = acc[mi][ni][0] + b0, v1 = acc[mi][ni][1] + b1;
            float v2 = acc[mi][ni][2] + b0, v3 = acc[mi][ni][3] + b1;
            if (OUT == 0) {
                *(uint32_t*)&Cf[(size_t)r0 * N + cb]     = packh2(v0, v1);
                *(uint32_t*)&Cf[(size_t)(r0+8) * N + cb] = packh2(v2, v3);
            } else {
                float2 r0v = *(const float2*)&res[(size_t)r0 * N + cb];
                float2 r1v = *(const float2*)&res[(size_t)(r0+8) * N + cb];
                float2 o0 = { v0 + r0v.x, v1 + r0v.y };
                float2 o1 = { v2 + r1v.x, v3 + r1v.y };
                *(float2*)&C32[(size_t)r0 * N + cb]     = o0;
                *(float2*)&C32[(size_t)(r0+8) * N + cb] = o1;
            }
        }
    }
}

// ---------------- tensor-core causal flash attention + GELU ----------------
#define AQT 128
#define AKT 64
#define LDQ 72
#define LDK 72
#define LDV 264
#define QBUF (AQT*LDQ)                 // 9216
#define KBUF (AKT*LDK)                 // 4608
#define VBUF (AKT*LDV)                 // 16896
#define ATTN_SMEM ((2*QBUF + 4*KBUF + 2*VBUF) * 2)    // 141312 B

__global__ __launch_bounds__(256, 1)
void attn_mma_kernel(const bf16* __restrict__ xh, const bf16* __restrict__ xl,
                     const bf16* __restrict__ Kh, const bf16* __restrict__ Kl,
                     const f16* __restrict__ Vf, f16* __restrict__ Og)
{
    extern __shared__ char smraw[];
    bf16* sQh = (bf16*)smraw;
    bf16* sQl = sQh + QBUF;
    bf16* sKh = sQl + QBUF;       // [2][KBUF]
    bf16* sKl = sKh + 2*KBUF;
    f16*  sV  = (f16*)(sKl + 2*KBUF);   // [2][VBUF]

    const int qtile = gridDim.x - 1 - blockIdx.x;   // long CTAs first
    const int bh = blockIdx.y;
    const int b = bh >> 4, h = bh & 15;
    const int q0 = qtile * AQT;
    const int t = threadIdx.x, warp = t >> 5, lane = t & 31;
    const int g = lane >> 2, tq = lane & 3;
    const int wrow = warp * 16;

    // ---- Q tile load (once) ----
    const size_t qbase = (size_t)(b*SQ + q0) * DMODEL + (size_t)h * DKH;
    #pragma unroll
    for (int i = 0; i < 8; ++i) {
        int chunk = t + i*256;              // 0..2047
        int r = chunk >> 4;
        int rem = chunk & 15;
        const bf16* src = (rem & 8) ? xl : xh;
        bf16* dst = (rem & 8) ? sQl : sQh;
        int c = (rem & 7) * 8;
        cp16(dst + r*LDQ + c, src + qbase + (size_t)r*DMODEL + c);
    }

    const size_t kbase = (size_t)(b*SQ) * DMODEL + (size_t)h * DKH;
    const size_t vbase = (size_t)(b*SQ) * DHID  + (size_t)h * DVH;

    auto load_kv = [&](int st, int kb) {
        bf16* dKh = sKh + st*KBUF;  bf16* dKl = sKl + st*KBUF;
        f16*  dV  = sV  + st*VBUF;
        #pragma unroll
        for (int i = 0; i < 4; ++i) {
            int chunk = t + i*256;          // 0..1023
            int r = chunk >> 4;
            int rem = chunk & 15;
            int c = (rem & 7) * 8;
            const bf16* src = (rem & 8) ? Kl : Kh;
            bf16* dst = (rem & 8) ? dKl : dKh;
            cp16(dst + r*LDK + c, src + kbase + (size_t)(kb + r)*DMODEL + c);
        }
        #pragma unroll
        for (int i = 0; i < 8; ++i) {
            int chunk = t + i*256;          // 0..2047
            int r = chunk >> 5;             // 0..63
            int c = (chunk & 31) * 8;
            cp16(dV + r*LDV + c, Vf + vbase + (size_t)(kb + r)*DHID + c);
        }
    };

    float acc[32][4];
    #pragma unroll
    for (int i = 0; i < 32; ++i) { acc[i][0]=0.f; acc[i][1]=0.f; acc[i][2]=0.f; acc[i][3]=0.f; }
    float m0 = -INFINITY, m1 = -INFINITY, l0 = 0.f, l1 = 0.f;

    const int ntiles = 2*qtile + 2;
    load_kv(0, 0);
    asm volatile("cp.async.commit_group;\n");

    const int mat = lane >> 3;
    const int lmoff = ((mat & 1)*8 + (lane & 7)) * LDV + (mat >> 1)*8;

    const int qrow0 = q0 + wrow + g;
    const int qrow1 = qrow0 + 8;

    for (int j = 0; j < ntiles; ++j) {
        const int cur = j & 1;
        const int kb = j * AKT;
        if (j + 1 < ntiles) load_kv(cur ^ 1, kb + AKT);
        asm volatile("cp.async.commit_group;\n");
        asm volatile("cp.async.wait_group 1;\n");
        __syncthreads();

        const bool active = (kb <= q0 + wrow + 15);   // warp-uniform causal skip
        if (active) {
            const bf16* cKh = sKh + cur*KBUF;
            const bf16* cKl = sKl + cur*KBUF;
            const f16*  cV  = sV  + cur*VBUF;

            // ---- S = Q @ K^T (bf16 hi/lo 3-mma) ----
            float sc[8][4];
            #pragma unroll
            for (int nt = 0; nt < 8; ++nt) { sc[nt][0]=0.f; sc[nt][1]=0.f; sc[nt][2]=0.f; sc[nt][3]=0.f; }
            #pragma unroll
            for (int ks = 0; ks < 4; ++ks) {
                const bf16* pah = sQh + (wrow+g)*LDQ + ks*16 + tq*2;
                const bf16* pal = sQl + (wrow+g)*LDQ + ks*16 + tq*2;
                uint32_t qh0 = lds32(pah),     qh1 = lds32(pah + 8*LDQ);
                uint32_t qh2 = lds32(pah + 8), qh3 = lds32(pah + 8*LDQ + 8);
                uint32_t ql0 = lds32(pal),     ql1 = lds32(pal + 8*LDQ);
                uint32_t ql2 = lds32(pal + 8), ql3 = lds32(pal + 8*LDQ + 8);
                #pragma unroll
                for (int nt = 0; nt < 8; ++nt) {
                    const bf16* pbh = cKh + (nt*8+g)*LDK + ks*16 + tq*2;
                    const bf16* pbl = cKl + (nt*8+g)*LDK + ks*16 + tq*2;
                    uint32_t kh0 = lds32(pbh), kh1 = lds32(pbh + 8);
                    uint32_t kl0 = lds32(pbl), kl1 = lds32(pbl + 8);
                    mma_bf16(sc[nt], qh0,qh1,qh2,qh3, kh0, kh1);
                    mma_bf16(sc[nt], ql0,ql1,ql2,ql3, kh0, kh1);
                    mma_bf16(sc[nt], qh0,qh1,qh2,qh3, kl0, kl1);
                }
            }

            // ---- causal mask ----
            if (kb + AKT - 1 > q0 + wrow) {
                #pragma unroll
                for (int nt = 0; nt < 8; ++nt) {
                    int k0 = kb + nt*8 + tq*2;
                    if (k0     > qrow0) sc[nt][0] = -INFINITY;
                    if (k0 + 1 > qrow0) sc[nt][1] = -INFINITY;
                    if (k0     > qrow1) sc[nt][2] = -INFINITY;
                    if (k0 + 1 > qrow1) sc[nt][3] = -INFINITY;
                }
            }

            // ---- online softmax ----
            float mx0 = -INFINITY, mx1 = -INFINITY;
            #pragma unroll
            for (int nt = 0; nt < 8; ++nt) {
                mx0 = fmaxf(mx0, fmaxf(sc[nt][0], sc[nt][1]));
                mx1 = fmaxf(mx1, fmaxf(sc[nt][2], sc[nt][3]));
            }
            mx0 = fmaxf(mx0, __shfl_xor_sync(0xffffffffu, mx0, 1));
            mx0 = fmaxf(mx0, __shfl_xor_sync(0xffffffffu, mx0, 2));
            mx1 = fmaxf(mx1, __shfl_xor_sync(0xffffffffu, mx1, 1));
            mx1 = fmaxf(mx1, __shfl_xor_sync(0xffffffffu, mx1, 2));
            float mn0 = fmaxf(m0, mx0), mn1 = fmaxf(m1, mx1);
            float al0 = __expf(m0 - mn0), al1 = __expf(m1 - mn1);
            m0 = mn0; m1 = mn1;

            float ps0 = 0.f, ps1 = 0.f;
            uint32_t ph[8][2];
            #pragma unroll
            for (int nt = 0; nt < 8; ++nt) {
                float p0 = __expf(sc[nt][0] - mn0);
                float p1 = __expf(sc[nt][1] - mn0);
                float p2 = __expf(sc[nt][2] - mn1);
                float p3 = __expf(sc[nt][3] - mn1);
                ps0 += p0 + p1; ps1 += p2 + p3;
                ph[nt][0] = packh2(p0, p1);
                ph[nt][1] = packh2(p2, p3);
            }
            ps0 += __shfl_xor_sync(0xffffffffu, ps0, 1);
            ps0 += __shfl_xor_sync(0xffffffffu, ps0, 2);
            ps1 += __shfl_xor_sync(0xffffffffu, ps1, 1);
            ps1 += __shfl_xor_sync(0xffffffffu, ps1, 2);
            l0 = l0*al0 + ps0;
            l1 = l1*al1 + ps1;
            #pragma unroll
            for (int i = 0; i < 32; ++i) {
                acc[i][0] *= al0; acc[i][1] *= al0;
                acc[i][2] *= al1; acc[i][3] *= al1;
            }

            // ---- O += P @ V  (fp16 single) ----
            #pragma unroll
            for (int kk = 0; kk < 4; ++kk) {
                uint32_t a0 = ph[2*kk][0],   a1 = ph[2*kk][1];
                uint32_t a2 = ph[2*kk+1][0], a3 = ph[2*kk+1][1];
                #pragma unroll
                for (int ng = 0; ng < 16; ++ng) {
                    uint32_t v0,v1,v2,v3;
                    ldmx4t(v0,v1,v2,v3, cV + kk*16*LDV + ng*16 + lmoff);
                    mma_f16(acc[2*ng],   a0,a1,a2,a3, v0, v1);
                    mma_f16(acc[2*ng+1], a0,a1,a2,a3, v2, v3);
                }
            }
        }
        __syncthreads();
    }

    // ---- epilogue: normalize + GELU -> fp16 single ----
    const float inv0 = 1.0f / l0, inv1 = 1.0f / l1;
    f16* o0p = Og + ((size_t)b*SQ + qrow0)*DHID + (size_t)h*DVH;
    f16* o1p = Og + ((size_t)b*SQ + qrow1)*DHID + (size_t)h*DVH;
    #pragma unroll
    for (int nt = 0; nt < 32; ++nt) {
        int c = nt*8 + tq*2;
        float v0 = gelu_exact(acc[nt][0] * inv0);
        float v1 = gelu_exact(acc[nt][1] * inv0);
        float v2 = gelu_exact(acc[nt][2] * inv1);
        float v3 = gelu_exact(acc[nt][3] * inv1);
        *(uint32_t*)(o0p + c) = packh2(v0, v1);
        *(uint32_t*)(o1p + c) = packh2(v2, v3);
    }
}

// ---------------------------------------------------------------------------
extern "C" void kernel_launch(void* const* d_in, const int* in_sizes, int n_in,
                              void* d_out, int out_size)
{
    const float* x  = (const float*)d_in[0];
    const float* Wk = (const float*)d_in[1];
    const float* bk = (const float*)d_in[2];
    const float* Wv = (const float*)d_in[3];
    const float* bv = (const float*)d_in[4];
    const float* Wf = (const float*)d_in[5];
    const float* bf_ = (const float*)d_in[6];
    float* out = (float*)d_out;

    bf16 *gxh, *gxl, *gKh, *gKl, *gWkh, *gWkl;
    f16  *gxf, *gVf, *gOf, *gWvf, *gWff;
    cudaGetSymbolAddress((void**)&gxh,  g_xh);
    cudaGetSymbolAddress((void**)&gxl,  g_xl);
    cudaGetSymbolAddress((void**)&gxf,  g_xf);
    cudaGetSymbolAddress((void**)&gKh,  g_Kh);
    cudaGetSymbolAddress((void**)&gKl,  g_Kl);
    cudaGetSymbolAddress((void**)&gVf,  g_Vf);
    cudaGetSymbolAddress((void**)&gOf,  g_Of);
    cudaGetSymbolAddress((void**)&gWkh, g_Wkh);
    cudaGetSymbolAddress((void**)&gWkl, g_Wkl);
    cudaGetSymbolAddress((void**)&gWvf, g_Wvf);
    cudaGetSymbolAddress((void**)&gWff, g_Wff);

    cudaFuncSetAttribute(attn_mma_kernel,
        cudaFuncAttributeMaxDynamicSharedMemorySize, ATTN_SMEM);
    cudaFuncSetAttribute(gemm_bf16_kernel,
        cudaFuncAttributeMaxDynamicSharedMemorySize, GEMM_SMEM_BF);
    cudaFuncSetAttribute(gemm_f16_kernel<0>,
        cudaFuncAttributeMaxDynamicSharedMemorySize, GEMM_SMEM_F1);
    cudaFuncSetAttribute(gemm_f16_kernel<1>,
        cudaFuncAttributeMaxDynamicSharedMemorySize, GEMM_SMEM_F1);

    // 0) conversions
    convert_x_kernel<<<(MROWS*DMODEL/4 + 255)/256, 256>>>(
        x, gxh, gxl, gxf, MROWS*DMODEL/4);
    transpose_hl_kernel<<<dim3(DMODEL/32, DMODEL/32), dim3(32,8)>>>(
        Wk, gWkh, gWkl, DMODEL, DMODEL);
    transpose_f16_kernel<<<dim3(DHID/32,   DMODEL/32), dim3(32,8)>>>(
        Wv, gWvf, DMODEL, DHID);
    transpose_f16_kernel<<<dim3(DMODEL/32, DHID/32),   dim3(32,8)>>>(
        Wf, gWff, DHID, DMODEL);

    // 1) K = x @ Wk + bk  -> bf16 hi/lo  (accuracy-critical path)
    gemm_bf16_kernel<<<dim3(DMODEL/GBN, MROWS/GBM), 256, GEMM_SMEM_BF>>>(
        gxh, gxl, gWkh, gWkl, bk, gKh, gKl, MROWS, DMODEL, DMODEL);

    // 2) V = x @ Wv + bv  -> fp16 single  (fp16 1-mma)
    gemm_f16_kernel<0><<<dim3(DHID/GBN, MROWS/GBM), 256, GEMM_SMEM_F1>>>(
        gxf, gWvf, bv, nullptr, gVf, nullptr, MROWS, DHID, DMODEL);

    // 3) gelu(attn(x,K,V)) -> fp16 single
    attn_mma_kernel<<<dim3(SQ/AQT, BATCH*NHEADS), 256, ATTN_SMEM>>>(
        gxh, gxl, gKh, gKl, gVf, gOf);

    // 4) out = x + O @ Wf + bf  (fp16 1-mma)
    gemm_f16_kernel<1><<<dim3(DMODEL/GBN, MROWS/GBM), 256, GEMM_SMEM_F1>>>(
        gOf, gWff, bf_, x, nullptr, out, MROWS, DMODEL, DHID);
}

// round 11
// speedup vs baseline: 7.8985x; 1.0504x over previous
#include <cuda_runtime.h>
#include <cuda_bf16.h>
#include <cuda_fp16.h>
#include <cstdint>
#include <cstddef>
#include <math.h>

// Problem constants
#define BATCH   2
#define SQ      2048
#define DMODEL  1024
#define NHEADS  16
#define DHID    4096
#define DKH     64
#define DVH     256
#define MROWS   (BATCH*SQ)   // 4096

typedef __half f16;

// ---------------- scratch (device globals; no allocation allowed) ----------
__device__ f16  g_xfh[MROWS * DMODEL];   // x fp16 hi (Q, K GEMM A, V GEMM A)
__device__ f16  g_xfl[MROWS * DMODEL];   // x fp16 lo
__device__ f16  g_Kfh[MROWS * DMODEL];   // K fp16 hi
__device__ f16  g_Kfl[MROWS * DMODEL];   // K fp16 lo
__device__ f16  g_Vf [MROWS * DHID];     // V fp16 single
__device__ f16  g_Of [MROWS * DHID];     // gelu(attn) fp16 single
__device__ f16  g_Wkf[DMODEL * DMODEL];  // Wk^T fp16 single
__device__ f16  g_Wvf[DHID * DMODEL];    // Wv^T fp16 single
__device__ f16  g_Wff[DMODEL * DHID];    // Wf^T fp16 single

// ---------------- helpers ---------------------------------------------------
__device__ __forceinline__ void cp16(void* s, const void* g) {
    uint32_t sa = (uint32_t)__cvta_generic_to_shared(s);
    asm volatile("cp.async.cg.shared.global [%0], [%1], 16;\n" :: "r"(sa), "l"(g));
}
template<class T>
__device__ __forceinline__ uint32_t lds32(const T* p) {
    return *reinterpret_cast<const uint32_t*>(p);
}
__device__ __forceinline__ uint32_t packh2(float a, float b) {
    __half2 v = __floats2half2_rn(a, b);
    return *reinterpret_cast<uint32_t*>(&v);
}
__device__ __forceinline__ void mma_f16(float* c, uint32_t a0, uint32_t a1,
                                        uint32_t a2, uint32_t a3,
                                        uint32_t b0, uint32_t b1) {
    asm volatile(
        "mma.sync.aligned.m16n8k16.row.col.f32.f16.f16.f32 "
        "{%0,%1,%2,%3}, {%4,%5,%6,%7}, {%8,%9}, {%0,%1,%2,%3};\n"
        : "+f"(c[0]), "+f"(c[1]), "+f"(c[2]), "+f"(c[3])
        : "r"(a0), "r"(a1), "r"(a2), "r"(a3), "r"(b0), "r"(b1));
}
__device__ __forceinline__ void ldmx4t(uint32_t& r0, uint32_t& r1,
                                       uint32_t& r2, uint32_t& r3, const void* p) {
    uint32_t a = (uint32_t)__cvta_generic_to_shared(p);
    asm volatile("ldmatrix.sync.aligned.m8n8.x4.trans.shared.b16 {%0,%1,%2,%3}, [%4];"
                 : "=r"(r0), "=r"(r1), "=r"(r2), "=r"(r3) : "r"(a));
}
__device__ __forceinline__ float gelu_exact(float v) {
    return 0.5f * v * (1.0f + erff(v * 0.70710678118654752f));
}

// ---------------- conversion kernels ---------------------------------------
// x -> fp16 hi/lo pair
__global__ __launch_bounds__(256)
void convert_x_kernel(const float* __restrict__ src,
                      f16* __restrict__ fh, f16* __restrict__ fl, int n4)
{
    int i = blockIdx.x * blockDim.x + threadIdx.x;
    if (i >= n4) return;
    float4 v = ((const float4*)src)[i];
    f16 p0 = __float2half_rn(v.x), p1 = __float2half_rn(v.y);
    f16 p2 = __float2half_rn(v.z), p3 = __float2half_rn(v.w);
    __half2 h0 = __halves2half2(p0, p1), h1 = __halves2half2(p2, p3);
    ((uint32_t*)fh)[i*2+0] = *(uint32_t*)&h0;
    ((uint32_t*)fh)[i*2+1] = *(uint32_t*)&h1;
    ((uint32_t*)fl)[i*2+0] = packh2(v.x - __half2float(p0), v.y - __half2float(p1));
    ((uint32_t*)fl)[i*2+1] = packh2(v.z - __half2float(p2), v.w - __half2float(p3));
}

// fp32 [R][C] -> transposed fp16 single [C][R]
__global__ __launch_bounds__(256)
void transpose_f16_kernel(const float* __restrict__ W, f16* __restrict__ T,
                          int R, int C)
{
    __shared__ float tile[32][33];
    const int c0 = blockIdx.x * 32, r0 = blockIdx.y * 32;
    const int tx = threadIdx.x, ty = threadIdx.y;
    #pragma unroll
    for (int j = 0; j < 4; ++j)
        tile[ty + j*8][tx] = W[(size_t)(r0 + ty + j*8) * C + c0 + tx];
    __syncthreads();
    #pragma unroll
    for (int j = 0; j < 4; ++j)
        T[(size_t)(c0 + ty + j*8) * R + r0 + tx] = __float2half_rn(tile[tx][ty + j*8]);
}

// ---------------- GEMM tiling constants ------------------------------------
#define GBM 128
#define GBN 128
#define GBK 32
#define LDT 40
#define TBUF (GBM * LDT)
#define GEMM_SMEM_P  (6 * TBUF * (int)sizeof(f16))    // 61440 (A pair + B single)
#define GEMM_SMEM_F1 (4 * TBUF * (int)sizeof(f16))    // 40960 (A single + B single)

// ---- fp16 2-mma GEMM (K projection): A fp16 pair, B single, out fp16 pair -
__global__ __launch_bounds__(256)
void gemm_f16pair_kernel(const f16* __restrict__ Ah, const f16* __restrict__ Al,
                         const f16* __restrict__ B, const float* __restrict__ bias,
                         f16* __restrict__ Ch, f16* __restrict__ Cl,
                         int M, int N, int K)
{
    extern __shared__ f16 smp[];
    f16* sAh = smp;                 // [2][TBUF]
    f16* sAl = smp + 2 * TBUF;
    f16* sB  = smp + 4 * TBUF;

    const int t = threadIdx.x;
    const int warp = t >> 5, lane = t & 31;
    const int g = lane >> 2, tq = lane & 3;
    const int wm = warp >> 2, wn = warp & 3;
    const int m0 = wm * 64, n0 = wn * 32;
    const int rowBase = blockIdx.y * GBM, colBase = blockIdx.x * GBN;

    float acc[4][4][4];
    #pragma unroll
    for (int i = 0; i < 4; ++i)
        #pragma unroll
        for (int j = 0; j < 4; ++j)
            #pragma unroll
            for (int k = 0; k < 4; ++k) acc[i][j][k] = 0.f;

    auto load_tile = [&](int stage, int kt) {
        f16* dAh = sAh + stage * TBUF;
        f16* dAl = sAl + stage * TBUF;
        f16* dB  = sB  + stage * TBUF;
        #pragma unroll
        for (int it = 0; it < 2; ++it) {
            int c  = t + it * 256;
            int r  = c >> 2, cc = (c & 3) * 8;
            size_t ga = (size_t)(rowBase + r) * K + kt + cc;
            size_t gb = (size_t)(colBase + r) * K + kt + cc;
            cp16(dAh + r * LDT + cc, Ah + ga);
            cp16(dAl + r * LDT + cc, Al + ga);
            cp16(dB  + r * LDT + cc, B  + gb);
        }
    };

    const int nk = K / GBK;
    load_tile(0, 0);
    asm volatile("cp.async.commit_group;\n");

    for (int kt = 0; kt < nk; ++kt) {
        const int cur = kt & 1;
        if (kt + 1 < nk) load_tile(cur ^ 1, (kt + 1) * GBK);
        asm volatile("cp.async.commit_group;\n");
        asm volatile("cp.async.wait_group 1;\n");
        __syncthreads();

        const f16* Ahc = sAh + cur * TBUF;
        const f16* Alc = sAl + cur * TBUF;
        const f16* Bc  = sB  + cur * TBUF;

        #pragma unroll
        for (int ks = 0; ks < 2; ++ks) {
            uint32_t bf[4][2];
            #pragma unroll
            for (int ni = 0; ni < 4; ++ni) {
                const f16* p = Bc + (n0 + ni*8 + g) * LDT + ks*16 + tq*2;
                bf[ni][0] = lds32(p);  bf[ni][1] = lds32(p + 8);
            }
            #pragma unroll
            for (int mi = 0; mi < 4; ++mi) {
                const f16* pa = Ahc + (m0 + mi*16 + g) * LDT + ks*16 + tq*2;
                uint32_t ah0 = lds32(pa),     ah1 = lds32(pa + 8*LDT);
                uint32_t ah2 = lds32(pa + 8), ah3 = lds32(pa + 8*LDT + 8);
                const f16* pl = Alc + (m0 + mi*16 + g) * LDT + ks*16 + tq*2;
                uint32_t al0 = lds32(pl),     al1 = lds32(pl + 8*LDT);
                uint32_t al2 = lds32(pl + 8), al3 = lds32(pl + 8*LDT + 8);
                #pragma unroll
                for (int ni = 0; ni < 4; ++ni) {
                    mma_f16(acc[mi][ni], ah0, ah1, ah2, ah3, bf[ni][0], bf[ni][1]);
                    mma_f16(acc[mi][ni], al0, al1, al2, al3, bf[ni][0], bf[ni][1]);
                }
            }
        }
        __syncthreads();
    }

    #pragma unroll
    for (int mi = 0; mi < 4; ++mi) {
        #pragma unroll
        for (int ni = 0; ni < 4; ++ni) {
            int r0 = rowBase + m0 + mi*16 + g;
            int cb = colBase + n0 + ni*8 + tq*2;
            float b0 = bias[cb], b1 = bias[cb + 1];
            float v0 = acc[mi][ni][0] + b0, v1 = acc[mi][ni][1] + b1;
            float v2 = acc[mi][ni][2] + b0, v3 = acc[mi][ni][3] + b1;
            f16 h0 = __float2half_rn(v0), h1 = __float2half_rn(v1);
            f16 h2 = __float2half_rn(v2), h3 = __float2half_rn(v3);
            __half2 hh0 = __halves2half2(h0, h1), hh1 = __halves2half2(h2, h3);
            *(uint32_t*)&Ch[(size_t)r0 * N + cb]     = *(uint32_t*)&hh0;
            *(uint32_t*)&Cl[(size_t)r0 * N + cb]     =
                packh2(v0 - __half2float(h0), v1 - __half2float(h1));
            *(uint32_t*)&Ch[(size_t)(r0+8) * N + cb] = *(uint32_t*)&hh1;
            *(uint32_t*)&Cl[(size_t)(r0+8) * N + cb] =
                packh2(v2 - __half2float(h2), v3 - __half2float(h3));
        }
    }
}

// ---- fp16 1-mma GEMM: C = A @ B^T + bias, both single fp16 ----------------
//  OUT==0: emit fp16 single.  OUT==1: emit fp32 with residual.
template<int OUT>
__global__ __launch_bounds__(256)
void gemm_f16_kernel(const f16* __restrict__ A, const f16* __restrict__ B,
                     const float* __restrict__ bias, const float* __restrict__ res,
                     f16* __restrict__ Cf, float* __restrict__ C32,
                     int M, int N, int K)
{
    extern __shared__ f16 smh[];
    f16* sA = smh;                 // [2][TBUF]
    f16* sB = smh + 2 * TBUF;      // [2][TBUF]

    const int t = threadIdx.x;
    const int warp = t >> 5, lane = t & 31;
    const int g = lane >> 2, tq = lane & 3;
    const int wm = warp >> 2, wn = warp & 3;
    const int m0 = wm * 64, n0 = wn * 32;
    const int rowBase = blockIdx.y * GBM, colBase = blockIdx.x * GBN;

    float acc[4][4][4];
    #pragma unroll
    for (int i = 0; i < 4; ++i)
        #pragma unroll
        for (int j = 0; j < 4; ++j)
            #pragma unroll
            for (int k = 0; k < 4; ++k) acc[i][j][k] = 0.f;

    auto load_tile = [&](int stage, int kt) {
        f16* dA = sA + stage * TBUF;
        f16* dB = sB + stage * TBUF;
        #pragma unroll
        for (int it = 0; it < 2; ++it) {
            int c  = t + it * 256;
            int r  = c >> 2, cc = (c & 3) * 8;
            cp16(dA + r * LDT + cc, A + (size_t)(rowBase + r) * K + kt + cc);
            cp16(dB + r * LDT + cc, B + (size_t)(colBase + r) * K + kt + cc);
        }
    };

    const int nk = K / GBK;
    load_tile(0, 0);
    asm volatile("cp.async.commit_group;\n");

    for (int kt = 0; kt < nk; ++kt) {
        const int cur = kt & 1;
        if (kt + 1 < nk) load_tile(cur ^ 1, (kt + 1) * GBK);
        asm volatile("cp.async.commit_group;\n");
        asm volatile("cp.async.wait_group 1;\n");
        __syncthreads();

        const f16* Ac = sA + cur * TBUF;
        const f16* Bc = sB + cur * TBUF;

        #pragma unroll
        for (int ks = 0; ks < 2; ++ks) {
            uint32_t bf[4][2];
            #pragma unroll
            for (int ni = 0; ni < 4; ++ni) {
                const f16* p = Bc + (n0 + ni*8 + g) * LDT + ks*16 + tq*2;
                bf[ni][0] = lds32(p);  bf[ni][1] = lds32(p + 8);
            }
            #pragma unroll
            for (int mi = 0; mi < 4; ++mi) {
                const f16* pa = Ac + (m0 + mi*16 + g) * LDT + ks*16 + tq*2;
                uint32_t a0 = lds32(pa),     a1 = lds32(pa + 8*LDT);
                uint32_t a2 = lds32(pa + 8), a3 = lds32(pa + 8*LDT + 8);
                #pragma unroll
                for (int ni = 0; ni < 4; ++ni)
                    mma_f16(acc[mi][ni], a0, a1, a2, a3, bf[ni][0], bf[ni][1]);
            }
        }
        __syncthreads();
    }

    #pragma unroll
    for (int mi = 0; mi < 4; ++mi) {
        #pragma unroll
        for (int ni = 0; ni < 4; ++ni) {
            int r0 = rowBase + m0 + mi*16 + g;
            int cb = colBase + n0 + ni*8 + tq*2;
            float b0 = bias[cb], b1 = bias[cb + 1];
            float v0 = acc[mi][ni][0] + b0, v1 = acc[mi][ni][1] + b1;
            float v2 = acc[mi][ni][2] + b0, v3 = acc[mi][ni][3] + b1;
            if (OUT == 0) {
                *(uint32_t*)&Cf[(size_t)r0 * N + cb]     = packh2(v0, v1);
                *(uint32_t*)&Cf[(size_t)(r0+8) * N + cb] = packh2(v2, v3);
            } else {
                float2 r0v = *(const float2*)&res[(size_t)r0 * N + cb];
                float2 r1v = *(const float2*)&res[(size_t)(r0+8) * N + cb];
                float2 o0 = { v0 + r0v.x, v1 + r0v.y };
                float2 o1 = { v2 + r1v.x, v3 + r1v.y };
                *(float2*)&C32[(size_t)r0 * N + cb]     = o0;
                *(float2*)&C32[(size_t)(r0+8) * N + cb] = o1;
            }
        }
    }
}

// ---------------- tensor-core causal flash attention + GELU ----------------
#define AQT 128
#define AKT 64
#define LDQ 72
#define LDK 72
#define LDV 264
#define QBUF (AQT*LDQ)                 // 9216
#define KBUF (AKT*LDK)                 // 4608
#define VBUF (AKT*LDV)                 // 16896
#define ATTN_SMEM ((2*QBUF + 4*KBUF + 2*VBUF) * 2)    // 141312 B

__global__ __launch_bounds__(256, 1)
void attn_mma_kernel(const f16* __restrict__ xh, const f16* __restrict__ xl,
                     const f16* __restrict__ Kh, const f16* __restrict__ Kl,
                     const f16* __restrict__ Vf, f16* __restrict__ Og)
{
    extern __shared__ char smraw[];
    f16* sQh = (f16*)smraw;
    f16* sQl = sQh + QBUF;
    f16* sKh = sQl + QBUF;        // [2][KBUF]
    f16* sKl = sKh + 2*KBUF;
    f16* sV  = sKl + 2*KBUF;      // [2][VBUF]

    const int qtile = gridDim.x - 1 - blockIdx.x;   // long CTAs first
    const int bh = blockIdx.y;
    const int b = bh >> 4, h = bh & 15;
    const int q0 = qtile * AQT;
    const int t = threadIdx.x, warp = t >> 5, lane = t & 31;
    const int g = lane >> 2, tq = lane & 3;
    const int wrow = warp * 16;

    // ---- Q tile load (once) ----
    const size_t qbase = (size_t)(b*SQ + q0) * DMODEL + (size_t)h * DKH;
    #pragma unroll
    for (int i = 0; i < 8; ++i) {
        int chunk = t + i*256;              // 0..2047
        int r = chunk >> 4;
        int rem = chunk & 15;
        const f16* src = (rem & 8) ? xl : xh;
        f16* dst = (rem & 8) ? sQl : sQh;
        int c = (rem & 7) * 8;
        cp16(dst + r*LDQ + c, src + qbase + (size_t)r*DMODEL + c);
    }

    const size_t kbase = (size_t)(b*SQ) * DMODEL + (size_t)h * DKH;
    const size_t vbase = (size_t)(b*SQ) * DHID  + (size_t)h * DVH;

    auto load_kv = [&](int st, int kb) {
        f16* dKh = sKh + st*KBUF;  f16* dKl = sKl + st*KBUF;
        f16* dV  = sV  + st*VBUF;
        #pragma unroll
        for (int i = 0; i < 4; ++i) {
            int chunk = t + i*256;          // 0..1023
            int r = chunk >> 4;
            int rem = chunk & 15;
            int c = (rem & 7) * 8;
            const f16* src = (rem & 8) ? Kl : Kh;
            f16* dst = (rem & 8) ? dKl : dKh;
            cp16(dst + r*LDK + c, src + kbase + (size_t)(kb + r)*DMODEL + c);
        }
        #pragma unroll
        for (int i = 0; i < 8; ++i) {
            int chunk = t + i*256;          // 0..2047
            int r = chunk >> 5;             // 0..63
            int c = (chunk & 31) * 8;
            cp16(dV + r*LDV + c, Vf + vbase + (size_t)(kb + r)*DHID + c);
        }
    };

    float acc[32][4];
    #pragma unroll
    for (int i = 0; i < 32; ++i) { acc[i][0]=0.f; acc[i][1]=0.f; acc[i][2]=0.f; acc[i][3]=0.f; }
    float m0 = -INFINITY, m1 = -INFINITY, l0 = 0.f, l1 = 0.f;

    const int ntiles = 2*qtile + 2;
    load_kv(0, 0);
    asm volatile("cp.async.commit_group;\n");

    const int mat = lane >> 3;
    const int lmoff = ((mat & 1)*8 + (lane & 7)) * LDV + (mat >> 1)*8;

    const int qrow0 = q0 + wrow + g;
    const int qrow1 = qrow0 + 8;

    for (int j = 0; j < ntiles; ++j) {
        const int cur = j & 1;
        const int kb = j * AKT;
        if (j + 1 < ntiles) load_kv(cur ^ 1, kb + AKT);
        asm volatile("cp.async.commit_group;\n");
        asm volatile("cp.async.wait_group 1;\n");
        __syncthreads();

        const bool active = (kb <= q0 + wrow + 15);   // warp-uniform causal skip
        if (active) {
            const f16* cKh = sKh + cur*KBUF;
            const f16* cKl = sKl + cur*KBUF;
            const f16* cV  = sV  + cur*VBUF;

            // ---- S = Q @ K^T (fp16 hi/lo 3-mma) ----
            float sc[8][4];
            #pragma unroll
            for (int nt = 0; nt < 8; ++nt) { sc[nt][0]=0.f; sc[nt][1]=0.f; sc[nt][2]=0.f; sc[nt][3]=0.f; }
            #pragma unroll
            for (int ks = 0; ks < 4; ++ks) {
                const f16* pah = sQh + (wrow+g)*LDQ + ks*16 + tq*2;
                const f16* pal = sQl + (wrow+g)*LDQ + ks*16 + tq*2;
                uint32_t qh0 = lds32(pah),     qh1 = lds32(pah + 8*LDQ);
                uint32_t qh2 = lds32(pah + 8), qh3 = lds32(pah + 8*LDQ + 8);
                uint32_t ql0 = lds32(pal),     ql1 = lds32(pal + 8*LDQ);
                uint32_t ql2 = lds32(pal + 8), ql3 = lds32(pal + 8*LDQ + 8);
                #pragma unroll
                for (int nt = 0; nt < 8; ++nt) {
                    const f16* pbh = cKh + (nt*8+g)*LDK + ks*16 + tq*2;
                    const f16* pbl = cKl + (nt*8+g)*LDK + ks*16 + tq*2;
                    uint32_t kh0 = lds32(pbh), kh1 = lds32(pbh + 8);
                    uint32_t kl0 = lds32(pbl), kl1 = lds32(pbl + 8);
                    mma_f16(sc[nt], qh0,qh1,qh2,qh3, kh0, kh1);
                    mma_f16(sc[nt], ql0,ql1,ql2,ql3, kh0, kh1);
                    mma_f16(sc[nt], qh0,qh1,qh2,qh3, kl0, kl1);
                }
            }

            // ---- causal mask ----
            if (kb + AKT - 1 > q0 + wrow) {
                #pragma unroll
                for (int nt = 0; nt < 8; ++nt) {
                    int k0 = kb + nt*8 + tq*2;
                    if (k0     > qrow0) sc[nt][0] = -INFINITY;
                    if (k0 + 1 > qrow0) sc[nt][1] = -INFINITY;
                    if (k0     > qrow1) sc[nt][2] = -INFINITY;
                    if (k0 + 1 > qrow1) sc[nt][3] = -INFINITY;
                }
            }

            // ---- online softmax ----
            float mx0 = -INFINITY, mx1 = -INFINITY;
            #pragma unroll
            for (int nt = 0; nt < 8; ++nt) {
                mx0 = fmaxf(mx0, fmaxf(sc[nt][0], sc[nt][1]));
                mx1 = fmaxf(mx1, fmaxf(sc[nt][2], sc[nt][3]));
            }
            mx0 = fmaxf(mx0, __shfl_xor_sync(0xffffffffu, mx0, 1));
            mx0 = fmaxf(mx0, __shfl_xor_sync(0xffffffffu, mx0, 2));
            mx1 = fmaxf(mx1, __shfl_xor_sync(0xffffffffu, mx1, 1));
            mx1 = fmaxf(mx1, __shfl_xor_sync(0xffffffffu, mx1, 2));
            float mn0 = fmaxf(m0, mx0), mn1 = fmaxf(m1, mx1);
            float al0 = __expf(m0 - mn0), al1 = __expf(m1 - mn1);
            m0 = mn0; m1 = mn1;

            float ps0 = 0.f, ps1 = 0.f;
            uint32_t ph[8][2];
            #pragma unroll
            for (int nt = 0; nt < 8; ++nt) {
                float p0 = __expf(sc[nt][0] - mn0);
                float p1 = __expf(sc[nt][1] - mn0);
                float p2 = __expf(sc[nt][2] - mn1);
                float p3 = __expf(sc[nt][3] - mn1);
                ps0 += p0 + p1; ps1 += p2 + p3;
                ph[nt][0] = packh2(p0, p1);
                ph[nt][1] = packh2(p2, p3);
            }
            ps0 += __shfl_xor_sync(0xffffffffu, ps0, 1);
            ps0 += __shfl_xor_sync(0xffffffffu, ps0, 2);
            ps1 += __shfl_xor_sync(0xffffffffu, ps1, 1);
            ps1 += __shfl_xor_sync(0xffffffffu, ps1, 2);
            l0 = l0*al0 + ps0;
            l1 = l1*al1 + ps1;
            #pragma unroll
            for (int i = 0; i < 32; ++i) {
                acc[i][0] *= al0; acc[i][1] *= al0;
                acc[i][2] *= al1; acc[i][3] *= al1;
            }

            // ---- O += P @ V  (fp16 single) ----
            #pragma unroll
            for (int kk = 0; kk < 4; ++kk) {
                uint32_t a0 = ph[2*kk][0],   a1 = ph[2*kk][1];
                uint32_t a2 = ph[2*kk+1][0], a3 = ph[2*kk+1][1];
                #pragma unroll
                for (int ng = 0; ng < 16; ++ng) {
                    uint32_t v0,v1,v2,v3;
                    ldmx4t(v0,v1,v2,v3, cV + kk*16*LDV + ng*16 + lmoff);
                    mma_f16(acc[2*ng],   a0,a1,a2,a3, v0, v1);
                    mma_f16(acc[2*ng+1], a0,a1,a2,a3, v2, v3);
                }
            }
        }
        __syncthreads();
    }

    // ---- epilogue: normalize + GELU -> fp16 single ----
    const float inv0 = 1.0f / l0, inv1 = 1.0f / l1;
    f16* o0p = Og + ((size_t)b*SQ + qrow0)*DHID + (size_t)h*DVH;
    f16* o1p = Og + ((size_t)b*SQ + qrow1)*DHID + (size_t)h*DVH;
    #pragma unroll
    for (int nt = 0; nt < 32; ++nt) {
        int c = nt*8 + tq*2;
        float v0 = gelu_exact(acc[nt][0] * inv0);
        float v1 = gelu_exact(acc[nt][1] * inv0);
        float v2 = gelu_exact(acc[nt][2] * inv1);
        float v3 = gelu_exact(acc[nt][3] * inv1);
        *(uint32_t*)(o0p + c) = packh2(v0, v1);
        *(uint32_t*)(o1p + c) = packh2(v2, v3);
    }
}

// ---------------------------------------------------------------------------
extern "C" void kernel_launch(void* const* d_in, const int* in_sizes, int n_in,
                              void* d_out, int out_size)
{
    const float* x  = (const float*)d_in[0];
    const float* Wk = (const float*)d_in[1];
    const float* bk = (const float*)d_in[2];
    const float* Wv = (const float*)d_in[3];
    const float* bv = (const float*)d_in[4];
    const float* Wf = (const float*)d_in[5];
    const float* bf_ = (const float*)d_in[6];
    float* out = (float*)d_out;

    f16 *gxfh, *gxfl, *gKfh, *gKfl, *gVf, *gOf, *gWkf, *gWvf, *gWff;
    cudaGetSymbolAddress((void**)&gxfh, g_xfh);
    cudaGetSymbolAddress((void**)&gxfl, g_xfl);
    cudaGetSymbolAddress((void**)&gKfh, g_Kfh);
    cudaGetSymbolAddress((void**)&gKfl, g_Kfl);
    cudaGetSymbolAddress((void**)&gVf,  g_Vf);
    cudaGetSymbolAddress((void**)&gOf,  g_Of);
    cudaGetSymbolAddress((void**)&gWkf, g_Wkf);
    cudaGetSymbolAddress((void**)&gWvf, g_Wvf);
    cudaGetSymbolAddress((void**)&gWff, g_Wff);

    cudaFuncSetAttribute(attn_mma_kernel,
        cudaFuncAttributeMaxDynamicSharedMemorySize, ATTN_SMEM);
    cudaFuncSetAttribute(gemm_f16pair_kernel,
        cudaFuncAttributeMaxDynamicSharedMemorySize, GEMM_SMEM_P);
    cudaFuncSetAttribute(gemm_f16_kernel<0>,
        cudaFuncAttributeMaxDynamicSharedMemorySize, GEMM_SMEM_F1);
    cudaFuncSetAttribute(gemm_f16_kernel<1>,
        cudaFuncAttributeMaxDynamicSharedMemorySize, GEMM_SMEM_F1);

    // 0) conversions (all fp16 now)
    convert_x_kernel<<<(MROWS*DMODEL/4 + 255)/256, 256>>>(
        x, gxfh, gxfl, MROWS*DMODEL/4);
    transpose_f16_kernel<<<dim3(DMODEL/32, DMODEL/32), dim3(32,8)>>>(
        Wk, gWkf, DMODEL, DMODEL);
    transpose_f16_kernel<<<dim3(DHID/32,   DMODEL/32), dim3(32,8)>>>(
        Wv, gWvf, DMODEL, DHID);
    transpose_f16_kernel<<<dim3(DMODEL/32, DHID/32),   dim3(32,8)>>>(
        Wf, gWff, DHID, DMODEL);

    // 1) K = x @ Wk + bk  -> fp16 hi/lo  (fp16 2-mma)
    gemm_f16pair_kernel<<<dim3(DMODEL/GBN, MROWS/GBM), 256, GEMM_SMEM_P>>>(
        gxfh, gxfl, gWkf, bk, gKfh, gKfl, MROWS, DMODEL, DMODEL);

    // 2) V = x @ Wv + bv  -> fp16 single  (fp16 1-mma)
    gemm_f16_kernel<0><<<dim3(DHID/GBN, MROWS/GBM), 256, GEMM_SMEM_F1>>>(
        gxfh, gWvf, bv, nullptr, gVf, nullptr, MROWS, DHID, DMODEL);

    // 3) gelu(attn(x,K,V)) -> fp16 single
    attn_mma_kernel<<<dim3(SQ/AQT, BATCH*NHEADS), 256, ATTN_SMEM>>>(
        gxfh, gxfl, gKfh, gKfl, gVf, gOf);

    // 4) out = x + O @ Wf + bf  (fp16 1-mma)
    gemm_f16_kernel<1><<<dim3(DMODEL/GBN, MROWS/GBM), 256, GEMM_SMEM_F1>>>(
        gOf, gWff, bf_, x, nullptr, out, MROWS, DMODEL, DHID);
}

// round 12
// speedup vs baseline: 7.9833x; 1.0107x over previous
#include <cuda_runtime.h>
#include <cuda_bf16.h>
#include <cuda_fp16.h>
#include <cstdint>
#include <cstddef>
#include <math.h>

// Problem constants
#define BATCH   2
#define SQ      2048
#define DMODEL  1024
#define NHEADS  16
#define DHID    4096
#define DKH     64
#define DVH     256
#define MROWS   (BATCH*SQ)   // 4096

typedef __half f16;

// ---------------- scratch (device globals; no allocation allowed) ----------
__device__ f16  g_xfh[MROWS * DMODEL];   // x fp16 hi
__device__ f16  g_xfl[MROWS * DMODEL];   // x fp16 lo
__device__ f16  g_Kf [MROWS * DMODEL];   // K fp16 single
__device__ f16  g_Vf [MROWS * DHID];     // V fp16 single
__device__ f16  g_Of [MROWS * DHID];     // gelu(attn) fp16 single
__device__ f16  g_Wkf[DMODEL * DMODEL];  // Wk^T fp16 single
__device__ f16  g_Wvf[DHID * DMODEL];    // Wv^T fp16 single
__device__ f16  g_Wff[DMODEL * DHID];    // Wf^T fp16 single

// ---------------- helpers ---------------------------------------------------
__device__ __forceinline__ void cp16(void* s, const void* g) {
    uint32_t sa = (uint32_t)__cvta_generic_to_shared(s);
    asm volatile("cp.async.cg.shared.global [%0], [%1], 16;\n" :: "r"(sa), "l"(g));
}
template<class T>
__device__ __forceinline__ uint32_t lds32(const T* p) {
    return *reinterpret_cast<const uint32_t*>(p);
}
__device__ __forceinline__ uint32_t packh2(float a, float b) {
    __half2 v = __floats2half2_rn(a, b);
    return *reinterpret_cast<uint32_t*>(&v);
}
__device__ __forceinline__ void mma_f16(float* c, uint32_t a0, uint32_t a1,
                                        uint32_t a2, uint32_t a3,
                                        uint32_t b0, uint32_t b1) {
    asm volatile(
        "mma.sync.aligned.m16n8k16.row.col.f32.f16.f16.f32 "
        "{%0,%1,%2,%3}, {%4,%5,%6,%7}, {%8,%9}, {%0,%1,%2,%3};\n"
        : "+f"(c[0]), "+f"(c[1]), "+f"(c[2]), "+f"(c[3])
        : "r"(a0), "r"(a1), "r"(a2), "r"(a3), "r"(b0), "r"(b1));
}
__device__ __forceinline__ void ldmx4t(uint32_t& r0, uint32_t& r1,
                                       uint32_t& r2, uint32_t& r3, const void* p) {
    uint32_t a = (uint32_t)__cvta_generic_to_shared(p);
    asm volatile("ldmatrix.sync.aligned.m8n8.x4.trans.shared.b16 {%0,%1,%2,%3}, [%4];"
                 : "=r"(r0), "=r"(r1), "=r"(r2), "=r"(r3) : "r"(a));
}
__device__ __forceinline__ float gelu_exact(float v) {
    return 0.5f * v * (1.0f + erff(v * 0.70710678118654752f));
}

// ---------------- conversion kernels ---------------------------------------
__global__ __launch_bounds__(256)
void convert_x_kernel(const float* __restrict__ src,
                      f16* __restrict__ fh, f16* __restrict__ fl, int n4)
{
    int i = blockIdx.x * blockDim.x + threadIdx.x;
    if (i >= n4) return;
    float4 v = ((const float4*)src)[i];
    f16 p0 = __float2half_rn(v.x), p1 = __float2half_rn(v.y);
    f16 p2 = __float2half_rn(v.z), p3 = __float2half_rn(v.w);
    __half2 h0 = __halves2half2(p0, p1), h1 = __halves2half2(p2, p3);
    ((uint32_t*)fh)[i*2+0] = *(uint32_t*)&h0;
    ((uint32_t*)fh)[i*2+1] = *(uint32_t*)&h1;
    ((uint32_t*)fl)[i*2+0] = packh2(v.x - __half2float(p0), v.y - __half2float(p1));
    ((uint32_t*)fl)[i*2+1] = packh2(v.z - __half2float(p2), v.w - __half2float(p3));
}

__global__ __launch_bounds__(256)
void transpose_f16_kernel(const float* __restrict__ W, f16* __restrict__ T,
                          int R, int C)
{
    __shared__ float tile[32][33];
    const int c0 = blockIdx.x * 32, r0 = blockIdx.y * 32;
    const int tx = threadIdx.x, ty = threadIdx.y;
    #pragma unroll
    for (int j = 0; j < 4; ++j)
        tile[ty + j*8][tx] = W[(size_t)(r0 + ty + j*8) * C + c0 + tx];
    __syncthreads();
    #pragma unroll
    for (int j = 0; j < 4; ++j)
        T[(size_t)(c0 + ty + j*8) * R + r0 + tx] = __float2half_rn(tile[tx][ty + j*8]);
}

// ---------------- GEMM tiling constants ------------------------------------
#define GBM 128
#define GBN 128
#define GBK 32
#define LDT 40
#define TBUF (GBM * LDT)
#define GEMM_SMEM_P  (6 * TBUF * (int)sizeof(f16))    // 61440 (A pair + B single)
#define GEMM_SMEM_F1 (4 * TBUF * (int)sizeof(f16))    // 40960 (A single + B single)

// ---- fp16 2-mma GEMM (K projection): A fp16 pair, B single, out fp16 single
__global__ __launch_bounds__(256)
void gemm_f16pair_kernel(const f16* __restrict__ Ah, const f16* __restrict__ Al,
                         const f16* __restrict__ B, const float* __restrict__ bias,
                         f16* __restrict__ C, int M, int N, int K)
{
    extern __shared__ f16 smp[];
    f16* sAh = smp;                 // [2][TBUF]
    f16* sAl = smp + 2 * TBUF;
    f16* sB  = smp + 4 * TBUF;

    const int t = threadIdx.x;
    const int warp = t >> 5, lane = t & 31;
    const int g = lane >> 2, tq = lane & 3;
    const int wm = warp >> 2, wn = warp & 3;
    const int m0 = wm * 64, n0 = wn * 32;
    const int rowBase = blockIdx.y * GBM, colBase = blockIdx.x * GBN;

    float acc[4][4][4];
    #pragma unroll
    for (int i = 0; i < 4; ++i)
        #pragma unroll
        for (int j = 0; j < 4; ++j)
            #pragma unroll
            for (int k = 0; k < 4; ++k) acc[i][j][k] = 0.f;

    auto load_tile = [&](int stage, int kt) {
        f16* dAh = sAh + stage * TBUF;
        f16* dAl = sAl + stage * TBUF;
        f16* dB  = sB  + stage * TBUF;
        #pragma unroll
        for (int it = 0; it < 2; ++it) {
            int c  = t + it * 256;
            int r  = c >> 2, cc = (c & 3) * 8;
            size_t ga = (size_t)(rowBase + r) * K + kt + cc;
            size_t gb = (size_t)(colBase + r) * K + kt + cc;
            cp16(dAh + r * LDT + cc, Ah + ga);
            cp16(dAl + r * LDT + cc, Al + ga);
            cp16(dB  + r * LDT + cc, B  + gb);
        }
    };

    const int nk = K / GBK;
    load_tile(0, 0);
    asm volatile("cp.async.commit_group;\n");

    for (int kt = 0; kt < nk; ++kt) {
        const int cur = kt & 1;
        if (kt + 1 < nk) load_tile(cur ^ 1, (kt + 1) * GBK);
        asm volatile("cp.async.commit_group;\n");
        asm volatile("cp.async.wait_group 1;\n");
        __syncthreads();

        const f16* Ahc = sAh + cur * TBUF;
        const f16* Alc = sAl + cur * TBUF;
        const f16* Bc  = sB  + cur * TBUF;

        #pragma unroll
        for (int ks = 0; ks < 2; ++ks) {
            uint32_t bf[4][2];
            #pragma unroll
            for (int ni = 0; ni < 4; ++ni) {
                const f16* p = Bc + (n0 + ni*8 + g) * LDT + ks*16 + tq*2;
                bf[ni][0] = lds32(p);  bf[ni][1] = lds32(p + 8);
            }
            #pragma unroll
            for (int mi = 0; mi < 4; ++mi) {
                const f16* pa = Ahc + (m0 + mi*16 + g) * LDT + ks*16 + tq*2;
                uint32_t ah0 = lds32(pa),     ah1 = lds32(pa + 8*LDT);
                uint32_t ah2 = lds32(pa + 8), ah3 = lds32(pa + 8*LDT + 8);
                const f16* pl = Alc + (m0 + mi*16 + g) * LDT + ks*16 + tq*2;
                uint32_t al0 = lds32(pl),     al1 = lds32(pl + 8*LDT);
                uint32_t al2 = lds32(pl + 8), al3 = lds32(pl + 8*LDT + 8);
                #pragma unroll
                for (int ni = 0; ni < 4; ++ni) {
                    mma_f16(acc[mi][ni], ah0, ah1, ah2, ah3, bf[ni][0], bf[ni][1]);
                    mma_f16(acc[mi][ni], al0, al1, al2, al3, bf[ni][0], bf[ni][1]);
                }
            }
        }
        __syncthreads();
    }

    #pragma unroll
    for (int mi = 0; mi < 4; ++mi) {
        #pragma unroll
        for (int ni = 0; ni < 4; ++ni) {
            int r0 = rowBase + m0 + mi*16 + g;
            int cb = colBase + n0 + ni*8 + tq*2;
            float b0 = bias[cb], b1 = bias[cb + 1];
            *(uint32_t*)&C[(size_t)r0 * N + cb] =
                packh2(acc[mi][ni][0] + b0, acc[mi][ni][1] + b1);
            *(uint32_t*)&C[(size_t)(r0+8) * N + cb] =
                packh2(acc[mi][ni][2] + b0, acc[mi][ni][3] + b1);
        }
    }
}

// ---- fp16 1-mma GEMM: C = A @ B^T + bias, both single fp16 ----------------
//  OUT==0: emit fp16 single.  OUT==1: emit fp32 with residual.
template<int OUT>
__global__ __launch_bounds__(256)
void gemm_f16_kernel(const f16* __restrict__ A, const f16* __restrict__ B,
                     const float* __restrict__ bias, const float* __restrict__ res,
                     f16* __restrict__ Cf, float* __restrict__ C32,
                     int M, int N, int K)
{
    extern __shared__ f16 smh[];
    f16* sA = smh;                 // [2][TBUF]
    f16* sB = smh + 2 * TBUF;      // [2][TBUF]

    const int t = threadIdx.x;
    const int warp = t >> 5, lane = t & 31;
    const int g = lane >> 2, tq = lane & 3;
    const int wm = warp >> 2, wn = warp & 3;
    const int m0 = wm * 64, n0 = wn * 32;
    const int rowBase = blockIdx.y * GBM, colBase = blockIdx.x * GBN;

    float acc[4][4][4];
    #pragma unroll
    for (int i = 0; i < 4; ++i)
        #pragma unroll
        for (int j = 0; j < 4; ++j)
            #pragma unroll
            for (int k = 0; k < 4; ++k) acc[i][j][k] = 0.f;

    auto load_tile = [&](int stage, int kt) {
        f16* dA = sA + stage * TBUF;
        f16* dB = sB + stage * TBUF;
        #pragma unroll
        for (int it = 0; it < 2; ++it) {
            int c  = t + it * 256;
            int r  = c >> 2, cc = (c & 3) * 8;
            cp16(dA + r * LDT + cc, A + (size_t)(rowBase + r) * K + kt + cc);
            cp16(dB + r * LDT + cc, B + (size_t)(colBase + r) * K + kt + cc);
        }
    };

    const int nk = K / GBK;
    load_tile(0, 0);
    asm volatile("cp.async.commit_group;\n");

    for (int kt = 0; kt < nk; ++kt) {
        const int cur = kt & 1;
        if (kt + 1 < nk) load_tile(cur ^ 1, (kt + 1) * GBK);
        asm volatile("cp.async.commit_group;\n");
        asm volatile("cp.async.wait_group 1;\n");
        __syncthreads();

        const f16* Ac = sA + cur * TBUF;
        const f16* Bc = sB + cur * TBUF;

        #pragma unroll
        for (int ks = 0; ks < 2; ++ks) {
            uint32_t bf[4][2];
            #pragma unroll
            for (int ni = 0; ni < 4; ++ni) {
                const f16* p = Bc + (n0 + ni*8 + g) * LDT + ks*16 + tq*2;
                bf[ni][0] = lds32(p);  bf[ni][1] = lds32(p + 8);
            }
            #pragma unroll
            for (int mi = 0; mi < 4; ++mi) {
                const f16* pa = Ac + (m0 + mi*16 + g) * LDT + ks*16 + tq*2;
                uint32_t a0 = lds32(pa),     a1 = lds32(pa + 8*LDT);
                uint32_t a2 = lds32(pa + 8), a3 = lds32(pa + 8*LDT + 8);
                #pragma unroll
                for (int ni = 0; ni < 4; ++ni)
                    mma_f16(acc[mi][ni], a0, a1, a2, a3, bf[ni][0], bf[ni][1]);
            }
        }
        __syncthreads();
    }

    #pragma unroll
    for (int mi = 0; mi < 4; ++mi) {
        #pragma unroll
        for (int ni = 0; ni < 4; ++ni) {
            int r0 = rowBase + m0 + mi*16 + g;
            int cb = colBase + n0 + ni*8 + tq*2;
            float b0 = bias[cb], b1 = bias[cb + 1];
            float v0 = acc[mi][ni][0] + b0, v1 = acc[mi][ni][1] + b1;
            float v2 = acc[mi][ni][2] + b0, v3 = acc[mi][ni][3] + b1;
            if (OUT == 0) {
                *(uint32_t*)&Cf[(size_t)r0 * N + cb]     = packh2(v0, v1);
                *(uint32_t*)&Cf[(size_t)(r0+8) * N + cb] = packh2(v2, v3);
            } else {
                float2 r0v = *(const float2*)&res[(size_t)r0 * N + cb];
                float2 r1v = *(const float2*)&res[(size_t)(r0+8) * N + cb];
                float2 o0 = { v0 + r0v.x, v1 + r0v.y };
                float2 o1 = { v2 + r1v.x, v3 + r1v.y };
                *(float2*)&C32[(size_t)r0 * N + cb]     = o0;
                *(float2*)&C32[(size_t)(r0+8) * N + cb] = o1;
            }
        }
    }
}

// ---------------- tensor-core causal flash attention + GELU ----------------
#define AQT 128
#define AKT 64
#define LDQ 72
#define LDK 72
#define LDV 264
#define QBUF (AQT*LDQ)                 // 9216
#define KBUF (AKT*LDK)                 // 4608
#define VBUF (AKT*LDV)                 // 16896
// Q fp16 pair + K fp16 single x2 stages + V fp16 single x2 stages
#define ATTN_SMEM ((2*QBUF + 2*KBUF + 2*VBUF) * 2)    // 122880 B

__global__ __launch_bounds__(256, 1)
void attn_mma_kernel(const f16* __restrict__ xh, const f16* __restrict__ xl,
                     const f16* __restrict__ Kf, const f16* __restrict__ Vf,
                     f16* __restrict__ Og)
{
    extern __shared__ char smraw[];
    f16* sQh = (f16*)smraw;
    f16* sQl = sQh + QBUF;
    f16* sK  = sQl + QBUF;        // [2][KBUF]
    f16* sV  = sK + 2*KBUF;       // [2][VBUF]

    const int qtile = gridDim.x - 1 - blockIdx.x;   // long CTAs first
    const int bh = blockIdx.y;
    const int b = bh >> 4, h = bh & 15;
    const int q0 = qtile * AQT;
    const int t = threadIdx.x, warp = t >> 5, lane = t & 31;
    const int g = lane >> 2, tq = lane & 3;
    const int wrow = warp * 16;

    // ---- Q tile load (once) ----
    const size_t qbase = (size_t)(b*SQ + q0) * DMODEL + (size_t)h * DKH;
    #pragma unroll
    for (int i = 0; i < 8; ++i) {
        int chunk = t + i*256;              // 0..2047
        int r = chunk >> 4;
        int rem = chunk & 15;
        const f16* src = (rem & 8) ? xl : xh;
        f16* dst = (rem & 8) ? sQl : sQh;
        int c = (rem & 7) * 8;
        cp16(dst + r*LDQ + c, src + qbase + (size_t)r*DMODEL + c);
    }

    const size_t kbase = (size_t)(b*SQ) * DMODEL + (size_t)h * DKH;
    const size_t vbase = (size_t)(b*SQ) * DHID  + (size_t)h * DVH;

    auto load_kv = [&](int st, int kb) {
        f16* dK = sK + st*KBUF;
        f16* dV = sV + st*VBUF;
        #pragma unroll
        for (int i = 0; i < 2; ++i) {
            int chunk = t + i*256;          // 0..511 (64 rows x 8 chunks)
            int r = chunk >> 3;
            int c = (chunk & 7) * 8;
            cp16(dK + r*LDK + c, Kf + kbase + (size_t)(kb + r)*DMODEL + c);
        }
        #pragma unroll
        for (int i = 0; i < 8; ++i) {
            int chunk = t + i*256;          // 0..2047
            int r = chunk >> 5;             // 0..63
            int c = (chunk & 31) * 8;
            cp16(dV + r*LDV + c, Vf + vbase + (size_t)(kb + r)*DHID + c);
        }
    };

    float acc[32][4];
    #pragma unroll
    for (int i = 0; i < 32; ++i) { acc[i][0]=0.f; acc[i][1]=0.f; acc[i][2]=0.f; acc[i][3]=0.f; }
    float m0 = -INFINITY, m1 = -INFINITY, l0 = 0.f, l1 = 0.f;

    const int ntiles = 2*qtile + 2;
    load_kv(0, 0);
    asm volatile("cp.async.commit_group;\n");

    const int mat = lane >> 3;
    const int lmoff = ((mat & 1)*8 + (lane & 7)) * LDV + (mat >> 1)*8;

    const int qrow0 = q0 + wrow + g;
    const int qrow1 = qrow0 + 8;

    for (int j = 0; j < ntiles; ++j) {
        const int cur = j & 1;
        const int kb = j * AKT;
        if (j + 1 < ntiles) load_kv(cur ^ 1, kb + AKT);
        asm volatile("cp.async.commit_group;\n");
        asm volatile("cp.async.wait_group 1;\n");
        __syncthreads();

        const bool active = (kb <= q0 + wrow + 15);   // warp-uniform causal skip
        if (active) {
            const f16* cK = sK + cur*KBUF;
            const f16* cV = sV + cur*VBUF;

            // ---- S = Q @ K^T (Q fp16 hi/lo pair, K single: 2-mma) ----
            float sc[8][4];
            #pragma unroll
            for (int nt = 0; nt < 8; ++nt) { sc[nt][0]=0.f; sc[nt][1]=0.f; sc[nt][2]=0.f; sc[nt][3]=0.f; }
            #pragma unroll
            for (int ks = 0; ks < 4; ++ks) {
                const f16* pah = sQh + (wrow+g)*LDQ + ks*16 + tq*2;
                const f16* pal = sQl + (wrow+g)*LDQ + ks*16 + tq*2;
                uint32_t qh0 = lds32(pah),     qh1 = lds32(pah + 8*LDQ);
                uint32_t qh2 = lds32(pah + 8), qh3 = lds32(pah + 8*LDQ + 8);
                uint32_t ql0 = lds32(pal),     ql1 = lds32(pal + 8*LDQ);
                uint32_t ql2 = lds32(pal + 8), ql3 = lds32(pal + 8*LDQ + 8);
                #pragma unroll
                for (int nt = 0; nt < 8; ++nt) {
                    const f16* pb = cK + (nt*8+g)*LDK + ks*16 + tq*2;
                    uint32_t k0 = lds32(pb), k1 = lds32(pb + 8);
                    mma_f16(sc[nt], qh0,qh1,qh2,qh3, k0, k1);
                    mma_f16(sc[nt], ql0,ql1,ql2,ql3, k0, k1);
                }
            }

            // ---- causal mask ----
            if (kb + AKT - 1 > q0 + wrow) {
                #pragma unroll
                for (int nt = 0; nt < 8; ++nt) {
                    int k0 = kb + nt*8 + tq*2;
                    if (k0     > qrow0) sc[nt][0] = -INFINITY;
                    if (k0 + 1 > qrow0) sc[nt][1] = -INFINITY;
                    if (k0     > qrow1) sc[nt][2] = -INFINITY;
                    if (k0 + 1 > qrow1) sc[nt][3] = -INFINITY;
                }
            }

            // ---- online softmax ----
            float mx0 = -INFINITY, mx1 = -INFINITY;
            #pragma unroll
            for (int nt = 0; nt < 8; ++nt) {
                mx0 = fmaxf(mx0, fmaxf(sc[nt][0], sc[nt][1]));
                mx1 = fmaxf(mx1, fmaxf(sc[nt][2], sc[nt][3]));
            }
            mx0 = fmaxf(mx0, __shfl_xor_sync(0xffffffffu, mx0, 1));
            mx0 = fmaxf(mx0, __shfl_xor_sync(0xffffffffu, mx0, 2));
            mx1 = fmaxf(mx1, __shfl_xor_sync(0xffffffffu, mx1, 1));
            mx1 = fmaxf(mx1, __shfl_xor_sync(0xffffffffu, mx1, 2));
            float mn0 = fmaxf(m0, mx0), mn1 = fmaxf(m1, mx1);
            float al0 = __expf(m0 - mn0), al1 = __expf(m1 - mn1);
            m0 = mn0; m1 = mn1;

            float ps0 = 0.f, ps1 = 0.f;
            uint32_t ph[8][2];
            #pragma unroll
            for (int nt = 0; nt < 8; ++nt) {
                float p0 = __expf(sc[nt][0] - mn0);
                float p1 = __expf(sc[nt][1] - mn0);
                float p2 = __expf(sc[nt][2] - mn1);
                float p3 = __expf(sc[nt][3] - mn1);
                ps0 += p0 + p1; ps1 += p2 + p3;
                ph[nt][0] = packh2(p0, p1);
                ph[nt][1] = packh2(p2, p3);
            }
            ps0 += __shfl_xor_sync(0xffffffffu, ps0, 1);
            ps0 += __shfl_xor_sync(0xffffffffu, ps0, 2);
            ps1 += __shfl_xor_sync(0xffffffffu, ps1, 1);
            ps1 += __shfl_xor_sync(0xffffffffu, ps1, 2);
            l0 = l0*al0 + ps0;
            l1 = l1*al1 + ps1;
            #pragma unroll
            for (int i = 0; i < 32; ++i) {
                acc[i][0] *= al0; acc[i][1] *= al0;
                acc[i][2] *= al1; acc[i][3] *= al1;
            }

            // ---- O += P @ V  (fp16 single) ----
            #pragma unroll
            for (int kk = 0; kk < 4; ++kk) {
                uint32_t a0 = ph[2*kk][0],   a1 = ph[2*kk][1];
                uint32_t a2 = ph[2*kk+1][0], a3 = ph[2*kk+1][1];
                #pragma unroll
                for (int ng = 0; ng < 16; ++ng) {
                    uint32_t v0,v1,v2,v3;
                    ldmx4t(v0,v1,v2,v3, cV + kk*16*LDV + ng*16 + lmoff);
                    mma_f16(acc[2*ng],   a0,a1,a2,a3, v0, v1);
                    mma_f16(acc[2*ng+1], a0,a1,a2,a3, v2, v3);
                }
            }
        }
        __syncthreads();
    }

    // ---- epilogue: normalize + GELU -> fp16 single ----
    const float inv0 = 1.0f / l0, inv1 = 1.0f / l1;
    f16* o0p = Og + ((size_t)b*SQ + qrow0)*DHID + (size_t)h*DVH;
    f16* o1p = Og + ((size_t)b*SQ + qrow1)*DHID + (size_t)h*DVH;
    #pragma unroll
    for (int nt = 0; nt < 32; ++nt) {
        int c = nt*8 + tq*2;
        float v0 = gelu_exact(acc[nt][0] * inv0);
        float v1 = gelu_exact(acc[nt][1] * inv0);
        float v2 = gelu_exact(acc[nt][2] * inv1);
        float v3 = gelu_exact(acc[nt][3] * inv1);
        *(uint32_t*)(o0p + c) = packh2(v0, v1);
        *(uint32_t*)(o1p + c) = packh2(v2, v3);
    }
}

// ---------------------------------------------------------------------------
extern "C" void kernel_launch(void* const* d_in, const int* in_sizes, int n_in,
                              void* d_out, int out_size)
{
    const float* x  = (const float*)d_in[0];
    const float* Wk = (const float*)d_in[1];
    const float* bk = (const float*)d_in[2];
    const float* Wv = (const float*)d_in[3];
    const float* bv = (const float*)d_in[4];
    const float* Wf = (const float*)d_in[5];
    const float* bf_ = (const float*)d_in[6];
    float* out = (float*)d_out;

    f16 *gxfh, *gxfl, *gKf, *gVf, *gOf, *gWkf, *gWvf, *gWff;
    cudaGetSymbolAddress((void**)&gxfh, g_xfh);
    cudaGetSymbolAddress((void**)&gxfl, g_xfl);
    cudaGetSymbolAddress((void**)&gKf,  g_Kf);
    cudaGetSymbolAddress((void**)&gVf,  g_Vf);
    cudaGetSymbolAddress((void**)&gOf,  g_Of);
    cudaGetSymbolAddress((void**)&gWkf, g_Wkf);
    cudaGetSymbolAddress((void**)&gWvf, g_Wvf);
    cudaGetSymbolAddress((void**)&gWff, g_Wff);

    cudaFuncSetAttribute(attn_mma_kernel,
        cudaFuncAttributeMaxDynamicSharedMemorySize, ATTN_SMEM);
    cudaFuncSetAttribute(gemm_f16pair_kernel,
        cudaFuncAttributeMaxDynamicSharedMemorySize, GEMM_SMEM_P);
    cudaFuncSetAttribute(gemm_f16_kernel<0>,
        cudaFuncAttributeMaxDynamicSharedMemorySize, GEMM_SMEM_F1);
    cudaFuncSetAttribute(gemm_f16_kernel<1>,
        cudaFuncAttributeMaxDynamicSharedMemorySize, GEMM_SMEM_F1);

    // 0) conversions
    convert_x_kernel<<<(MROWS*DMODEL/4 + 255)/256, 256>>>(
        x, gxfh, gxfl, MROWS*DMODEL/4);
    transpose_f16_kernel<<<dim3(DMODEL/32, DMODEL/32), dim3(32,8)>>>(
        Wk, gWkf, DMODEL, DMODEL);
    transpose_f16_kernel<<<dim3(DHID/32,   DMODEL/32), dim3(32,8)>>>(
        Wv, gWvf, DMODEL, DHID);
    transpose_f16_kernel<<<dim3(DMODEL/32, DHID/32),   dim3(32,8)>>>(
        Wf, gWff, DHID, DMODEL);

    // 1) K = x @ Wk + bk  -> fp16 single  (fp16 2-mma, x pair)
    gemm_f16pair_kernel<<<dim3(DMODEL/GBN, MROWS/GBM), 256, GEMM_SMEM_P>>>(
        gxfh, gxfl, gWkf, bk, gKf, MROWS, DMODEL, DMODEL);

    // 2) V = x @ Wv + bv  -> fp16 single  (fp16 1-mma)
    gemm_f16_kernel<0><<<dim3(DHID/GBN, MROWS/GBM), 256, GEMM_SMEM_F1>>>(
        gxfh, gWvf, bv, nullptr, gVf, nullptr, MROWS, DHID, DMODEL);

    // 3) gelu(attn(x,K,V)) -> fp16 single
    attn_mma_kernel<<<dim3(SQ/AQT, BATCH*NHEADS), 256, ATTN_SMEM>>>(
        gxfh, gxfl, gKf, gVf, gOf);

    // 4) out = x + O @ Wf + bf  (fp16 1-mma)
    gemm_f16_kernel<1><<<dim3(DMODEL/GBN, MROWS/GBM), 256, GEMM_SMEM_F1>>>(
        gOf, gWff, bf_, x, nullptr, out, MROWS, DMODEL, DHID);
}

// round 14
// speedup vs baseline: 8.0088x; 1.0032x over previous
#include <cuda_runtime.h>
#include <cuda_bf16.h>
#include <cuda_fp16.h>
#include <cstdint>
#include <cstddef>
#include <math.h>

// Problem constants
#define BATCH   2
#define SQ      2048
#define DMODEL  1024
#define NHEADS  16
#define DHID    4096
#define DKH     64
#define DVH     256
#define MROWS   (BATCH*SQ)   // 4096

typedef __half f16;

// ---------------- scratch (device globals; no allocation allowed) ----------
__device__ f16  g_xfh[MROWS * DMODEL];   // x fp16 hi
__device__ f16  g_xfl[MROWS * DMODEL];   // x fp16 lo
__device__ f16  g_Kf [MROWS * DMODEL];   // K fp16 single
__device__ f16  g_Vf [MROWS * DHID];     // V fp16 single
__device__ f16  g_Of [MROWS * DHID];     // gelu(attn) fp16 single
__device__ f16  g_Wkf[DMODEL * DMODEL];  // Wk^T fp16 single
__device__ f16  g_Wvf[DHID * DMODEL];    // Wv^T fp16 single
__device__ f16  g_Wff[DMODEL * DHID];    // Wf^T fp16 single

// ---------------- helpers ---------------------------------------------------
__device__ __forceinline__ void cp16(void* s, const void* g) {
    uint32_t sa = (uint32_t)__cvta_generic_to_shared(s);
    asm volatile("cp.async.cg.shared.global [%0], [%1], 16;\n" :: "r"(sa), "l"(g));
}
template<class T>
__device__ __forceinline__ uint32_t lds32(const T* p) {
    return *reinterpret_cast<const uint32_t*>(p);
}
__device__ __forceinline__ uint32_t packh2(float a, float b) {
    __half2 v = __floats2half2_rn(a, b);
    return *reinterpret_cast<uint32_t*>(&v);
}
__device__ __forceinline__ void mma_f16(float* c, uint32_t a0, uint32_t a1,
                                        uint32_t a2, uint32_t a3,
                                        uint32_t b0, uint32_t b1) {
    asm volatile(
        "mma.sync.aligned.m16n8k16.row.col.f32.f16.f16.f32 "
        "{%0,%1,%2,%3}, {%4,%5,%6,%7}, {%8,%9}, {%0,%1,%2,%3};\n"
        : "+f"(c[0]), "+f"(c[1]), "+f"(c[2]), "+f"(c[3])
        : "r"(a0), "r"(a1), "r"(a2), "r"(a3), "r"(b0), "r"(b1));
}
__device__ __forceinline__ void ldmx4t(uint32_t& r0, uint32_t& r1,
                                       uint32_t& r2, uint32_t& r3, const void* p) {
    uint32_t a = (uint32_t)__cvta_generic_to_shared(p);
    asm volatile("ldmatrix.sync.aligned.m8n8.x4.trans.shared.b16 {%0,%1,%2,%3}, [%4];"
                 : "=r"(r0), "=r"(r1), "=r"(r2), "=r"(r3) : "r"(a));
}
__device__ __forceinline__ float gelu_exact(float v) {
    return 0.5f * v * (1.0f + erff(v * 0.70710678118654752f));
}

// ---------------- conversion kernels ---------------------------------------
__global__ __launch_bounds__(256)
void convert_x_kernel(const float* __restrict__ src,
                      f16* __restrict__ fh, f16* __restrict__ fl, int n4)
{
    int i = blockIdx.x * blockDim.x + threadIdx.x;
    if (i >= n4) return;
    float4 v = ((const float4*)src)[i];
    f16 p0 = __float2half_rn(v.x), p1 = __float2half_rn(v.y);
    f16 p2 = __float2half_rn(v.z), p3 = __float2half_rn(v.w);
    __half2 h0 = __halves2half2(p0, p1), h1 = __halves2half2(p2, p3);
    ((uint32_t*)fh)[i*2+0] = *(uint32_t*)&h0;
    ((uint32_t*)fh)[i*2+1] = *(uint32_t*)&h1;
    ((uint32_t*)fl)[i*2+0] = packh2(v.x - __half2float(p0), v.y - __half2float(p1));
    ((uint32_t*)fl)[i*2+1] = packh2(v.z - __half2float(p2), v.w - __half2float(p3));
}

__global__ __launch_bounds__(256)
void transpose_f16_kernel(const float* __restrict__ W, f16* __restrict__ T,
                          int R, int C)
{
    __shared__ float tile[32][33];
    const int c0 = blockIdx.x * 32, r0 = blockIdx.y * 32;
    const int tx = threadIdx.x, ty = threadIdx.y;
    #pragma unroll
    for (int j = 0; j < 4; ++j)
        tile[ty + j*8][tx] = W[(size_t)(r0 + ty + j*8) * C + c0 + tx];
    __syncthreads();
    #pragma unroll
    for (int j = 0; j < 4; ++j)
        T[(size_t)(c0 + ty + j*8) * R + r0 + tx] = __float2half_rn(tile[tx][ty + j*8]);
}

// ---------------- GEMM tiling constants ------------------------------------
#define GBM 128
#define GBN 128
#define GBK 32
#define LDT 40
#define TBUF (GBM * LDT)
#define GEMM_SMEM_P  (6 * TBUF * (int)sizeof(f16))    // 61440 (A pair + B single)
#define GEMM_SMEM_F1 (4 * TBUF * (int)sizeof(f16))    // 40960 (A single + B single)

// ---- fp16 2-mma GEMM (K projection): A fp16 pair, B single, out fp16 single
__global__ __launch_bounds__(256)
void gemm_f16pair_kernel(const f16* __restrict__ Ah, const f16* __restrict__ Al,
                         const f16* __restrict__ B, const float* __restrict__ bias,
                         f16* __restrict__ C, int M, int N, int K)
{
    extern __shared__ f16 smp[];
    f16* sAh = smp;                 // [2][TBUF]
    f16* sAl = smp + 2 * TBUF;
    f16* sB  = smp + 4 * TBUF;

    const int t = threadIdx.x;
    const int warp = t >> 5, lane = t & 31;
    const int g = lane >> 2, tq = lane & 3;
    const int wm = warp >> 2, wn = warp & 3;
    const int m0 = wm * 64, n0 = wn * 32;
    const int rowBase = blockIdx.y * GBM, colBase = blockIdx.x * GBN;

    float acc[4][4][4];
    #pragma unroll
    for (int i = 0; i < 4; ++i)
        #pragma unroll
        for (int j = 0; j < 4; ++j)
            #pragma unroll
            for (int k = 0; k < 4; ++k) acc[i][j][k] = 0.f;

    auto load_tile = [&](int stage, int kt) {
        f16* dAh = sAh + stage * TBUF;
        f16* dAl = sAl + stage * TBUF;
        f16* dB  = sB  + stage * TBUF;
        #pragma unroll
        for (int it = 0; it < 2; ++it) {
            int c  = t + it * 256;
            int r  = c >> 2, cc = (c & 3) * 8;
            size_t ga = (size_t)(rowBase + r) * K + kt + cc;
            size_t gb = (size_t)(colBase + r) * K + kt + cc;
            cp16(dAh + r * LDT + cc, Ah + ga);
            cp16(dAl + r * LDT + cc, Al + ga);
            cp16(dB  + r * LDT + cc, B  + gb);
        }
    };

    const int nk = K / GBK;
    load_tile(0, 0);
    asm volatile("cp.async.commit_group;\n");

    for (int kt = 0; kt < nk; ++kt) {
        const int cur = kt & 1;
        if (kt + 1 < nk) load_tile(cur ^ 1, (kt + 1) * GBK);
        asm volatile("cp.async.commit_group;\n");
        asm volatile("cp.async.wait_group 1;\n");
        __syncthreads();

        const f16* Ahc = sAh + cur * TBUF;
        const f16* Alc = sAl + cur * TBUF;
        const f16* Bc  = sB  + cur * TBUF;

        #pragma unroll
        for (int ks = 0; ks < 2; ++ks) {
            uint32_t bf[4][2];
            #pragma unroll
            for (int ni = 0; ni < 4; ++ni) {
                const f16* p = Bc + (n0 + ni*8 + g) * LDT + ks*16 + tq*2;
                bf[ni][0] = lds32(p);  bf[ni][1] = lds32(p + 8);
            }
            #pragma unroll
            for (int mi = 0; mi < 4; ++mi) {
                const f16* pa = Ahc + (m0 + mi*16 + g) * LDT + ks*16 + tq*2;
                uint32_t ah0 = lds32(pa),     ah1 = lds32(pa + 8*LDT);
                uint32_t ah2 = lds32(pa + 8), ah3 = lds32(pa + 8*LDT + 8);
                const f16* pl = Alc + (m0 + mi*16 + g) * LDT + ks*16 + tq*2;
                uint32_t al0 = lds32(pl),     al1 = lds32(pl + 8*LDT);
                uint32_t al2 = lds32(pl + 8), al3 = lds32(pl + 8*LDT + 8);
                #pragma unroll
                for (int ni = 0; ni < 4; ++ni) {
                    mma_f16(acc[mi][ni], ah0, ah1, ah2, ah3, bf[ni][0], bf[ni][1]);
                    mma_f16(acc[mi][ni], al0, al1, al2, al3, bf[ni][0], bf[ni][1]);
                }
            }
        }
        __syncthreads();
    }

    #pragma unroll
    for (int mi = 0; mi < 4; ++mi) {
        #pragma unroll
        for (int ni = 0; ni < 4; ++ni) {
            int r0 = rowBase + m0 + mi*16 + g;
            int cb = colBase + n0 + ni*8 + tq*2;
            float b0 = bias[cb], b1 = bias[cb + 1];
            *(uint32_t*)&C[(size_t)r0 * N + cb] =
                packh2(acc[mi][ni][0] + b0, acc[mi][ni][1] + b1);
            *(uint32_t*)&C[(size_t)(r0+8) * N + cb] =
                packh2(acc[mi][ni][2] + b0, acc[mi][ni][3] + b1);
        }
    }
}

// ---- fp16 1-mma GEMM: C = A @ B^T + bias, both single fp16 ----------------
//  OUT==0: emit fp16 single.  OUT==1: emit fp32 with residual.
template<int OUT>
__global__ __launch_bounds__(256)
void gemm_f16_kernel(const f16* __restrict__ A, const f16* __restrict__ B,
                     const float* __restrict__ bias, const float* __restrict__ res,
                     f16* __restrict__ Cf, float* __restrict__ C32,
                     int M, int N, int K)
{
    extern __shared__ f16 smh[];
    f16* sA = smh;                 // [2][TBUF]
    f16* sB = smh + 2 * TBUF;      // [2][TBUF]

    const int t = threadIdx.x;
    const int warp = t >> 5, lane = t & 31;
    const int g = lane >> 2, tq = lane & 3;
    const int wm = warp >> 2, wn = warp & 3;
    const int m0 = wm * 64, n0 = wn * 32;
    const int rowBase = blockIdx.y * GBM, colBase = blockIdx.x * GBN;

    float acc[4][4][4];
    #pragma unroll
    for (int i = 0; i < 4; ++i)
        #pragma unroll
        for (int j = 0; j < 4; ++j)
            #pragma unroll
            for (int k = 0; k < 4; ++k) acc[i][j][k] = 0.f;

    auto load_tile = [&](int stage, int kt) {
        f16* dA = sA + stage * TBUF;
        f16* dB = sB + stage * TBUF;
        #pragma unroll
        for (int it = 0; it < 2; ++it) {
            int c  = t + it * 256;
            int r  = c >> 2, cc = (c & 3) * 8;
            cp16(dA + r * LDT + cc, A + (size_t)(rowBase + r) * K + kt + cc);
            cp16(dB + r * LDT + cc, B + (size_t)(colBase + r) * K + kt + cc);
        }
    };

    const int nk = K / GBK;
    load_tile(0, 0);
    asm volatile("cp.async.commit_group;\n");

    for (int kt = 0; kt < nk; ++kt) {
        const int cur = kt & 1;
        if (kt + 1 < nk) load_tile(cur ^ 1, (kt + 1) * GBK);
        asm volatile("cp.async.commit_group;\n");
        asm volatile("cp.async.wait_group 1;\n");
        __syncthreads();

        const f16* Ac = sA + cur * TBUF;
        const f16* Bc = sB + cur * TBUF;

        #pragma unroll
        for (int ks = 0; ks < 2; ++ks) {
            uint32_t bf[4][2];
            #pragma unroll
            for (int ni = 0; ni < 4; ++ni) {
                const f16* p = Bc + (n0 + ni*8 + g) * LDT + ks*16 + tq*2;
                bf[ni][0] = lds32(p);  bf[ni][1] = lds32(p + 8);
            }
            #pragma unroll
            for (int mi = 0; mi < 4; ++mi) {
                const f16* pa = Ac + (m0 + mi*16 + g) * LDT + ks*16 + tq*2;
                uint32_t a0 = lds32(pa),     a1 = lds32(pa + 8*LDT);
                uint32_t a2 = lds32(pa + 8), a3 = lds32(pa + 8*LDT + 8);
                #pragma unroll
                for (int ni = 0; ni < 4; ++ni)
                    mma_f16(acc[mi][ni], a0, a1, a2, a3, bf[ni][0], bf[ni][1]);
            }
        }
        __syncthreads();
    }

    #pragma unroll
    for (int mi = 0; mi < 4; ++mi) {
        #pragma unroll
        for (int ni = 0; ni < 4; ++ni) {
            int r0 = rowBase + m0 + mi*16 + g;
            int cb = colBase + n0 + ni*8 + tq*2;
            float b0 = bias[cb], b1 = bias[cb + 1];
            float v0 = acc[mi][ni][0] + b0, v1 = acc[mi][ni][1] + b1;
            float v2 = acc[mi][ni][2] + b0, v3 = acc[mi][ni][3] + b1;
            if (OUT == 0) {
                *(uint32_t*)&Cf[(size_t)r0 * N + cb]     = packh2(v0, v1);
                *(uint32_t*)&Cf[(size_t)(r0+8) * N + cb] = packh2(v2, v3);
            } else {
                float2 r0v = *(const float2*)&res[(size_t)r0 * N + cb];
                float2 r1v = *(const float2*)&res[(size_t)(r0+8) * N + cb];
                float2 o0 = { v0 + r0v.x, v1 + r0v.y };
                float2 o1 = { v2 + r1v.x, v3 + r1v.y };
                *(float2*)&C32[(size_t)r0 * N + cb]     = o0;
                *(float2*)&C32[(size_t)(r0+8) * N + cb] = o1;
            }
        }
    }
}

// ---------------- tensor-core causal flash attention + GELU ----------------
// AQT=64, 128 threads (4 warps x 16 rows), 2 CTAs/SM for latency hiding.
#define AQT 64
#define AKT 64
#define LDQ 72
#define LDK 72
#define LDV 264
#define QBUF (AQT*LDQ)                 // 4608
#define KBUF (AKT*LDK)                 // 4608
#define VBUF (AKT*LDV)                 // 16896
// Q fp16 pair + K single x2 stages + V single x2 stages
#define ATTN_SMEM ((2*QBUF + 2*KBUF + 2*VBUF) * 2)    // 104448 B

__global__ __launch_bounds__(128, 2)
void attn_mma_kernel(const f16* __restrict__ xh, const f16* __restrict__ xl,
                     const f16* __restrict__ Kf, const f16* __restrict__ Vf,
                     f16* __restrict__ Og)
{
    extern __shared__ char smraw[];
    f16* sQh = (f16*)smraw;
    f16* sQl = sQh + QBUF;
    f16* sK  = sQl + QBUF;        // [2][KBUF]
    f16* sV  = sK + 2*KBUF;       // [2][VBUF]

    const int qtile = gridDim.x - 1 - blockIdx.x;   // long CTAs first
    const int bh = blockIdx.y;
    const int b = bh >> 4, h = bh & 15;
    const int q0 = qtile * AQT;
    const int t = threadIdx.x, warp = t >> 5, lane = t & 31;
    const int g = lane >> 2, tq = lane & 3;
    const int wrow = warp * 16;

    // ---- Q tile load (once): 64 rows x 64 cols x 2 planes ----
    const size_t qbase = (size_t)(b*SQ + q0) * DMODEL + (size_t)h * DKH;
    #pragma unroll
    for (int i = 0; i < 8; ++i) {
        int chunk = t + i*128;              // 0..1023
        int r = chunk >> 4;                 // 0..63
        int rem = chunk & 15;
        const f16* src = (rem & 8) ? xl : xh;
        f16* dst = (rem & 8) ? sQl : sQh;
        int c = (rem & 7) * 8;
        cp16(dst + r*LDQ + c, src + qbase + (size_t)r*DMODEL + c);
    }

    const size_t kbase = (size_t)(b*SQ) * DMODEL + (size_t)h * DKH;
    const size_t vbase = (size_t)(b*SQ) * DHID  + (size_t)h * DVH;

    auto load_kv = [&](int st, int kb) {
        f16* dK = sK + st*KBUF;
        f16* dV = sV + st*VBUF;
        #pragma unroll
        for (int i = 0; i < 4; ++i) {
            int chunk = t + i*128;          // 0..511
            int r = chunk >> 3;             // 0..63
            int c = (chunk & 7) * 8;
            cp16(dK + r*LDK + c, Kf + kbase + (size_t)(kb + r)*DMODEL + c);
        }
        #pragma unroll
        for (int i = 0; i < 16; ++i) {
            int chunk = t + i*128;          // 0..2047
            int r = chunk >> 5;             // 0..63
            int c = (chunk & 31) * 8;
            cp16(dV + r*LDV + c, Vf + vbase + (size_t)(kb + r)*DHID + c);
        }
    };

    float acc[32][4];
    #pragma unroll
    for (int i = 0; i < 32; ++i) { acc[i][0]=0.f; acc[i][1]=0.f; acc[i][2]=0.f; acc[i][3]=0.f; }
    float m0 = -INFINITY, m1 = -INFINITY, l0 = 0.f, l1 = 0.f;

    const int ntiles = qtile + 1;
    load_kv(0, 0);
    asm volatile("cp.async.commit_group;\n");

    const int mat = lane >> 3;
    const int lmoff = ((mat & 1)*8 + (lane & 7)) * LDV + (mat >> 1)*8;

    const int qrow0 = q0 + wrow + g;
    const int qrow1 = qrow0 + 8;

    for (int j = 0; j < ntiles; ++j) {
        const int cur = j & 1;
        const int kb = j * AKT;
        if (j + 1 < ntiles) load_kv(cur ^ 1, kb + AKT);
        asm volatile("cp.async.commit_group;\n");
        asm volatile("cp.async.wait_group 1;\n");
        __syncthreads();

        {
            const f16* cK = sK + cur*KBUF;
            const f16* cV = sV + cur*VBUF;

            // ---- S = Q @ K^T (Q fp16 hi/lo pair, K single: 2-mma) ----
            float sc[8][4];
            #pragma unroll
            for (int nt = 0; nt < 8; ++nt) { sc[nt][0]=0.f; sc[nt][1]=0.f; sc[nt][2]=0.f; sc[nt][3]=0.f; }
            #pragma unroll
            for (int ks = 0; ks < 4; ++ks) {
                const f16* pah = sQh + (wrow+g)*LDQ + ks*16 + tq*2;
                const f16* pal = sQl + (wrow+g)*LDQ + ks*16 + tq*2;
                uint32_t qh0 = lds32(pah),     qh1 = lds32(pah + 8*LDQ);
                uint32_t qh2 = lds32(pah + 8), qh3 = lds32(pah + 8*LDQ + 8);
                uint32_t ql0 = lds32(pal),     ql1 = lds32(pal + 8*LDQ);
                uint32_t ql2 = lds32(pal + 8), ql3 = lds32(pal + 8*LDQ + 8);
                #pragma unroll
                for (int nt = 0; nt < 8; ++nt) {
                    const f16* pb = cK + (nt*8+g)*LDK + ks*16 + tq*2;
                    uint32_t k0 = lds32(pb), k1 = lds32(pb + 8);
                    mma_f16(sc[nt], qh0,qh1,qh2,qh3, k0, k1);
                    mma_f16(sc[nt], ql0,ql1,ql2,ql3, k0, k1);
                }
            }

            // ---- causal mask (diagonal tile only) ----
            if (kb + AKT - 1 > q0 + wrow) {
                #pragma unroll
                for (int nt = 0; nt < 8; ++nt) {
                    int k0 = kb + nt*8 + tq*2;
                    if (k0     > qrow0) sc[nt][0] = -INFINITY;
                    if (k0 + 1 > qrow0) sc[nt][1] = -INFINITY;
                    if (k0     > qrow1) sc[nt][2] = -INFINITY;
                    if (k0 + 1 > qrow1) sc[nt][3] = -INFINITY;
                }
            }

            // ---- online softmax ----
            float mx0 = -INFINITY, mx1 = -INFINITY;
            #pragma unroll
            for (int nt = 0; nt < 8; ++nt) {
                mx0 = fmaxf(mx0, fmaxf(sc[nt][0], sc[nt][1]));
                mx1 = fmaxf(mx1, fmaxf(sc[nt][2], sc[nt][3]));
            }
            mx0 = fmaxf(mx0, __shfl_xor_sync(0xffffffffu, mx0, 1));
            mx0 = fmaxf(mx0, __shfl_xor_sync(0xffffffffu, mx0, 2));
            mx1 = fmaxf(mx1, __shfl_xor_sync(0xffffffffu, mx1, 1));
            mx1 = fmaxf(mx1, __shfl_xor_sync(0xffffffffu, mx1, 2));
            float mn0 = fmaxf(m0, mx0), mn1 = fmaxf(m1, mx1);
            float al0 = __expf(m0 - mn0), al1 = __expf(m1 - mn1);
            m0 = mn0; m1 = mn1;

            float ps0 = 0.f, ps1 = 0.f;
            uint32_t ph[8][2];
            #pragma unroll
            for (int nt = 0; nt < 8; ++nt) {
                float p0 = __expf(sc[nt][0] - mn0);
                float p1 = __expf(sc[nt][1] - mn0);
                float p2 = __expf(sc[nt][2] - mn1);
                float p3 = __expf(sc[nt][3] - mn1);
                ps0 += p0 + p1; ps1 += p2 + p3;
                ph[nt][0] = packh2(p0, p1);
                ph[nt][1] = packh2(p2, p3);
            }
            ps0 += __shfl_xor_sync(0xffffffffu, ps0, 1);
            ps0 += __shfl_xor_sync(0xffffffffu, ps0, 2);
            ps1 += __shfl_xor_sync(0xffffffffu, ps1, 1);
            ps1 += __shfl_xor_sync(0xffffffffu, ps1, 2);
            l0 = l0*al0 + ps0;
            l1 = l1*al1 + ps1;
            #pragma unroll
            for (int i = 0; i < 32; ++i) {
                acc[i][0] *= al0; acc[i][1] *= al0;
                acc[i][2] *= al1; acc[i][3] *= al1;
            }

            // ---- O += P @ V  (fp16 single) ----
            #pragma unroll
            for (int kk = 0; kk < 4; ++kk) {
                uint32_t a0 = ph[2*kk][0],   a1 = ph[2*kk][1];
                uint32_t a2 = ph[2*kk+1][0], a3 = ph[2*kk+1][1];
                #pragma unroll
                for (int ng = 0; ng < 16; ++ng) {
                    uint32_t v0,v1,v2,v3;
                    ldmx4t(v0,v1,v2,v3, cV + kk*16*LDV + ng*16 + lmoff);
                    mma_f16(acc[2*ng],   a0,a1,a2,a3, v0, v1);
                    mma_f16(acc[2*ng+1], a0,a1,a2,a3, v2, v3);
                }
            }
        }
        __syncthreads();
    }

    // ---- epilogue: normalize + GELU -> fp16 single ----
    const float inv0 = 1.0f / l0, inv1 = 1.0f / l1;
    f16* o0p = Og + ((size_t)b*SQ + qrow0)*DHID + (size_t)h*DVH;
    f16* o1p = Og + ((size_t)b*SQ + qrow1)*DHID + (size_t)h*DVH;
    #pragma unroll
    for (int nt = 0; nt < 32; ++nt) {
        int c = nt*8 + tq*2;
        float v0 = gelu_exact(acc[nt][0] * inv0);
        float v1 = gelu_exact(acc[nt][1] * inv0);
        float v2 = gelu_exact(acc[nt][2] * inv1);
        float v3 = gelu_exact(acc[nt][3] * inv1);
        *(uint32_t*)(o0p + c) = packh2(v0, v1);
        *(uint32_t*)(o1p + c) = packh2(v2, v3);
    }
}

// ---------------------------------------------------------------------------
extern "C" void kernel_launch(void* const* d_in, const int* in_sizes, int n_in,
                              void* d_out, int out_size)
{
    const float* x  = (const float*)d_in[0];
    const float* Wk = (const float*)d_in[1];
    const float* bk = (const float*)d_in[2];
    const float* Wv = (const float*)d_in[3];
    const float* bv = (const float*)d_in[4];
    const float* Wf = (const float*)d_in[5];
    const float* bf_ = (const float*)d_in[6];
    float* out = (float*)d_out;

    f16 *gxfh, *gxfl, *gKf, *gVf, *gOf, *gWkf, *gWvf, *gWff;
    cudaGetSymbolAddress((void**)&gxfh, g_xfh);
    cudaGetSymbolAddress((void**)&gxfl, g_xfl);
    cudaGetSymbolAddress((void**)&gKf,  g_Kf);
    cudaGetSymbolAddress((void**)&gVf,  g_Vf);
    cudaGetSymbolAddress((void**)&gOf,  g_Of);
    cudaGetSymbolAddress((void**)&gWkf, g_Wkf);
    cudaGetSymbolAddress((void**)&gWvf, g_Wvf);
    cudaGetSymbolAddress((void**)&gWff, g_Wff);

    cudaFuncSetAttribute(attn_mma_kernel,
        cudaFuncAttributeMaxDynamicSharedMemorySize, ATTN_SMEM);
    cudaFuncSetAttribute(gemm_f16pair_kernel,
        cudaFuncAttributeMaxDynamicSharedMemorySize, GEMM_SMEM_P);
    cudaFuncSetAttribute(gemm_f16_kernel<0>,
        cudaFuncAttributeMaxDynamicSharedMemorySize, GEMM_SMEM_F1);
    cudaFuncSetAttribute(gemm_f16_kernel<1>,
        cudaFuncAttributeMaxDynamicSharedMemorySize, GEMM_SMEM_F1);

    // 0) conversions
    convert_x_kernel<<<(MROWS*DMODEL/4 + 255)/256, 256>>>(
        x, gxfh, gxfl, MROWS*DMODEL/4);
    transpose_f16_kernel<<<dim3(DMODEL/32, DMODEL/32), dim3(32,8)>>>(
        Wk, gWkf, DMODEL, DMODEL);
    transpose_f16_kernel<<<dim3(DHID/32,   DMODEL/32), dim3(32,8)>>>(
        Wv, gWvf, DMODEL, DHID);
    transpose_f16_kernel<<<dim3(DMODEL/32, DHID/32),   dim3(32,8)>>>(
        Wf, gWff, DHID, DMODEL);

    // 1) K = x @ Wk + bk  -> fp16 single  (fp16 2-mma, x pair)
    gemm_f16pair_kernel<<<dim3(DMODEL/GBN, MROWS/GBM), 256, GEMM_SMEM_P>>>(
        gxfh, gxfl, gWkf, bk, gKf, MROWS, DMODEL, DMODEL);

    // 2) V = x @ Wv + bv  -> fp16 single  (fp16 1-mma)
    gemm_f16_kernel<0><<<dim3(DHID/GBN, MROWS/GBM), 256, GEMM_SMEM_F1>>>(
        gxfh, gWvf, bv, nullptr, gVf, nullptr, MROWS, DHID, DMODEL);

    // 3) gelu(attn(x,K,V)) -> fp16 single  (AQT=64, 2 CTAs/SM)
    attn_mma_kernel<<<dim3(SQ/AQT, BATCH*NHEADS), 128, ATTN_SMEM>>>(
        gxfh, gxfl, gKf, gVf, gOf);

    // 4) out = x + O @ Wf + bf  (fp16 1-mma)
    gemm_f16_kernel<1><<<dim3(DMODEL/GBN, MROWS/GBM), 256, GEMM_SMEM_F1>>>(
        gOf, gWff, bf_, x, nullptr, out, MROWS, DMODEL, DHID);
}